// round 1
// baseline (speedup 1.0000x reference)
#include <cuda_runtime.h>
#include <math.h>

#define BB 2
#define SS 4096
#define DD 768
#define HH 12
#define LL 2
#define DHH 64
#define WW 256
#define GG 64
#define FFN 3072
#define NB 16
#define KT 832          // 3*W + G
#define SEPID 2
#define NEGV -1000000000.0f
#define BS (BB*SS)

// ---------------- scratch (device globals; no allocation allowed) ----------------
__device__ float g_x[BS*DD];
__device__ float g_q[BS*DD];
__device__ float g_k[BS*DD];
__device__ float g_v[BS*DD];
__device__ float g_kga[BS*DD];
__device__ float g_vga[BS*DD];
__device__ float g_attn[BS*DD];
__device__ float g_tmp[BS*DD];
__device__ float g_h1[BS*FFN];
__device__ float g_sc[(size_t)BB*HH*SS*KT];     // band+global scores/probs (327MB)
__device__ float g_sg[(size_t)BB*HH*GG*SS];     // global attn scores (25MB)
__device__ float g_xg[BB*GG*DD];
__device__ float g_qg[BB*GG*DD];
__device__ float g_og[BB*GG*DD];
__device__ int   g_idxg[BB*GG];
__device__ unsigned char g_klo[BS];

// ---------------- block reductions ----------------
__device__ __forceinline__ float blk_sum(float v) {
    __shared__ float sm[33];
    int lane = threadIdx.x & 31, wid = threadIdx.x >> 5;
    #pragma unroll
    for (int o = 16; o; o >>= 1) v += __shfl_xor_sync(0xffffffffu, v, o);
    if (lane == 0) sm[wid] = v;
    __syncthreads();
    if (wid == 0) {
        int nw = (blockDim.x + 31) >> 5;
        float r = (lane < nw) ? sm[lane] : 0.f;
        #pragma unroll
        for (int o = 16; o; o >>= 1) r += __shfl_xor_sync(0xffffffffu, r, o);
        if (lane == 0) sm[32] = r;
    }
    __syncthreads();
    float r = sm[32];
    __syncthreads();
    return r;
}

__device__ __forceinline__ float blk_max(float v) {
    __shared__ float sm[33];
    int lane = threadIdx.x & 31, wid = threadIdx.x >> 5;
    #pragma unroll
    for (int o = 16; o; o >>= 1) v = fmaxf(v, __shfl_xor_sync(0xffffffffu, v, o));
    if (lane == 0) sm[wid] = v;
    __syncthreads();
    if (wid == 0) {
        int nw = (blockDim.x + 31) >> 5;
        float r = (lane < nw) ? sm[lane] : -3.4e38f;
        #pragma unroll
        for (int o = 16; o; o >>= 1) r = fmaxf(r, __shfl_xor_sync(0xffffffffu, r, o));
        if (lane == 0) sm[32] = r;
    }
    __syncthreads();
    float r = sm[32];
    __syncthreads();
    return r;
}

// ---------------- prep: idx_g + key_local_ok ----------------
__global__ void prep_k(const int* __restrict__ ids, const int* __restrict__ am,
                       int* __restrict__ idxg, unsigned char* __restrict__ klo) {
    int b = blockIdx.x;
    for (int s = threadIdx.x; s < SS; s += blockDim.x) {
        bool g = (ids[b*SS+s] == SEPID) || (s == 0);
        klo[b*SS+s] = (am[b*SS+s] != 0 && !g) ? 1 : 0;
    }
    if (threadIdx.x == 0) {
        int cnt = 0;
        for (int s = 0; s < SS && cnt < GG; s++)
            if (ids[b*SS+s] == SEPID || s == 0) idxg[b*GG + cnt++] = s;
        for (; cnt < GG; cnt++) idxg[b*GG + cnt] = 0;
    }
}

// ---------------- embedding + LN ----------------
__global__ void embed_ln_k(const int* __restrict__ ids, const float* __restrict__ etok,
                           const float* __restrict__ epos, const float* __restrict__ lns,
                           const float* __restrict__ lnb, float* __restrict__ x) {
    int row = blockIdx.x;               // b*S + s
    int spos = row & (SS - 1);
    int id = ids[row];
    const float* te = etok + (size_t)id * DD;
    const float* pe = epos + (size_t)spos * DD;
    float v[3]; float sum = 0.f;
    #pragma unroll
    for (int i = 0; i < 3; i++) {
        int d = threadIdx.x + i*256;
        float val = te[d] + pe[d];
        v[i] = val; sum += val;
    }
    float mean = blk_sum(sum) * (1.0f/DD);
    float sq = 0.f;
    #pragma unroll
    for (int i = 0; i < 3; i++) { float c = v[i] - mean; sq += c*c; }
    float inv = rsqrtf(blk_sum(sq) * (1.0f/DD) + 1e-5f);
    #pragma unroll
    for (int i = 0; i < 3; i++) {
        int d = threadIdx.x + i*256;
        x[(size_t)row*DD + d] = (v[i] - mean)*inv*lns[d] + lnb[d];
    }
}

// ---------------- residual add + LN (in-place on x) ----------------
__global__ void add_ln_k(float* __restrict__ x, const float* __restrict__ t,
                         const float* __restrict__ lns, const float* __restrict__ lnb) {
    int row = blockIdx.x;
    size_t base = (size_t)row * DD;
    float v[3]; float sum = 0.f;
    #pragma unroll
    for (int i = 0; i < 3; i++) {
        int d = threadIdx.x + i*256;
        float val = x[base+d] + t[base+d];
        v[i] = val; sum += val;
    }
    float mean = blk_sum(sum) * (1.0f/DD);
    float sq = 0.f;
    #pragma unroll
    for (int i = 0; i < 3; i++) { float c = v[i] - mean; sq += c*c; }
    float inv = rsqrtf(blk_sum(sq) * (1.0f/DD) + 1e-5f);
    #pragma unroll
    for (int i = 0; i < 3; i++) {
        int d = threadIdx.x + i*256;
        x[base+d] = (v[i] - mean)*inv*lns[d] + lnb[d];
    }
}

// ---------------- GEMM: C[M,N] = A[M,K] @ B[K,N] + bias[N] (all row-major) --------
// 64x64 tile, BK=16, 256 threads, 4x4 per thread.
__global__ void gemm_bias_k(const float* __restrict__ A, const float* __restrict__ Bm,
                            const float* __restrict__ bias, float* __restrict__ C,
                            int M, int N, int K) {
    __shared__ float As[16][68];
    __shared__ float Bs[16][68];
    int bn = blockIdx.x << 6, bm = blockIdx.y << 6;
    int tid = threadIdx.x;
    int tx = tid & 15, ty = tid >> 4;
    float acc[4][4];
    #pragma unroll
    for (int i = 0; i < 4; i++)
        #pragma unroll
        for (int j = 0; j < 4; j++) acc[i][j] = 0.f;

    for (int k0 = 0; k0 < K; k0 += 16) {
        #pragma unroll
        for (int p = 0; p < 4; p++) {
            int idx = tid + (p << 8);
            int m = idx >> 4, kk = idx & 15;
            As[kk][m] = A[(size_t)(bm+m)*K + (k0+kk)];
        }
        #pragma unroll
        for (int p = 0; p < 4; p++) {
            int idx = tid + (p << 8);
            int kk = idx >> 6, n = idx & 63;
            Bs[kk][n] = Bm[(size_t)(k0+kk)*N + (bn+n)];
        }
        __syncthreads();
        #pragma unroll
        for (int kk = 0; kk < 16; kk++) {
            float4 av = *(const float4*)&As[kk][ty << 2];
            float4 bv = *(const float4*)&Bs[kk][tx << 2];
            float a[4] = {av.x, av.y, av.z, av.w};
            float b[4] = {bv.x, bv.y, bv.z, bv.w};
            #pragma unroll
            for (int i = 0; i < 4; i++)
                #pragma unroll
                for (int j = 0; j < 4; j++) acc[i][j] += a[i]*b[j];
        }
        __syncthreads();
    }
    float4 bv4 = *(const float4*)&bias[bn + (tx << 2)];
    #pragma unroll
    for (int i = 0; i < 4; i++) {
        int m = bm + (ty << 2) + i;
        float4 o = make_float4(acc[i][0]+bv4.x, acc[i][1]+bv4.y,
                               acc[i][2]+bv4.z, acc[i][3]+bv4.w);
        *(float4*)&C[(size_t)m*N + bn + (tx << 2)] = o;
    }
}

// ---------------- GELU (tanh approximation, matches jax.nn.gelu default) ----------
__global__ void gelu_k(float* __restrict__ h, int n) {
    int i = blockIdx.x*blockDim.x + threadIdx.x;
    if (i < n) {
        float v = h[i];
        float u = 0.7978845608028654f * (v + 0.044715f*v*v*v);
        h[i] = 0.5f * v * (1.f + tanhf(u));
    }
}

// ---------------- band + global scores ----------------
// grid (NB, B*H), 256 threads, one q row per thread. 13 key chunks of 64.
__global__ void band_scores_k(const float* __restrict__ q, const float* __restrict__ k,
                              const int* __restrict__ idxg, const unsigned char* __restrict__ klo,
                              float* __restrict__ sc) {
    extern __shared__ float sm[];
    float* kt  = sm;            // 64 keys x 64 dims
    float* ssc = sm + 4096;     // 256 q x 65 (padded)
    int n = blockIdx.x;
    int b = blockIdx.y / HH, h = blockIdx.y % HH;
    int qr = threadIdx.x;
    int sq = n*WW + qr;
    float qv[64];
    const float4* qp = (const float4*)(q + ((size_t)(b*SS+sq))*DD + h*DHH);
    #pragma unroll
    for (int d4 = 0; d4 < 16; d4++) {
        float4 t = qp[d4];
        qv[4*d4] = t.x; qv[4*d4+1] = t.y; qv[4*d4+2] = t.z; qv[4*d4+3] = t.w;
    }
    size_t scbase = ((size_t)(b*HH+h)*SS + (size_t)n*WW) * KT;
    for (int c = 0; c < 13; c++) {
        __syncthreads();
        for (int idx = threadIdx.x; idx < 4096; idx += 256) {
            int kk = idx >> 6, d = idx & 63;
            int j = (c << 6) + kk;
            float val = 0.f;
            if (j < 768) {
                int kp = n*WW + j - WW;
                if (kp >= 0 && kp < SS) val = k[((size_t)(b*SS+kp))*DD + h*DHH + d];
            } else {
                int kp = idxg[b*GG + (j - 768)];
                val = k[((size_t)(b*SS+kp))*DD + h*DHH + d];
            }
            kt[idx] = val;
        }
        __syncthreads();
        for (int kk = 0; kk < 64; kk++) {
            int j = (c << 6) + kk;
            const float4* kr = (const float4*)(kt + (kk << 6));
            float s = 0.f;
            #pragma unroll
            for (int d4 = 0; d4 < 16; d4++) {
                float4 kv = kr[d4];
                s += qv[4*d4]*kv.x + qv[4*d4+1]*kv.y + qv[4*d4+2]*kv.z + qv[4*d4+3]*kv.w;
            }
            s *= 0.125f;
            if (j < 768) {
                int kp = n*WW + j - WW;
                int rel = j - WW - qr;
                bool ok = (kp >= 0) && (kp < SS) && klo[b*SS+kp] && (rel >= -WW) && (rel <= WW);
                if (!ok) s = NEGV;
            }
            ssc[qr*65 + kk] = s;
        }
        __syncthreads();
        for (int idx = threadIdx.x; idx < 16384; idx += 256) {
            int qq = idx >> 6, kk = idx & 63;
            sc[scbase + (size_t)qq*KT + (c << 6) + kk] = ssc[qq*65 + kk];
        }
    }
}

// ---------------- row softmax (rowlen <= 4096), in place ----------------
__global__ void softmax_k(float* __restrict__ sc, int rowlen) {
    __shared__ float buf[4096];
    float* row = sc + (size_t)blockIdx.x * rowlen;
    float m = -3.4e38f;
    for (int i = threadIdx.x; i < rowlen; i += 256) {
        float v = row[i]; buf[i] = v; m = fmaxf(m, v);
    }
    m = blk_max(m);
    float sum = 0.f;
    for (int i = threadIdx.x; i < rowlen; i += 256) {
        float e = expf(buf[i] - m); buf[i] = e; sum += e;
    }
    sum = blk_sum(sum);
    float inv = 1.f / sum;
    for (int i = threadIdx.x; i < rowlen; i += 256) row[i] = buf[i]*inv;
}

// ---------------- band + global PV ----------------
__global__ void band_pv_k(const float* __restrict__ probs, const float* __restrict__ v,
                          const int* __restrict__ idxg, float* __restrict__ out) {
    extern __shared__ float sm[];
    float* vt = sm;             // 64 x 64
    float* pt = sm + 4096;      // 256 x 65
    int n = blockIdx.x;
    int b = blockIdx.y / HH, h = blockIdx.y % HH;
    int qr = threadIdx.x, sq = n*WW + qr;
    float acc[64];
    #pragma unroll
    for (int d = 0; d < 64; d++) acc[d] = 0.f;
    size_t pbase = ((size_t)(b*HH+h)*SS + (size_t)n*WW) * KT;
    for (int c = 0; c < 13; c++) {
        __syncthreads();
        for (int idx = threadIdx.x; idx < 4096; idx += 256) {
            int kk = idx >> 6, d = idx & 63;
            int j = (c << 6) + kk;
            float val = 0.f;
            if (j < 768) {
                int kp = n*WW + j - WW;
                if (kp >= 0 && kp < SS) val = v[((size_t)(b*SS+kp))*DD + h*DHH + d];
            } else {
                int kp = idxg[b*GG + (j - 768)];
                val = v[((size_t)(b*SS+kp))*DD + h*DHH + d];
            }
            vt[idx] = val;
        }
        for (int idx = threadIdx.x; idx < 16384; idx += 256) {
            int qq = idx >> 6, kk = idx & 63;
            pt[qq*65 + kk] = probs[pbase + (size_t)qq*KT + (c << 6) + kk];
        }
        __syncthreads();
        for (int kk = 0; kk < 64; kk++) {
            float p = pt[qr*65 + kk];
            const float4* vr = (const float4*)(vt + (kk << 6));
            #pragma unroll
            for (int d4 = 0; d4 < 16; d4++) {
                float4 vv = vr[d4];
                acc[4*d4]   += p*vv.x; acc[4*d4+1] += p*vv.y;
                acc[4*d4+2] += p*vv.z; acc[4*d4+3] += p*vv.w;
            }
        }
    }
    float4* op = (float4*)(out + ((size_t)(b*SS+sq))*DD + h*DHH);
    #pragma unroll
    for (int d4 = 0; d4 < 16; d4++)
        op[d4] = make_float4(acc[4*d4], acc[4*d4+1], acc[4*d4+2], acc[4*d4+3]);
}

// ---------------- gather / scatter global rows ----------------
__global__ void gather_k(const float* __restrict__ x, const int* __restrict__ idxg,
                         float* __restrict__ xg) {
    int r = blockIdx.x;            // b*G + g
    int b = r / GG;
    int src = idxg[r];
    for (int d = threadIdx.x; d < DD; d += blockDim.x)
        xg[(size_t)r*DD + d] = x[((size_t)(b*SS+src))*DD + d];
}

__global__ void scatter_k(const float* __restrict__ og, const int* __restrict__ idxg,
                          float* __restrict__ out) {
    int r = blockIdx.x;            // b*G + g
    int b = r / GG;
    int dst = idxg[r];
    for (int d = threadIdx.x; d < DD; d += blockDim.x)
        out[((size_t)(b*SS+dst))*DD + d] = og[(size_t)r*DD + d];
}

// ---------------- global attention scores ----------------
__global__ void glob_scores_k(const float* __restrict__ qg, const float* __restrict__ kga,
                              const int* __restrict__ am, float* __restrict__ sg) {
    int g = blockIdx.x;
    int b = blockIdx.y / HH, h = blockIdx.y % HH;
    __shared__ float qv[64];
    if (threadIdx.x < 64)
        qv[threadIdx.x] = qg[((size_t)(b*GG+g))*DD + h*DHH + threadIdx.x];
    __syncthreads();
    float* srow = sg + ((size_t)((b*HH+h)*GG + g))*SS;
    for (int s = threadIdx.x; s < SS; s += 256) {
        const float4* kr = (const float4*)(kga + ((size_t)(b*SS+s))*DD + h*DHH);
        float dot = 0.f;
        #pragma unroll
        for (int d4 = 0; d4 < 16; d4++) {
            float4 kv = kr[d4];
            dot += qv[4*d4]*kv.x + qv[4*d4+1]*kv.y + qv[4*d4+2]*kv.z + qv[4*d4+3]*kv.w;
        }
        srow[s] = (am[b*SS+s] != 0) ? dot*0.125f : NEGV;
    }
}

// ---------------- global attention output ----------------
__global__ void glob_out_k(const float* __restrict__ sg, const float* __restrict__ vga,
                           float* __restrict__ og) {
    int g = blockIdx.x;
    int b = blockIdx.y / HH, h = blockIdx.y % HH;
    int d = threadIdx.x;   // 64 threads
    const float* p = sg + ((size_t)((b*HH+h)*GG + g))*SS;
    float acc = 0.f;
    for (int s = 0; s < SS; s += 4) {
        float p0 = p[s], p1 = p[s+1], p2 = p[s+2], p3 = p[s+3];
        acc += p0 * vga[((size_t)(b*SS+s  ))*DD + h*DHH + d];
        acc += p1 * vga[((size_t)(b*SS+s+1))*DD + h*DHH + d];
        acc += p2 * vga[((size_t)(b*SS+s+2))*DD + h*DHH + d];
        acc += p3 * vga[((size_t)(b*SS+s+3))*DD + h*DHH + d];
    }
    og[((size_t)(b*GG+g))*DD + h*DHH + d] = acc;
}

// ---------------- classifier head (reads lo/ro from device) ----------------
__global__ void classify_k(const float* __restrict__ x, const float* __restrict__ Wc,
                           const float* __restrict__ bc, const int* __restrict__ lo_p,
                           const int* __restrict__ ro_p, float* __restrict__ out, int nrows) {
    int r = blockIdx.x;
    int lo = *lo_p, ro = *ro_p;
    int per_b = 63 - lo - ro;     // N_SEPS - ro - lo
    if (per_b <= 0) per_b = 1;
    int b = r / per_b, t = lo + (r - b*per_b);
    const float* row = x + ((size_t)(b*SS + t))*DD;
    float p[7];
    #pragma unroll
    for (int c = 0; c < 7; c++) p[c] = 0.f;
    for (int d = threadIdx.x; d < DD; d += 256) {
        float xv = row[d];
        #pragma unroll
        for (int c = 0; c < 7; c++) p[c] += xv * Wc[d*7 + c];
    }
    #pragma unroll
    for (int c = 0; c < 7; c++) {
        float tot = blk_sum(p[c]);
        if (threadIdx.x == 0) out[r*7 + c] = tot + bc[c];
    }
}

// ---------------- launch ----------------
extern "C" void kernel_launch(void* const* d_in, const int* in_sizes, int n_in,
                              void* d_out, int out_size) {
    const float* emb_tok = (const float*)d_in[0];
    const float* emb_pos = (const float*)d_in[1];
    const float* ln_e_s  = (const float*)d_in[2];
    const float* ln_e_b  = (const float*)d_in[3];
    const float* Wq  = (const float*)d_in[4];
    const float* bq  = (const float*)d_in[5];
    const float* Wk  = (const float*)d_in[6];
    const float* bk  = (const float*)d_in[7];
    const float* Wv  = (const float*)d_in[8];
    const float* bv  = (const float*)d_in[9];
    const float* Wqg = (const float*)d_in[10];
    const float* bqg = (const float*)d_in[11];
    const float* Wkg = (const float*)d_in[12];
    const float* bkg = (const float*)d_in[13];
    const float* Wvg = (const float*)d_in[14];
    const float* bvg = (const float*)d_in[15];
    const float* Wo  = (const float*)d_in[16];
    const float* bo  = (const float*)d_in[17];
    const float* ln1_s = (const float*)d_in[18];
    const float* ln1_b = (const float*)d_in[19];
    const float* Wf1 = (const float*)d_in[20];
    const float* bf1 = (const float*)d_in[21];
    const float* Wf2 = (const float*)d_in[22];
    const float* bf2 = (const float*)d_in[23];
    const float* ln2_s = (const float*)d_in[24];
    const float* ln2_b = (const float*)d_in[25];
    const float* Wc  = (const float*)d_in[26];
    const float* bc  = (const float*)d_in[27];
    const int* input_ids = (const int*)d_in[28];
    const int* attn_mask = (const int*)d_in[29];
    const int* lo_p = (const int*)d_in[30];
    const int* ro_p = (const int*)d_in[31];
    float* out = (float*)d_out;

    float *x, *q, *k, *v, *kga, *vga, *attn, *tmp, *h1, *sc, *sg, *xg, *qg, *og;
    int* idxg; unsigned char* klo;
    cudaGetSymbolAddress((void**)&x,    g_x);
    cudaGetSymbolAddress((void**)&q,    g_q);
    cudaGetSymbolAddress((void**)&k,    g_k);
    cudaGetSymbolAddress((void**)&v,    g_v);
    cudaGetSymbolAddress((void**)&kga,  g_kga);
    cudaGetSymbolAddress((void**)&vga,  g_vga);
    cudaGetSymbolAddress((void**)&attn, g_attn);
    cudaGetSymbolAddress((void**)&tmp,  g_tmp);
    cudaGetSymbolAddress((void**)&h1,   g_h1);
    cudaGetSymbolAddress((void**)&sc,   g_sc);
    cudaGetSymbolAddress((void**)&sg,   g_sg);
    cudaGetSymbolAddress((void**)&xg,   g_xg);
    cudaGetSymbolAddress((void**)&qg,   g_qg);
    cudaGetSymbolAddress((void**)&og,   g_og);
    cudaGetSymbolAddress((void**)&idxg, g_idxg);
    cudaGetSymbolAddress((void**)&klo,  g_klo);

    const int SMEM_BAND = (4096 + 256*65) * 4;   // 82944 bytes
    cudaFuncSetAttribute(band_scores_k, cudaFuncAttributeMaxDynamicSharedMemorySize, SMEM_BAND);
    cudaFuncSetAttribute(band_pv_k,     cudaFuncAttributeMaxDynamicSharedMemorySize, SMEM_BAND);

    prep_k<<<BB, 256>>>(input_ids, attn_mask, idxg, klo);
    embed_ln_k<<<BS, 256>>>(input_ids, emb_tok, emb_pos, ln_e_s, ln_e_b, x);

    dim3 gD(DD/64, BS/64);          // 12 x 128
    dim3 gF1(FFN/64, BS/64);        // 48 x 128
    dim3 gQG(DD/64, (BB*GG)/64);    // 12 x 2
    dim3 gBand(NB, BB*HH);          // 16 x 24
    dim3 gGlob(GG, BB*HH);          // 64 x 24

    for (int l = 0; l < LL; l++) {
        const float* Wq_l  = Wq  + (size_t)l*DD*DD;  const float* bq_l  = bq  + l*DD;
        const float* Wk_l  = Wk  + (size_t)l*DD*DD;  const float* bk_l  = bk  + l*DD;
        const float* Wv_l  = Wv  + (size_t)l*DD*DD;  const float* bv_l  = bv  + l*DD;
        const float* Wqg_l = Wqg + (size_t)l*DD*DD;  const float* bqg_l = bqg + l*DD;
        const float* Wkg_l = Wkg + (size_t)l*DD*DD;  const float* bkg_l = bkg + l*DD;
        const float* Wvg_l = Wvg + (size_t)l*DD*DD;  const float* bvg_l = bvg + l*DD;
        const float* Wo_l  = Wo  + (size_t)l*DD*DD;  const float* bo_l  = bo  + l*DD;
        const float* Wf1_l = Wf1 + (size_t)l*DD*FFN; const float* bf1_l = bf1 + l*FFN;
        const float* Wf2_l = Wf2 + (size_t)l*FFN*DD; const float* bf2_l = bf2 + l*DD;

        gemm_bias_k<<<gD, 256>>>(x, Wq_l,  bq_l,  q,   BS, DD, DD);
        gemm_bias_k<<<gD, 256>>>(x, Wk_l,  bk_l,  k,   BS, DD, DD);
        gemm_bias_k<<<gD, 256>>>(x, Wv_l,  bv_l,  v,   BS, DD, DD);
        gemm_bias_k<<<gD, 256>>>(x, Wkg_l, bkg_l, kga, BS, DD, DD);
        gemm_bias_k<<<gD, 256>>>(x, Wvg_l, bvg_l, vga, BS, DD, DD);

        gather_k<<<BB*GG, 256>>>(x, idxg, xg);
        gemm_bias_k<<<gQG, 256>>>(xg, Wqg_l, bqg_l, qg, BB*GG, DD, DD);

        band_scores_k<<<gBand, 256, SMEM_BAND>>>(q, k, idxg, klo, sc);
        softmax_k<<<BB*HH*SS, 256>>>(sc, KT);
        band_pv_k<<<gBand, 256, SMEM_BAND>>>(sc, v, idxg, attn);

        glob_scores_k<<<gGlob, 256>>>(qg, kga, attn_mask, sg);
        softmax_k<<<BB*HH*GG, 256>>>(sg, SS);
        glob_out_k<<<gGlob, 64>>>(sg, vga, og);
        scatter_k<<<BB*GG, 256>>>(og, idxg, attn);

        gemm_bias_k<<<gD, 256>>>(attn, Wo_l, bo_l, tmp, BS, DD, DD);
        add_ln_k<<<BS, 256>>>(x, tmp, ln1_s + l*DD, ln1_b + l*DD);

        gemm_bias_k<<<gF1, 256>>>(x, Wf1_l, bf1_l, h1, BS, FFN, DD);
        gelu_k<<<(BS*FFN + 255)/256, 256>>>(h1, BS*FFN);
        gemm_bias_k<<<gD, 256>>>(h1, Wf2_l, bf2_l, tmp, BS, DD, FFN);
        add_ln_k<<<BS, 256>>>(x, tmp, ln2_s + l*DD, ln2_b + l*DD);
    }

    int nrows = out_size / 7;
    classify_k<<<nrows, 256>>>(x, Wc, bc, lo_p, ro_p, out, nrows);
}

// round 3
// speedup vs baseline: 1.4043x; 1.4043x over previous
#include <cuda_runtime.h>
#include <cuda_bf16.h>
#include <cstdint>
#include <math.h>

#define BB 2
#define SS 4096
#define DD 768
#define HH 12
#define LL 2
#define DHH 64
#define WW 256
#define GG 64
#define FFN 3072
#define NB 16
#define KT 832
#define SEPID 2
#define NEGV -1000000000.0f
#define BS (BB*SS)

// weight arena offsets (bf16, transposed [N][K])
#define WSZ_DD (DD*DD)
#define OFF_Q  0
#define OFF_K  (1*WSZ_DD)
#define OFF_V  (2*WSZ_DD)
#define OFF_QG (3*WSZ_DD)
#define OFF_KG (4*WSZ_DD)
#define OFF_VG (5*WSZ_DD)
#define OFF_O  (6*WSZ_DD)
#define OFF_F1 (7*WSZ_DD)
#define OFF_F2 (7*WSZ_DD + DD*FFN)
#define LWOFF  (7*WSZ_DD + 2*DD*FFN)

// ---------------- scratch ----------------
__device__ float g_x[BS*DD];
__device__ float g_q[BS*DD];
__device__ float g_k[BS*DD];
__device__ float g_v[BS*DD];
__device__ float g_kga[BS*DD];
__device__ float g_vga[BS*DD];
__device__ float g_attn[BS*DD];
__device__ float g_tmp[BS*DD];
__device__ float g_h1[BS*FFN];
__device__ float g_sc[(size_t)BB*HH*SS*KT];
__device__ float g_sg[(size_t)BB*HH*GG*SS];
__device__ float g_xg[BB*GG*DD];
__device__ float g_qg[BB*GG*DD];
__device__ float g_og[BB*GG*DD];
__device__ int   g_idxg[BB*GG];
__device__ unsigned char g_klo[BS];

__device__ __align__(16) __nv_bfloat16 g_whi[2*LWOFF];
__device__ __align__(16) __nv_bfloat16 g_wlo[2*LWOFF];
__device__ __align__(16) __nv_bfloat16 g_ahi[BS*FFN];
__device__ __align__(16) __nv_bfloat16 g_alo[BS*FFN];
__device__ __align__(16) __nv_bfloat16 g_xghi[BB*GG*DD];
__device__ __align__(16) __nv_bfloat16 g_xglo[BB*GG*DD];

// ---------------- helpers ----------------
__device__ __forceinline__ uint32_t smem_u32(const void* p) {
    uint32_t a;
    asm("{ .reg .u64 t; cvta.to.shared.u64 t, %1; cvt.u32.u64 %0, t; }" : "=r"(a) : "l"(p));
    return a;
}

__device__ __forceinline__ void ldmat4(uint32_t& r0, uint32_t& r1, uint32_t& r2, uint32_t& r3,
                                       uint32_t addr) {
    asm volatile("ldmatrix.sync.aligned.m8n8.x4.shared.b16 {%0,%1,%2,%3}, [%4];"
        : "=r"(r0), "=r"(r1), "=r"(r2), "=r"(r3) : "r"(addr));
}

__device__ __forceinline__ void mma16816(float* d, const uint32_t* a, const uint32_t* b) {
    asm volatile("mma.sync.aligned.m16n8k16.row.col.f32.bf16.bf16.f32 "
        "{%0,%1,%2,%3}, {%4,%5,%6,%7}, {%8,%9}, {%0,%1,%2,%3};"
        : "+f"(d[0]), "+f"(d[1]), "+f"(d[2]), "+f"(d[3])
        : "r"(a[0]), "r"(a[1]), "r"(a[2]), "r"(a[3]), "r"(b[0]), "r"(b[1]));
}

__device__ __forceinline__ float gelu_f(float v) {
    return 0.5f*v*(1.f + tanhf(0.7978845608028654f*(v + 0.044715f*v*v*v)));
}

// ---------------- block reductions ----------------
__device__ __forceinline__ float blk_sum(float v) {
    __shared__ float sm[33];
    int lane = threadIdx.x & 31, wid = threadIdx.x >> 5;
    #pragma unroll
    for (int o = 16; o; o >>= 1) v += __shfl_xor_sync(0xffffffffu, v, o);
    if (lane == 0) sm[wid] = v;
    __syncthreads();
    if (wid == 0) {
        int nw = (blockDim.x + 31) >> 5;
        float r = (lane < nw) ? sm[lane] : 0.f;
        #pragma unroll
        for (int o = 16; o; o >>= 1) r += __shfl_xor_sync(0xffffffffu, r, o);
        if (lane == 0) sm[32] = r;
    }
    __syncthreads();
    float r = sm[32];
    __syncthreads();
    return r;
}

__device__ __forceinline__ float blk_max(float v) {
    __shared__ float sm[33];
    int lane = threadIdx.x & 31, wid = threadIdx.x >> 5;
    #pragma unroll
    for (int o = 16; o; o >>= 1) v = fmaxf(v, __shfl_xor_sync(0xffffffffu, v, o));
    if (lane == 0) sm[wid] = v;
    __syncthreads();
    if (wid == 0) {
        int nw = (blockDim.x + 31) >> 5;
        float r = (lane < nw) ? sm[lane] : -3.4e38f;
        #pragma unroll
        for (int o = 16; o; o >>= 1) r = fmaxf(r, __shfl_xor_sync(0xffffffffu, r, o));
        if (lane == 0) sm[32] = r;
    }
    __syncthreads();
    float r = sm[32];
    __syncthreads();
    return r;
}

// ---------------- prep ----------------
__global__ void prep_k(const int* __restrict__ ids, const int* __restrict__ am,
                       int* __restrict__ idxg, unsigned char* __restrict__ klo) {
    int b = blockIdx.x;
    for (int s = threadIdx.x; s < SS; s += blockDim.x) {
        bool g = (ids[b*SS+s] == SEPID) || (s == 0);
        klo[b*SS+s] = (am[b*SS+s] != 0 && !g) ? 1 : 0;
    }
    if (threadIdx.x == 0) {
        int cnt = 0;
        for (int s = 0; s < SS && cnt < GG; s++)
            if (ids[b*SS+s] == SEPID || s == 0) idxg[b*GG + cnt++] = s;
        for (; cnt < GG; cnt++) idxg[b*GG + cnt] = 0;
    }
}

// ---------------- embedding + LN ----------------
__global__ void embed_ln_k(const int* __restrict__ ids, const float* __restrict__ etok,
                           const float* __restrict__ epos, const float* __restrict__ lns,
                           const float* __restrict__ lnb, float* __restrict__ x) {
    int row = blockIdx.x;
    int spos = row & (SS - 1);
    int id = ids[row];
    const float* te = etok + (size_t)id * DD;
    const float* pe = epos + (size_t)spos * DD;
    float v[3]; float sum = 0.f;
    #pragma unroll
    for (int i = 0; i < 3; i++) {
        int d = threadIdx.x + i*256;
        float val = te[d] + pe[d];
        v[i] = val; sum += val;
    }
    float mean = blk_sum(sum) * (1.0f/DD);
    float sq = 0.f;
    #pragma unroll
    for (int i = 0; i < 3; i++) { float c = v[i] - mean; sq += c*c; }
    float inv = rsqrtf(blk_sum(sq) * (1.0f/DD) + 1e-5f);
    #pragma unroll
    for (int i = 0; i < 3; i++) {
        int d = threadIdx.x + i*256;
        x[(size_t)row*DD + d] = (v[i] - mean)*inv*lns[d] + lnb[d];
    }
}

// ---------------- residual add + LN ----------------
__global__ void add_ln_k(float* __restrict__ x, const float* __restrict__ t,
                         const float* __restrict__ lns, const float* __restrict__ lnb) {
    int row = blockIdx.x;
    size_t base = (size_t)row * DD;
    float v[3]; float sum = 0.f;
    #pragma unroll
    for (int i = 0; i < 3; i++) {
        int d = threadIdx.x + i*256;
        float val = x[base+d] + t[base+d];
        v[i] = val; sum += val;
    }
    float mean = blk_sum(sum) * (1.0f/DD);
    float sq = 0.f;
    #pragma unroll
    for (int i = 0; i < 3; i++) { float c = v[i] - mean; sq += c*c; }
    float inv = rsqrtf(blk_sum(sq) * (1.0f/DD) + 1e-5f);
    #pragma unroll
    for (int i = 0; i < 3; i++) {
        int d = threadIdx.x + i*256;
        x[base+d] = (v[i] - mean)*inv*lns[d] + lnb[d];
    }
}

// ---------------- conversions ----------------
__global__ void asplit_k(const float4* __restrict__ A, __nv_bfloat162* __restrict__ hi,
                         __nv_bfloat162* __restrict__ lo, int n4) {
    int i = blockIdx.x*256 + threadIdx.x;
    if (i >= n4) return;
    float4 v = A[i];
    __nv_bfloat16 hx = __float2bfloat16(v.x), hy = __float2bfloat16(v.y);
    __nv_bfloat16 hz = __float2bfloat16(v.z), hw = __float2bfloat16(v.w);
    hi[2*i]   = __halves2bfloat162(hx, hy);
    hi[2*i+1] = __halves2bfloat162(hz, hw);
    __nv_bfloat16 lx = __float2bfloat16(v.x - __bfloat162float(hx));
    __nv_bfloat16 ly = __float2bfloat16(v.y - __bfloat162float(hy));
    __nv_bfloat16 lz = __float2bfloat16(v.z - __bfloat162float(hz));
    __nv_bfloat16 lw = __float2bfloat16(v.w - __bfloat162float(hw));
    lo[2*i]   = __halves2bfloat162(lx, ly);
    lo[2*i+1] = __halves2bfloat162(lz, lw);
}

// weight split + transpose: W[K][N] fp32 -> hi/lo [N][K] bf16
__global__ void wsplit_t_k(const float* __restrict__ W, __nv_bfloat16* __restrict__ hi,
                           __nv_bfloat16* __restrict__ lo, int K, int N) {
    __shared__ float t[32][33];
    int n0 = blockIdx.x*32, k0 = blockIdx.y*32;
    int tx = threadIdx.x, ty = threadIdx.y;
    #pragma unroll
    for (int i = 0; i < 4; i++)
        t[ty+8*i][tx] = W[(size_t)(k0+ty+8*i)*N + n0 + tx];
    __syncthreads();
    #pragma unroll
    for (int i = 0; i < 4; i++) {
        float v = t[tx][ty+8*i];
        __nv_bfloat16 h = __float2bfloat16(v);
        size_t o = (size_t)(n0+ty+8*i)*K + k0 + tx;
        hi[o] = h;
        lo[o] = __float2bfloat16(v - __bfloat162float(h));
    }
}

// ---------------- tensor-core GEMM (mma.sync bf16, 3-pass hi/lo compensated) -----
// C[M,N] = (Ahi+Alo)[M,K] @ (Bhi+Blo)[N,K]^T + bias. 128x128 tile, BK=32.
#define SPAD 40

template<int GELU>
__global__ void __launch_bounds__(256) tgemm_k(
        const __nv_bfloat16* __restrict__ Ahi, const __nv_bfloat16* __restrict__ Alo,
        const __nv_bfloat16* __restrict__ Bhi, const __nv_bfloat16* __restrict__ Blo,
        const float* __restrict__ bias, float* __restrict__ C,
        int M, int N, int K) {
    __shared__ __nv_bfloat16 Asm[2][128*SPAD];
    __shared__ __nv_bfloat16 Bsm[2][128*SPAD];
    const int bn = blockIdx.x << 7, bm = blockIdx.y << 7;
    const int tid = threadIdx.x, wid = tid >> 5, lane = tid & 31;
    const int wm = (wid >> 2) << 6;
    const int wn = (wid & 3) << 5;

    float acc[4][4][4];
    #pragma unroll
    for (int i = 0; i < 4; i++)
        #pragma unroll
        for (int j = 0; j < 4; j++)
            #pragma unroll
            for (int r = 0; r < 4; r++) acc[i][j][r] = 0.f;

    const int KC = K >> 5;
    const int total = 3 * KC;
    const __nv_bfloat16* Aps[3] = {Ahi, Alo, Ahi};
    const __nv_bfloat16* Bps[3] = {Bhi, Bhi, Blo};

    // per-thread global-load mapping: 2 x 16B for A, 2 x 16B for B
    const int r0g = tid >> 2, c0g = (tid & 3) << 3;          // idx = tid
    const int r1g = (tid + 256) >> 2;                        // idx = tid+256

    const uint32_t a_sm = smem_u32(Asm);
    const uint32_t b_sm = smem_u32(Bsm);
    // ldmatrix per-thread base offsets (bytes)
    const int lrow = lane & 15, lcol = (lane >> 4) << 3;
    const uint32_t aA = a_sm + (uint32_t)(((wm + lrow) * SPAD + lcol) << 1);
    const uint32_t aB = b_sm + (uint32_t)(((wn + lrow) * SPAD + lcol) << 1);

    // stage chunk 0 into buf 0
    {
        const __nv_bfloat16* Ap = Aps[0];
        const __nv_bfloat16* Bp = Bps[0];
        *(uint4*)&Asm[0][r0g*SPAD + c0g] = *(const uint4*)(Ap + (size_t)(bm + r0g)*K + c0g);
        *(uint4*)&Asm[0][r1g*SPAD + c0g] = *(const uint4*)(Ap + (size_t)(bm + r1g)*K + c0g);
        *(uint4*)&Bsm[0][r0g*SPAD + c0g] = *(const uint4*)(Bp + (size_t)(bn + r0g)*K + c0g);
        *(uint4*)&Bsm[0][r1g*SPAD + c0g] = *(const uint4*)(Bp + (size_t)(bn + r1g)*K + c0g);
    }
    __syncthreads();

    for (int s = 0; s < total; s++) {
        const int buf = s & 1;
        // prefetch chunk s+1 into registers
        uint4 pa0, pa1, pb0, pb1;
        const bool more = (s + 1 < total);
        if (more) {
            int s2 = s + 1;
            int p = s2 / KC, kc = s2 - p * KC;
            const __nv_bfloat16* Ap = Aps[p];
            const __nv_bfloat16* Bp = Bps[p];
            const int kb = kc << 5;
            pa0 = *(const uint4*)(Ap + (size_t)(bm + r0g)*K + kb + c0g);
            pa1 = *(const uint4*)(Ap + (size_t)(bm + r1g)*K + kb + c0g);
            pb0 = *(const uint4*)(Bp + (size_t)(bn + r0g)*K + kb + c0g);
            pb1 = *(const uint4*)(Bp + (size_t)(bn + r1g)*K + kb + c0g);
        }
        // compute on buf
        const uint32_t abuf = aA + (uint32_t)(buf * 128 * SPAD * 2);
        const uint32_t bbuf = aB + (uint32_t)(buf * 128 * SPAD * 2);
        #pragma unroll
        for (int ks = 0; ks < 2; ks++) {
            uint32_t af[4][4], bf[4][2];
            #pragma unroll
            for (int mt = 0; mt < 4; mt++)
                ldmat4(af[mt][0], af[mt][1], af[mt][2], af[mt][3],
                       abuf + (uint32_t)(((mt << 4) * SPAD + (ks << 4)) << 1));
            #pragma unroll
            for (int np = 0; np < 2; np++) {
                uint32_t m0, m1, m2, m3;
                ldmat4(m0, m1, m2, m3,
                       bbuf + (uint32_t)((((np << 4)) * SPAD + (ks << 4)) << 1));
                bf[2*np][0] = m0; bf[2*np+1][0] = m1;
                bf[2*np][1] = m2; bf[2*np+1][1] = m3;
            }
            #pragma unroll
            for (int mt = 0; mt < 4; mt++)
                #pragma unroll
                for (int nt = 0; nt < 4; nt++)
                    mma16816(acc[mt][nt], af[mt], bf[nt]);
        }
        // store prefetched chunk into other buffer
        if (more) {
            const int ob = buf ^ 1;
            *(uint4*)&Asm[ob][r0g*SPAD + c0g] = pa0;
            *(uint4*)&Asm[ob][r1g*SPAD + c0g] = pa1;
            *(uint4*)&Bsm[ob][r0g*SPAD + c0g] = pb0;
            *(uint4*)&Bsm[ob][r1g*SPAD + c0g] = pb1;
        }
        __syncthreads();
    }

    // epilogue
    const int mrow = lane >> 2, ncol = (lane & 3) << 1;
    #pragma unroll
    for (int mt = 0; mt < 4; mt++) {
        #pragma unroll
        for (int nt = 0; nt < 4; nt++) {
            int r = bm + wm + (mt << 4) + mrow;
            int c = bn + wn + (nt << 3) + ncol;
            float b0 = bias[c], b1 = bias[c+1];
            float v0 = acc[mt][nt][0] + b0, v1 = acc[mt][nt][1] + b1;
            float v2 = acc[mt][nt][2] + b0, v3 = acc[mt][nt][3] + b1;
            if (GELU) { v0 = gelu_f(v0); v1 = gelu_f(v1); v2 = gelu_f(v2); v3 = gelu_f(v3); }
            *(float2*)&C[(size_t)r*N + c]       = make_float2(v0, v1);
            *(float2*)&C[(size_t)(r+8)*N + c]   = make_float2(v2, v3);
        }
    }
}

// ---------------- band + global scores ----------------
__global__ void band_scores_k(const float* __restrict__ q, const float* __restrict__ k,
                              const int* __restrict__ idxg, const unsigned char* __restrict__ klo,
                              float* __restrict__ sc) {
    extern __shared__ float sm[];
    float* kt  = sm;
    float* ssc = sm + 4096;
    int n = blockIdx.x;
    int b = blockIdx.y / HH, h = blockIdx.y % HH;
    int qr = threadIdx.x;
    int sq = n*WW + qr;
    float qv[64];
    const float4* qp = (const float4*)(q + ((size_t)(b*SS+sq))*DD + h*DHH);
    #pragma unroll
    for (int d4 = 0; d4 < 16; d4++) {
        float4 t = qp[d4];
        qv[4*d4] = t.x; qv[4*d4+1] = t.y; qv[4*d4+2] = t.z; qv[4*d4+3] = t.w;
    }
    size_t scbase = ((size_t)(b*HH+h)*SS + (size_t)n*WW) * KT;
    for (int c = 0; c < 13; c++) {
        __syncthreads();
        for (int idx = threadIdx.x; idx < 4096; idx += 256) {
            int kk = idx >> 6, d = idx & 63;
            int j = (c << 6) + kk;
            float val = 0.f;
            if (j < 768) {
                int kp = n*WW + j - WW;
                if (kp >= 0 && kp < SS) val = k[((size_t)(b*SS+kp))*DD + h*DHH + d];
            } else {
                int kp = idxg[b*GG + (j - 768)];
                val = k[((size_t)(b*SS+kp))*DD + h*DHH + d];
            }
            kt[idx] = val;
        }
        __syncthreads();
        for (int kk = 0; kk < 64; kk++) {
            int j = (c << 6) + kk;
            const float4* kr = (const float4*)(kt + (kk << 6));
            float s = 0.f;
            #pragma unroll
            for (int d4 = 0; d4 < 16; d4++) {
                float4 kv = kr[d4];
                s += qv[4*d4]*kv.x + qv[4*d4+1]*kv.y + qv[4*d4+2]*kv.z + qv[4*d4+3]*kv.w;
            }
            s *= 0.125f;
            if (j < 768) {
                int kp = n*WW + j - WW;
                int rel = j - WW - qr;
                bool ok = (kp >= 0) && (kp < SS) && klo[b*SS+kp] && (rel >= -WW) && (rel <= WW);
                if (!ok) s = NEGV;
            }
            ssc[qr*65 + kk] = s;
        }
        __syncthreads();
        for (int idx = threadIdx.x; idx < 16384; idx += 256) {
            int qq = idx >> 6, kk = idx & 63;
            sc[scbase + (size_t)qq*KT + (c << 6) + kk] = ssc[qq*65 + kk];
        }
    }
}

// ---------------- softmax ----------------
__global__ void softmax_k(float* __restrict__ sc, int rowlen) {
    __shared__ float buf[4096];
    float* row = sc + (size_t)blockIdx.x * rowlen;
    float m = -3.4e38f;
    for (int i = threadIdx.x; i < rowlen; i += 256) {
        float v = row[i]; buf[i] = v; m = fmaxf(m, v);
    }
    m = blk_max(m);
    float sum = 0.f;
    for (int i = threadIdx.x; i < rowlen; i += 256) {
        float e = expf(buf[i] - m); buf[i] = e; sum += e;
    }
    sum = blk_sum(sum);
    float inv = 1.f / sum;
    for (int i = threadIdx.x; i < rowlen; i += 256) row[i] = buf[i]*inv;
}

// ---------------- band + global PV ----------------
__global__ void band_pv_k(const float* __restrict__ probs, const float* __restrict__ v,
                          const int* __restrict__ idxg, float* __restrict__ out) {
    extern __shared__ float sm[];
    float* vt = sm;
    float* pt = sm + 4096;
    int n = blockIdx.x;
    int b = blockIdx.y / HH, h = blockIdx.y % HH;
    int qr = threadIdx.x, sq = n*WW + qr;
    float acc[64];
    #pragma unroll
    for (int d = 0; d < 64; d++) acc[d] = 0.f;
    size_t pbase = ((size_t)(b*HH+h)*SS + (size_t)n*WW) * KT;
    for (int c = 0; c < 13; c++) {
        __syncthreads();
        for (int idx = threadIdx.x; idx < 4096; idx += 256) {
            int kk = idx >> 6, d = idx & 63;
            int j = (c << 6) + kk;
            float val = 0.f;
            if (j < 768) {
                int kp = n*WW + j - WW;
                if (kp >= 0 && kp < SS) val = v[((size_t)(b*SS+kp))*DD + h*DHH + d];
            } else {
                int kp = idxg[b*GG + (j - 768)];
                val = v[((size_t)(b*SS+kp))*DD + h*DHH + d];
            }
            vt[idx] = val;
        }
        for (int idx = threadIdx.x; idx < 16384; idx += 256) {
            int qq = idx >> 6, kk = idx & 63;
            pt[qq*65 + kk] = probs[pbase + (size_t)qq*KT + (c << 6) + kk];
        }
        __syncthreads();
        for (int kk = 0; kk < 64; kk++) {
            float p = pt[qr*65 + kk];
            const float4* vr = (const float4*)(vt + (kk << 6));
            #pragma unroll
            for (int d4 = 0; d4 < 16; d4++) {
                float4 vv = vr[d4];
                acc[4*d4]   += p*vv.x; acc[4*d4+1] += p*vv.y;
                acc[4*d4+2] += p*vv.z; acc[4*d4+3] += p*vv.w;
            }
        }
    }
    float4* op = (float4*)(out + ((size_t)(b*SS+sq))*DD + h*DHH);
    #pragma unroll
    for (int d4 = 0; d4 < 16; d4++)
        op[d4] = make_float4(acc[4*d4], acc[4*d4+1], acc[4*d4+2], acc[4*d4+3]);
}

// ---------------- gather / scatter ----------------
__global__ void gather_k(const float* __restrict__ x, const int* __restrict__ idxg,
                         float* __restrict__ xg) {
    int r = blockIdx.x;
    int b = r / GG;
    int src = idxg[r];
    for (int d = threadIdx.x; d < DD; d += blockDim.x)
        xg[(size_t)r*DD + d] = x[((size_t)(b*SS+src))*DD + d];
}

__global__ void scatter_k(const float* __restrict__ og, const int* __restrict__ idxg,
                          float* __restrict__ out) {
    int r = blockIdx.x;
    int b = r / GG;
    int dst = idxg[r];
    for (int d = threadIdx.x; d < DD; d += blockDim.x)
        out[((size_t)(b*SS+dst))*DD + d] = og[(size_t)r*DD + d];
}

// ---------------- global attention ----------------
__global__ void glob_scores_k(const float* __restrict__ qg, const float* __restrict__ kga,
                              const int* __restrict__ am, float* __restrict__ sg) {
    int g = blockIdx.x;
    int b = blockIdx.y / HH, h = blockIdx.y % HH;
    __shared__ float qv[64];
    if (threadIdx.x < 64)
        qv[threadIdx.x] = qg[((size_t)(b*GG+g))*DD + h*DHH + threadIdx.x];
    __syncthreads();
    float* srow = sg + ((size_t)((b*HH+h)*GG + g))*SS;
    for (int s = threadIdx.x; s < SS; s += 256) {
        const float4* kr = (const float4*)(kga + ((size_t)(b*SS+s))*DD + h*DHH);
        float dot = 0.f;
        #pragma unroll
        for (int d4 = 0; d4 < 16; d4++) {
            float4 kv = kr[d4];
            dot += qv[4*d4]*kv.x + qv[4*d4+1]*kv.y + qv[4*d4+2]*kv.z + qv[4*d4+3]*kv.w;
        }
        srow[s] = (am[b*SS+s] != 0) ? dot*0.125f : NEGV;
    }
}

__global__ void glob_out_k(const float* __restrict__ sg, const float* __restrict__ vga,
                           float* __restrict__ og) {
    int g = blockIdx.x;
    int b = blockIdx.y / HH, h = blockIdx.y % HH;
    int d = threadIdx.x;
    const float* p = sg + ((size_t)((b*HH+h)*GG + g))*SS;
    float acc = 0.f;
    for (int s = 0; s < SS; s += 4) {
        float p0 = p[s], p1 = p[s+1], p2 = p[s+2], p3 = p[s+3];
        acc += p0 * vga[((size_t)(b*SS+s  ))*DD + h*DHH + d];
        acc += p1 * vga[((size_t)(b*SS+s+1))*DD + h*DHH + d];
        acc += p2 * vga[((size_t)(b*SS+s+2))*DD + h*DHH + d];
        acc += p3 * vga[((size_t)(b*SS+s+3))*DD + h*DHH + d];
    }
    og[((size_t)(b*GG+g))*DD + h*DHH + d] = acc;
}

// ---------------- classifier ----------------
__global__ void classify_k(const float* __restrict__ x, const float* __restrict__ Wc,
                           const float* __restrict__ bc, const int* __restrict__ lo_p,
                           const int* __restrict__ ro_p, float* __restrict__ out, int nrows) {
    int r = blockIdx.x;
    int lo = *lo_p, ro = *ro_p;
    int per_b = 63 - lo - ro;
    if (per_b <= 0) per_b = 1;
    int b = r / per_b, t = lo + (r - b*per_b);
    const float* row = x + ((size_t)(b*SS + t))*DD;
    float p[7];
    #pragma unroll
    for (int c = 0; c < 7; c++) p[c] = 0.f;
    for (int d = threadIdx.x; d < DD; d += 256) {
        float xv = row[d];
        #pragma unroll
        for (int c = 0; c < 7; c++) p[c] += xv * Wc[d*7 + c];
    }
    #pragma unroll
    for (int c = 0; c < 7; c++) {
        float tot = blk_sum(p[c]);
        if (threadIdx.x == 0) out[r*7 + c] = tot + bc[c];
    }
}

// ---------------- launch ----------------
extern "C" void kernel_launch(void* const* d_in, const int* in_sizes, int n_in,
                              void* d_out, int out_size) {
    const float* emb_tok = (const float*)d_in[0];
    const float* emb_pos = (const float*)d_in[1];
    const float* ln_e_s  = (const float*)d_in[2];
    const float* ln_e_b  = (const float*)d_in[3];
    const float* Wq  = (const float*)d_in[4];
    const float* bq  = (const float*)d_in[5];
    const float* Wk  = (const float*)d_in[6];
    const float* bk  = (const float*)d_in[7];
    const float* Wv  = (const float*)d_in[8];
    const float* bv  = (const float*)d_in[9];
    const float* Wqg = (const float*)d_in[10];
    const float* bqg = (const float*)d_in[11];
    const float* Wkg = (const float*)d_in[12];
    const float* bkg = (const float*)d_in[13];
    const float* Wvg = (const float*)d_in[14];
    const float* bvg = (const float*)d_in[15];
    const float* Wo  = (const float*)d_in[16];
    const float* bo  = (const float*)d_in[17];
    const float* ln1_s = (const float*)d_in[18];
    const float* ln1_b = (const float*)d_in[19];
    const float* Wf1 = (const float*)d_in[20];
    const float* bf1 = (const float*)d_in[21];
    const float* Wf2 = (const float*)d_in[22];
    const float* bf2 = (const float*)d_in[23];
    const float* ln2_s = (const float*)d_in[24];
    const float* ln2_b = (const float*)d_in[25];
    const float* Wc  = (const float*)d_in[26];
    const float* bc  = (const float*)d_in[27];
    const int* input_ids = (const int*)d_in[28];
    const int* attn_mask = (const int*)d_in[29];
    const int* lo_p = (const int*)d_in[30];
    const int* ro_p = (const int*)d_in[31];
    float* out = (float*)d_out;

    float *x, *q, *k, *v, *kga, *vga, *attn, *tmp, *h1, *sc, *sg, *xg, *qg, *og;
    int* idxg; unsigned char* klo;
    __nv_bfloat16 *whi, *wlo, *ahi, *alo, *xghi, *xglo;
    cudaGetSymbolAddress((void**)&x,    g_x);
    cudaGetSymbolAddress((void**)&q,    g_q);
    cudaGetSymbolAddress((void**)&k,    g_k);
    cudaGetSymbolAddress((void**)&v,    g_v);
    cudaGetSymbolAddress((void**)&kga,  g_kga);
    cudaGetSymbolAddress((void**)&vga,  g_vga);
    cudaGetSymbolAddress((void**)&attn, g_attn);
    cudaGetSymbolAddress((void**)&tmp,  g_tmp);
    cudaGetSymbolAddress((void**)&h1,   g_h1);
    cudaGetSymbolAddress((void**)&sc,   g_sc);
    cudaGetSymbolAddress((void**)&sg,   g_sg);
    cudaGetSymbolAddress((void**)&xg,   g_xg);
    cudaGetSymbolAddress((void**)&qg,   g_qg);
    cudaGetSymbolAddress((void**)&og,   g_og);
    cudaGetSymbolAddress((void**)&idxg, g_idxg);
    cudaGetSymbolAddress((void**)&klo,  g_klo);
    cudaGetSymbolAddress((void**)&whi,  g_whi);
    cudaGetSymbolAddress((void**)&wlo,  g_wlo);
    cudaGetSymbolAddress((void**)&ahi,  g_ahi);
    cudaGetSymbolAddress((void**)&alo,  g_alo);
    cudaGetSymbolAddress((void**)&xghi, g_xghi);
    cudaGetSymbolAddress((void**)&xglo, g_xglo);

    const int SMEM_BAND = (4096 + 256*65) * 4;
    cudaFuncSetAttribute(band_scores_k, cudaFuncAttributeMaxDynamicSharedMemorySize, SMEM_BAND);
    cudaFuncSetAttribute(band_pv_k,     cudaFuncAttributeMaxDynamicSharedMemorySize, SMEM_BAND);

    prep_k<<<BB, 256>>>(input_ids, attn_mask, idxg, klo);
    embed_ln_k<<<BS, 256>>>(input_ids, emb_tok, emb_pos, ln_e_s, ln_e_b, x);

    // ---- weight conversion (both layers) ----
    dim3 wb(32, 8);
    for (int l = 0; l < LL; l++) {
        size_t base = (size_t)l * LWOFF;
        wsplit_t_k<<<dim3(DD/32, DD/32), wb>>>(Wq  + (size_t)l*DD*DD, whi+base+OFF_Q,  wlo+base+OFF_Q,  DD, DD);
        wsplit_t_k<<<dim3(DD/32, DD/32), wb>>>(Wk  + (size_t)l*DD*DD, whi+base+OFF_K,  wlo+base+OFF_K,  DD, DD);
        wsplit_t_k<<<dim3(DD/32, DD/32), wb>>>(Wv  + (size_t)l*DD*DD, whi+base+OFF_V,  wlo+base+OFF_V,  DD, DD);
        wsplit_t_k<<<dim3(DD/32, DD/32), wb>>>(Wqg + (size_t)l*DD*DD, whi+base+OFF_QG, wlo+base+OFF_QG, DD, DD);
        wsplit_t_k<<<dim3(DD/32, DD/32), wb>>>(Wkg + (size_t)l*DD*DD, whi+base+OFF_KG, wlo+base+OFF_KG, DD, DD);
        wsplit_t_k<<<dim3(DD/32, DD/32), wb>>>(Wvg + (size_t)l*DD*DD, whi+base+OFF_VG, wlo+base+OFF_VG, DD, DD);
        wsplit_t_k<<<dim3(DD/32, DD/32), wb>>>(Wo  + (size_t)l*DD*DD, whi+base+OFF_O,  wlo+base+OFF_O,  DD, DD);
        wsplit_t_k<<<dim3(FFN/32, DD/32), wb>>>(Wf1 + (size_t)l*DD*FFN, whi+base+OFF_F1, wlo+base+OFF_F1, DD, FFN);
        wsplit_t_k<<<dim3(DD/32, FFN/32), wb>>>(Wf2 + (size_t)l*FFN*DD, whi+base+OFF_F2, wlo+base+OFF_F2, FFN, DD);
    }

    dim3 gT(DD/128, BS/128);       // 6 x 64
    dim3 gT1(FFN/128, BS/128);     // 24 x 64
    dim3 gTqg(DD/128, 1);          // 6 x 1
    dim3 gBand(NB, BB*HH);
    dim3 gGlob(GG, BB*HH);
    const int nXD4 = BS*DD/4, nXG4 = BB*GG*DD/4, nH14 = BS*FFN/4;

    for (int l = 0; l < LL; l++) {
        size_t base = (size_t)l * LWOFF;
        const float* bq_l  = bq  + l*DD;  const float* bk_l  = bk  + l*DD;
        const float* bv_l  = bv  + l*DD;  const float* bqg_l = bqg + l*DD;
        const float* bkg_l = bkg + l*DD;  const float* bvg_l = bvg + l*DD;
        const float* bo_l  = bo  + l*DD;
        const float* bf1_l = bf1 + l*FFN; const float* bf2_l = bf2 + l*DD;

        asplit_k<<<(nXD4+255)/256, 256>>>((const float4*)x, (__nv_bfloat162*)ahi, (__nv_bfloat162*)alo, nXD4);
        tgemm_k<0><<<gT, 256>>>(ahi, alo, whi+base+OFF_Q,  wlo+base+OFF_Q,  bq_l,  q,   BS, DD, DD);
        tgemm_k<0><<<gT, 256>>>(ahi, alo, whi+base+OFF_K,  wlo+base+OFF_K,  bk_l,  k,   BS, DD, DD);
        tgemm_k<0><<<gT, 256>>>(ahi, alo, whi+base+OFF_V,  wlo+base+OFF_V,  bv_l,  v,   BS, DD, DD);
        tgemm_k<0><<<gT, 256>>>(ahi, alo, whi+base+OFF_KG, wlo+base+OFF_KG, bkg_l, kga, BS, DD, DD);
        tgemm_k<0><<<gT, 256>>>(ahi, alo, whi+base+OFF_VG, wlo+base+OFF_VG, bvg_l, vga, BS, DD, DD);

        gather_k<<<BB*GG, 256>>>(x, idxg, xg);
        asplit_k<<<(nXG4+255)/256, 256>>>((const float4*)xg, (__nv_bfloat162*)xghi, (__nv_bfloat162*)xglo, nXG4);
        tgemm_k<0><<<gTqg, 256>>>(xghi, xglo, whi+base+OFF_QG, wlo+base+OFF_QG, bqg_l, qg, BB*GG, DD, DD);

        band_scores_k<<<gBand, 256, SMEM_BAND>>>(q, k, idxg, klo, sc);
        softmax_k<<<BB*HH*SS, 256>>>(sc, KT);
        band_pv_k<<<gBand, 256, SMEM_BAND>>>(sc, v, idxg, attn);

        glob_scores_k<<<gGlob, 256>>>(qg, kga, attn_mask, sg);
        softmax_k<<<BB*HH*GG, 256>>>(sg, SS);
        glob_out_k<<<gGlob, 64>>>(sg, vga, og);
        scatter_k<<<BB*GG, 256>>>(og, idxg, attn);

        asplit_k<<<(nXD4+255)/256, 256>>>((const float4*)attn, (__nv_bfloat162*)ahi, (__nv_bfloat162*)alo, nXD4);
        tgemm_k<0><<<gT, 256>>>(ahi, alo, whi+base+OFF_O, wlo+base+OFF_O, bo_l, tmp, BS, DD, DD);
        add_ln_k<<<BS, 256>>>(x, tmp, ln1_s + l*DD, ln1_b + l*DD);

        asplit_k<<<(nXD4+255)/256, 256>>>((const float4*)x, (__nv_bfloat162*)ahi, (__nv_bfloat162*)alo, nXD4);
        tgemm_k<1><<<gT1, 256>>>(ahi, alo, whi+base+OFF_F1, wlo+base+OFF_F1, bf1_l, h1, BS, FFN, DD);
        asplit_k<<<(nH14+255)/256, 256>>>((const float4*)h1, (__nv_bfloat162*)ahi, (__nv_bfloat162*)alo, nH14);
        tgemm_k<0><<<gT, 256>>>(ahi, alo, whi+base+OFF_F2, wlo+base+OFF_F2, bf2_l, tmp, BS, DD, FFN);
        add_ln_k<<<BS, 256>>>(x, tmp, ln2_s + l*DD, ln2_b + l*DD);
    }

    int nrows = out_size / 7;
    classify_k<<<nrows, 256>>>(x, Wc, bc, lo_p, ro_p, out, nrows);
}

// round 4
// speedup vs baseline: 1.7020x; 1.2120x over previous
#include <cuda_runtime.h>
#include <cuda_bf16.h>
#include <cstdint>
#include <math.h>

#define BB 2
#define SS 4096
#define DD 768
#define HH 12
#define LL 2
#define DHH 64
#define WW 256
#define GG 64
#define FFN 3072
#define NB 16
#define KT 832
#define SEPID 2
#define NEGV -1000000000.0f
#define BS (BB*SS)
#define QS (5*DD)          // merged qkv row stride (3840)

// weight arena offsets (bf16, transposed [N][K]); Q,K,V,KG,VG contiguous for merged GEMM
#define WSZ_DD (DD*DD)
#define OFF_Q  0
#define OFF_K  (1*WSZ_DD)
#define OFF_V  (2*WSZ_DD)
#define OFF_KG (3*WSZ_DD)
#define OFF_VG (4*WSZ_DD)
#define OFF_QG (5*WSZ_DD)
#define OFF_O  (6*WSZ_DD)
#define OFF_F1 (7*WSZ_DD)
#define OFF_F2 (7*WSZ_DD + DD*FFN)
#define LWOFF  (7*WSZ_DD + 2*DD*FFN)

// ---------------- scratch ----------------
__device__ float g_x[BS*DD];
__device__ float g_qkv[(size_t)BS*QS];          // q|k|v|kga|vga strided
__device__ float g_attn[BS*DD];
__device__ float g_tmp[BS*DD];
__device__ float g_h1[BS*FFN];
__device__ float g_sg[(size_t)BB*HH*GG*SS];
__device__ float g_xg[BB*GG*DD];
__device__ float g_qg[BB*GG*DD];
__device__ float g_og[BB*GG*DD];
__device__ float g_bcat[2*QS];
__device__ int   g_idxg[BB*GG];
__device__ unsigned char g_klo[BS];

__device__ __align__(16) __nv_bfloat16 g_whi[2*LWOFF];
__device__ __align__(16) __nv_bfloat16 g_wlo[2*LWOFF];
__device__ __align__(16) __nv_bfloat16 g_ahi[BS*FFN];
__device__ __align__(16) __nv_bfloat16 g_alo[BS*FFN];
__device__ __align__(16) __nv_bfloat16 g_xghi[BB*GG*DD];
__device__ __align__(16) __nv_bfloat16 g_xglo[BB*GG*DD];

// ---------------- helpers ----------------
__device__ __forceinline__ uint32_t smem_u32(const void* p) {
    uint32_t a;
    asm("{ .reg .u64 t; cvta.to.shared.u64 t, %1; cvt.u32.u64 %0, t; }" : "=r"(a) : "l"(p));
    return a;
}

__device__ __forceinline__ void ldmat4(uint32_t& r0, uint32_t& r1, uint32_t& r2, uint32_t& r3,
                                       uint32_t addr) {
    asm volatile("ldmatrix.sync.aligned.m8n8.x4.shared.b16 {%0,%1,%2,%3}, [%4];"
        : "=r"(r0), "=r"(r1), "=r"(r2), "=r"(r3) : "r"(addr));
}

__device__ __forceinline__ void mma16816(float* d, const uint32_t* a, const uint32_t* b) {
    asm volatile("mma.sync.aligned.m16n8k16.row.col.f32.bf16.bf16.f32 "
        "{%0,%1,%2,%3}, {%4,%5,%6,%7}, {%8,%9}, {%0,%1,%2,%3};"
        : "+f"(d[0]), "+f"(d[1]), "+f"(d[2]), "+f"(d[3])
        : "r"(a[0]), "r"(a[1]), "r"(a[2]), "r"(a[3]), "r"(b[0]), "r"(b[1]));
}

__device__ __forceinline__ float gelu_f(float v) {
    return 0.5f*v*(1.f + tanhf(0.7978845608028654f*(v + 0.044715f*v*v*v)));
}

// ---------------- block reductions ----------------
__device__ __forceinline__ float blk_sum(float v) {
    __shared__ float sm[33];
    int lane = threadIdx.x & 31, wid = threadIdx.x >> 5;
    #pragma unroll
    for (int o = 16; o; o >>= 1) v += __shfl_xor_sync(0xffffffffu, v, o);
    if (lane == 0) sm[wid] = v;
    __syncthreads();
    if (wid == 0) {
        int nw = (blockDim.x + 31) >> 5;
        float r = (lane < nw) ? sm[lane] : 0.f;
        #pragma unroll
        for (int o = 16; o; o >>= 1) r += __shfl_xor_sync(0xffffffffu, r, o);
        if (lane == 0) sm[32] = r;
    }
    __syncthreads();
    float r = sm[32];
    __syncthreads();
    return r;
}

__device__ __forceinline__ float blk_max(float v) {
    __shared__ float sm[33];
    int lane = threadIdx.x & 31, wid = threadIdx.x >> 5;
    #pragma unroll
    for (int o = 16; o; o >>= 1) v = fmaxf(v, __shfl_xor_sync(0xffffffffu, v, o));
    if (lane == 0) sm[wid] = v;
    __syncthreads();
    if (wid == 0) {
        int nw = (blockDim.x + 31) >> 5;
        float r = (lane < nw) ? sm[lane] : -3.4e38f;
        #pragma unroll
        for (int o = 16; o; o >>= 1) r = fmaxf(r, __shfl_xor_sync(0xffffffffu, r, o));
        if (lane == 0) sm[32] = r;
    }
    __syncthreads();
    float r = sm[32];
    __syncthreads();
    return r;
}

// ---------------- prep ----------------
__global__ void prep_k(const int* __restrict__ ids, const int* __restrict__ am,
                       int* __restrict__ idxg, unsigned char* __restrict__ klo) {
    int b = blockIdx.x;
    for (int s = threadIdx.x; s < SS; s += blockDim.x) {
        bool g = (ids[b*SS+s] == SEPID) || (s == 0);
        klo[b*SS+s] = (am[b*SS+s] != 0 && !g) ? 1 : 0;
    }
    if (threadIdx.x == 0) {
        int cnt = 0;
        for (int s = 0; s < SS && cnt < GG; s++)
            if (ids[b*SS+s] == SEPID || s == 0) idxg[b*GG + cnt++] = s;
        for (; cnt < GG; cnt++) idxg[b*GG + cnt] = 0;
    }
}

// ---------------- embedding + LN ----------------
__global__ void embed_ln_k(const int* __restrict__ ids, const float* __restrict__ etok,
                           const float* __restrict__ epos, const float* __restrict__ lns,
                           const float* __restrict__ lnb, float* __restrict__ x) {
    int row = blockIdx.x;
    int spos = row & (SS - 1);
    int id = ids[row];
    const float* te = etok + (size_t)id * DD;
    const float* pe = epos + (size_t)spos * DD;
    float v[3]; float sum = 0.f;
    #pragma unroll
    for (int i = 0; i < 3; i++) {
        int d = threadIdx.x + i*256;
        float val = te[d] + pe[d];
        v[i] = val; sum += val;
    }
    float mean = blk_sum(sum) * (1.0f/DD);
    float sq = 0.f;
    #pragma unroll
    for (int i = 0; i < 3; i++) { float c = v[i] - mean; sq += c*c; }
    float inv = rsqrtf(blk_sum(sq) * (1.0f/DD) + 1e-5f);
    #pragma unroll
    for (int i = 0; i < 3; i++) {
        int d = threadIdx.x + i*256;
        x[(size_t)row*DD + d] = (v[i] - mean)*inv*lns[d] + lnb[d];
    }
}

// ---------------- residual add + LN ----------------
__global__ void add_ln_k(float* __restrict__ x, const float* __restrict__ t,
                         const float* __restrict__ lns, const float* __restrict__ lnb) {
    int row = blockIdx.x;
    size_t base = (size_t)row * DD;
    float v[3]; float sum = 0.f;
    #pragma unroll
    for (int i = 0; i < 3; i++) {
        int d = threadIdx.x + i*256;
        float val = x[base+d] + t[base+d];
        v[i] = val; sum += val;
    }
    float mean = blk_sum(sum) * (1.0f/DD);
    float sq = 0.f;
    #pragma unroll
    for (int i = 0; i < 3; i++) { float c = v[i] - mean; sq += c*c; }
    float inv = rsqrtf(blk_sum(sq) * (1.0f/DD) + 1e-5f);
    #pragma unroll
    for (int i = 0; i < 3; i++) {
        int d = threadIdx.x + i*256;
        x[base+d] = (v[i] - mean)*inv*lns[d] + lnb[d];
    }
}

// ---------------- conversions ----------------
__global__ void asplit_k(const float4* __restrict__ A, __nv_bfloat162* __restrict__ hi,
                         __nv_bfloat162* __restrict__ lo, int n4) {
    int i = blockIdx.x*256 + threadIdx.x;
    if (i >= n4) return;
    float4 v = A[i];
    __nv_bfloat16 hx = __float2bfloat16(v.x), hy = __float2bfloat16(v.y);
    __nv_bfloat16 hz = __float2bfloat16(v.z), hw = __float2bfloat16(v.w);
    hi[2*i]   = __halves2bfloat162(hx, hy);
    hi[2*i+1] = __halves2bfloat162(hz, hw);
    __nv_bfloat16 lx = __float2bfloat16(v.x - __bfloat162float(hx));
    __nv_bfloat16 ly = __float2bfloat16(v.y - __bfloat162float(hy));
    __nv_bfloat16 lz = __float2bfloat16(v.z - __bfloat162float(hz));
    __nv_bfloat16 lw = __float2bfloat16(v.w - __bfloat162float(hw));
    lo[2*i]   = __halves2bfloat162(lx, ly);
    lo[2*i+1] = __halves2bfloat162(lz, lw);
}

// weight split + transpose: W[K][N] fp32 -> hi/lo [N][K] bf16
__global__ void wsplit_t_k(const float* __restrict__ W, __nv_bfloat16* __restrict__ hi,
                           __nv_bfloat16* __restrict__ lo, int K, int N) {
    __shared__ float t[32][33];
    int n0 = blockIdx.x*32, k0 = blockIdx.y*32;
    int tx = threadIdx.x, ty = threadIdx.y;
    #pragma unroll
    for (int i = 0; i < 4; i++)
        t[ty+8*i][tx] = W[(size_t)(k0+ty+8*i)*N + n0 + tx];
    __syncthreads();
    #pragma unroll
    for (int i = 0; i < 4; i++) {
        float v = t[tx][ty+8*i];
        __nv_bfloat16 h = __float2bfloat16(v);
        size_t o = (size_t)(n0+ty+8*i)*K + k0 + tx;
        hi[o] = h;
        lo[o] = __float2bfloat16(v - __bfloat162float(h));
    }
}

// bias concat for merged QKV GEMM
__global__ void bcat_k(const float* __restrict__ b0, const float* __restrict__ b1,
                       const float* __restrict__ b2, const float* __restrict__ b3,
                       const float* __restrict__ b4, float* __restrict__ dst) {
    int i = blockIdx.x*256 + threadIdx.x;
    if (i >= QS) return;
    int seg = i / DD, off = i - seg*DD;
    const float* src = (seg == 0) ? b0 : (seg == 1) ? b1 : (seg == 2) ? b2 : (seg == 3) ? b3 : b4;
    dst[i] = src[off];
}

// ---------------- tensor-core GEMM (mma.sync bf16, 3-pass hi/lo compensated) -----
#define SPAD 40

template<int GELU>
__global__ void __launch_bounds__(256) tgemm_k(
        const __nv_bfloat16* __restrict__ Ahi, const __nv_bfloat16* __restrict__ Alo,
        const __nv_bfloat16* __restrict__ Bhi, const __nv_bfloat16* __restrict__ Blo,
        const float* __restrict__ bias, float* __restrict__ C,
        int M, int N, int K) {
    __shared__ __nv_bfloat16 Asm[2][128*SPAD];
    __shared__ __nv_bfloat16 Bsm[2][128*SPAD];
    const int bn = blockIdx.x << 7, bm = blockIdx.y << 7;
    const int tid = threadIdx.x, wid = tid >> 5, lane = tid & 31;
    const int wm = (wid >> 2) << 6;
    const int wn = (wid & 3) << 5;

    float acc[4][4][4];
    #pragma unroll
    for (int i = 0; i < 4; i++)
        #pragma unroll
        for (int j = 0; j < 4; j++)
            #pragma unroll
            for (int r = 0; r < 4; r++) acc[i][j][r] = 0.f;

    const int KC = K >> 5;
    const int total = 3 * KC;
    const __nv_bfloat16* Aps[3] = {Ahi, Alo, Ahi};
    const __nv_bfloat16* Bps[3] = {Bhi, Bhi, Blo};

    const int r0g = tid >> 2, c0g = (tid & 3) << 3;
    const int r1g = (tid + 256) >> 2;

    const uint32_t a_sm = smem_u32(Asm);
    const uint32_t b_sm = smem_u32(Bsm);
    const int lrow = lane & 15, lcol = (lane >> 4) << 3;
    const uint32_t aA = a_sm + (uint32_t)(((wm + lrow) * SPAD + lcol) << 1);
    const uint32_t aB = b_sm + (uint32_t)(((wn + lrow) * SPAD + lcol) << 1);

    {
        const __nv_bfloat16* Ap = Aps[0];
        const __nv_bfloat16* Bp = Bps[0];
        *(uint4*)&Asm[0][r0g*SPAD + c0g] = *(const uint4*)(Ap + (size_t)(bm + r0g)*K + c0g);
        *(uint4*)&Asm[0][r1g*SPAD + c0g] = *(const uint4*)(Ap + (size_t)(bm + r1g)*K + c0g);
        *(uint4*)&Bsm[0][r0g*SPAD + c0g] = *(const uint4*)(Bp + (size_t)(bn + r0g)*K + c0g);
        *(uint4*)&Bsm[0][r1g*SPAD + c0g] = *(const uint4*)(Bp + (size_t)(bn + r1g)*K + c0g);
    }
    __syncthreads();

    for (int s = 0; s < total; s++) {
        const int buf = s & 1;
        uint4 pa0, pa1, pb0, pb1;
        const bool more = (s + 1 < total);
        if (more) {
            int s2 = s + 1;
            int p = s2 / KC, kc = s2 - p * KC;
            const __nv_bfloat16* Ap = Aps[p];
            const __nv_bfloat16* Bp = Bps[p];
            const int kb = kc << 5;
            pa0 = *(const uint4*)(Ap + (size_t)(bm + r0g)*K + kb + c0g);
            pa1 = *(const uint4*)(Ap + (size_t)(bm + r1g)*K + kb + c0g);
            pb0 = *(const uint4*)(Bp + (size_t)(bn + r0g)*K + kb + c0g);
            pb1 = *(const uint4*)(Bp + (size_t)(bn + r1g)*K + kb + c0g);
        }
        const uint32_t abuf = aA + (uint32_t)(buf * 128 * SPAD * 2);
        const uint32_t bbuf = aB + (uint32_t)(buf * 128 * SPAD * 2);
        #pragma unroll
        for (int ks = 0; ks < 2; ks++) {
            uint32_t af[4][4], bf[4][2];
            #pragma unroll
            for (int mt = 0; mt < 4; mt++)
                ldmat4(af[mt][0], af[mt][1], af[mt][2], af[mt][3],
                       abuf + (uint32_t)(((mt << 4) * SPAD + (ks << 4)) << 1));
            #pragma unroll
            for (int np = 0; np < 2; np++) {
                uint32_t m0, m1, m2, m3;
                ldmat4(m0, m1, m2, m3,
                       bbuf + (uint32_t)((((np << 4)) * SPAD + (ks << 4)) << 1));
                bf[2*np][0] = m0; bf[2*np+1][0] = m1;
                bf[2*np][1] = m2; bf[2*np+1][1] = m3;
            }
            #pragma unroll
            for (int mt = 0; mt < 4; mt++)
                #pragma unroll
                for (int nt = 0; nt < 4; nt++)
                    mma16816(acc[mt][nt], af[mt], bf[nt]);
        }
        if (more) {
            const int ob = buf ^ 1;
            *(uint4*)&Asm[ob][r0g*SPAD + c0g] = pa0;
            *(uint4*)&Asm[ob][r1g*SPAD + c0g] = pa1;
            *(uint4*)&Bsm[ob][r0g*SPAD + c0g] = pb0;
            *(uint4*)&Bsm[ob][r1g*SPAD + c0g] = pb1;
        }
        __syncthreads();
    }

    const int mrow = lane >> 2, ncol = (lane & 3) << 1;
    #pragma unroll
    for (int mt = 0; mt < 4; mt++) {
        #pragma unroll
        for (int nt = 0; nt < 4; nt++) {
            int r = bm + wm + (mt << 4) + mrow;
            int c = bn + wn + (nt << 3) + ncol;
            float b0 = bias[c], b1 = bias[c+1];
            float v0 = acc[mt][nt][0] + b0, v1 = acc[mt][nt][1] + b1;
            float v2 = acc[mt][nt][2] + b0, v3 = acc[mt][nt][3] + b1;
            if (GELU) { v0 = gelu_f(v0); v1 = gelu_f(v1); v2 = gelu_f(v2); v3 = gelu_f(v3); }
            *(float2*)&C[(size_t)r*N + c]       = make_float2(v0, v1);
            *(float2*)&C[(size_t)(r+8)*N + c]   = make_float2(v2, v3);
        }
    }
}

// ---------------- fused band attention (online softmax) ----------------
// grid (NB, B*H), 256 threads, one q row per thread. 13 chunks of 64 keys.
// Replaces band_scores + softmax + band_pv; no global score buffer.
__global__ void band_fused_k(const float* __restrict__ qkv, const int* __restrict__ idxg,
                             const unsigned char* __restrict__ klo, float* __restrict__ out) {
    extern __shared__ float sm[];
    float* kt  = sm;            // 64 keys x 64 dims
    float* vt  = sm + 4096;     // 64 vals x 64 dims
    float* ssc = sm + 8192;     // 256 x 65 scores (thread-private rows)
    int n = blockIdx.x;
    int b = blockIdx.y / HH, h = blockIdx.y % HH;
    int qr = threadIdx.x;
    int sq = n*WW + qr;
    float qv[64];
    const float4* qp = (const float4*)(qkv + (size_t)(b*SS+sq)*QS + h*DHH);
    #pragma unroll
    for (int d4 = 0; d4 < 16; d4++) {
        float4 t = qp[d4];
        qv[4*d4] = t.x; qv[4*d4+1] = t.y; qv[4*d4+2] = t.z; qv[4*d4+3] = t.w;
    }
    float acc[64];
    #pragma unroll
    for (int d = 0; d < 64; d++) acc[d] = 0.f;
    float mrow = -INFINITY, lrow = 0.f;

    for (int c = 0; c < 13; c++) {
        __syncthreads();
        for (int idx = threadIdx.x; idx < 4096; idx += 256) {
            int kk = idx >> 6, d = idx & 63;
            int j = (c << 6) + kk;
            float kval = 0.f, vval = 0.f;
            if (j < 768) {
                int kp = n*WW + j - WW;
                if (kp >= 0 && kp < SS) {
                    size_t base = (size_t)(b*SS+kp)*QS + h*DHH + d;
                    kval = qkv[base + DD];
                    vval = qkv[base + 2*DD];
                }
            } else {
                int kp = idxg[b*GG + (j - 768)];
                size_t base = (size_t)(b*SS+kp)*QS + h*DHH + d;
                kval = qkv[base + DD];
                vval = qkv[base + 2*DD];
            }
            kt[idx] = kval;
            vt[idx] = vval;
        }
        __syncthreads();
        // sweep 1: scores
        float cmax = -INFINITY;
        for (int kk = 0; kk < 64; kk++) {
            int j = (c << 6) + kk;
            const float4* kr = (const float4*)(kt + (kk << 6));
            float s = 0.f;
            #pragma unroll
            for (int d4 = 0; d4 < 16; d4++) {
                float4 kv = kr[d4];
                s += qv[4*d4]*kv.x + qv[4*d4+1]*kv.y + qv[4*d4+2]*kv.z + qv[4*d4+3]*kv.w;
            }
            s *= 0.125f;
            if (j < 768) {
                int kp = n*WW + j - WW;
                int rel = j - WW - qr;
                bool ok = (kp >= 0) && (kp < SS) && klo[b*SS+kp] && (rel >= -WW) && (rel <= WW);
                if (!ok) s = NEGV;
            }
            ssc[qr*65 + kk] = s;
            cmax = fmaxf(cmax, s);
        }
        // online update
        float mnew = fmaxf(mrow, cmax);
        float rescale = expf(mrow - mnew);     // first chunk: exp(-inf)=0
        lrow *= rescale;
        #pragma unroll
        for (int d = 0; d < 64; d++) acc[d] *= rescale;
        // sweep 2: exp + PV accumulate
        for (int kk = 0; kk < 64; kk++) {
            float e = expf(ssc[qr*65 + kk] - mnew);
            lrow += e;
            const float4* vr = (const float4*)(vt + (kk << 6));
            #pragma unroll
            for (int d4 = 0; d4 < 16; d4++) {
                float4 vv = vr[d4];
                acc[4*d4]   += e*vv.x; acc[4*d4+1] += e*vv.y;
                acc[4*d4+2] += e*vv.z; acc[4*d4+3] += e*vv.w;
            }
        }
        mrow = mnew;
    }
    float inv = 1.f / lrow;
    float4* op = (float4*)(out + (size_t)(b*SS+sq)*DD + h*DHH);
    #pragma unroll
    for (int d4 = 0; d4 < 16; d4++)
        op[d4] = make_float4(acc[4*d4]*inv, acc[4*d4+1]*inv, acc[4*d4+2]*inv, acc[4*d4+3]*inv);
}

// ---------------- softmax (global attention rows, rowlen 4096) ----------------
__global__ void softmax_k(float* __restrict__ sc, int rowlen) {
    __shared__ float buf[4096];
    float* row = sc + (size_t)blockIdx.x * rowlen;
    float m = -3.4e38f;
    for (int i = threadIdx.x; i < rowlen; i += 256) {
        float v = row[i]; buf[i] = v; m = fmaxf(m, v);
    }
    m = blk_max(m);
    float sum = 0.f;
    for (int i = threadIdx.x; i < rowlen; i += 256) {
        float e = expf(buf[i] - m); buf[i] = e; sum += e;
    }
    sum = blk_sum(sum);
    float inv = 1.f / sum;
    for (int i = threadIdx.x; i < rowlen; i += 256) row[i] = buf[i]*inv;
}

// ---------------- gather / scatter ----------------
__global__ void gather_k(const float* __restrict__ x, const int* __restrict__ idxg,
                         float* __restrict__ xg) {
    int r = blockIdx.x;
    int b = r / GG;
    int src = idxg[r];
    for (int d = threadIdx.x; d < DD; d += blockDim.x)
        xg[(size_t)r*DD + d] = x[((size_t)(b*SS+src))*DD + d];
}

__global__ void scatter_k(const float* __restrict__ og, const int* __restrict__ idxg,
                          float* __restrict__ out) {
    int r = blockIdx.x;
    int b = r / GG;
    int dst = idxg[r];
    for (int d = threadIdx.x; d < DD; d += blockDim.x)
        out[((size_t)(b*SS+dst))*DD + d] = og[(size_t)r*DD + d];
}

// ---------------- global attention ----------------
__global__ void glob_scores_k(const float* __restrict__ qg, const float* __restrict__ qkv,
                              const int* __restrict__ am, float* __restrict__ sg) {
    int g = blockIdx.x;
    int b = blockIdx.y / HH, h = blockIdx.y % HH;
    __shared__ float qv[64];
    if (threadIdx.x < 64)
        qv[threadIdx.x] = qg[((size_t)(b*GG+g))*DD + h*DHH + threadIdx.x];
    __syncthreads();
    float* srow = sg + ((size_t)((b*HH+h)*GG + g))*SS;
    const float* kga = qkv + 3*DD;
    for (int s = threadIdx.x; s < SS; s += 256) {
        const float4* kr = (const float4*)(kga + (size_t)(b*SS+s)*QS + h*DHH);
        float dot = 0.f;
        #pragma unroll
        for (int d4 = 0; d4 < 16; d4++) {
            float4 kv = kr[d4];
            dot += qv[4*d4]*kv.x + qv[4*d4+1]*kv.y + qv[4*d4+2]*kv.z + qv[4*d4+3]*kv.w;
        }
        srow[s] = (am[b*SS+s] != 0) ? dot*0.125f : NEGV;
    }
}

__global__ void glob_out_k(const float* __restrict__ sg, const float* __restrict__ qkv,
                           float* __restrict__ og) {
    int g = blockIdx.x;
    int b = blockIdx.y / HH, h = blockIdx.y % HH;
    int grp = threadIdx.x >> 6, d = threadIdx.x & 63;
    const float* p = sg + ((size_t)((b*HH+h)*GG + g))*SS;
    const float* vga = qkv + 4*DD;
    float acc = 0.f;
    int s0 = grp << 10;
    for (int s = s0; s < s0 + 1024; s += 4) {
        float p0 = p[s], p1 = p[s+1], p2 = p[s+2], p3 = p[s+3];
        acc += p0 * vga[(size_t)(b*SS+s  )*QS + h*DHH + d];
        acc += p1 * vga[(size_t)(b*SS+s+1)*QS + h*DHH + d];
        acc += p2 * vga[(size_t)(b*SS+s+2)*QS + h*DHH + d];
        acc += p3 * vga[(size_t)(b*SS+s+3)*QS + h*DHH + d];
    }
    __shared__ float red[4][64];
    red[grp][d] = acc;
    __syncthreads();
    if (grp == 0)
        og[(size_t)(b*GG+g)*DD + h*DHH + d] = red[0][d] + red[1][d] + red[2][d] + red[3][d];
}

// ---------------- classifier ----------------
__global__ void classify_k(const float* __restrict__ x, const float* __restrict__ Wc,
                           const float* __restrict__ bc, const int* __restrict__ lo_p,
                           const int* __restrict__ ro_p, float* __restrict__ out, int nrows) {
    int r = blockIdx.x;
    int lo = *lo_p, ro = *ro_p;
    int per_b = 63 - lo - ro;
    if (per_b <= 0) per_b = 1;
    int b = r / per_b, t = lo + (r - b*per_b);
    const float* row = x + ((size_t)(b*SS + t))*DD;
    float p[7];
    #pragma unroll
    for (int c = 0; c < 7; c++) p[c] = 0.f;
    for (int d = threadIdx.x; d < DD; d += 256) {
        float xv = row[d];
        #pragma unroll
        for (int c = 0; c < 7; c++) p[c] += xv * Wc[d*7 + c];
    }
    #pragma unroll
    for (int c = 0; c < 7; c++) {
        float tot = blk_sum(p[c]);
        if (threadIdx.x == 0) out[r*7 + c] = tot + bc[c];
    }
}

// ---------------- launch ----------------
extern "C" void kernel_launch(void* const* d_in, const int* in_sizes, int n_in,
                              void* d_out, int out_size) {
    const float* emb_tok = (const float*)d_in[0];
    const float* emb_pos = (const float*)d_in[1];
    const float* ln_e_s  = (const float*)d_in[2];
    const float* ln_e_b  = (const float*)d_in[3];
    const float* Wq  = (const float*)d_in[4];
    const float* bq  = (const float*)d_in[5];
    const float* Wk  = (const float*)d_in[6];
    const float* bk  = (const float*)d_in[7];
    const float* Wv  = (const float*)d_in[8];
    const float* bv  = (const float*)d_in[9];
    const float* Wqg = (const float*)d_in[10];
    const float* bqg = (const float*)d_in[11];
    const float* Wkg = (const float*)d_in[12];
    const float* bkg = (const float*)d_in[13];
    const float* Wvg = (const float*)d_in[14];
    const float* bvg = (const float*)d_in[15];
    const float* Wo  = (const float*)d_in[16];
    const float* bo  = (const float*)d_in[17];
    const float* ln1_s = (const float*)d_in[18];
    const float* ln1_b = (const float*)d_in[19];
    const float* Wf1 = (const float*)d_in[20];
    const float* bf1 = (const float*)d_in[21];
    const float* Wf2 = (const float*)d_in[22];
    const float* bf2 = (const float*)d_in[23];
    const float* ln2_s = (const float*)d_in[24];
    const float* ln2_b = (const float*)d_in[25];
    const float* Wc  = (const float*)d_in[26];
    const float* bc  = (const float*)d_in[27];
    const int* input_ids = (const int*)d_in[28];
    const int* attn_mask = (const int*)d_in[29];
    const int* lo_p = (const int*)d_in[30];
    const int* ro_p = (const int*)d_in[31];
    float* out = (float*)d_out;

    float *x, *qkv, *attn, *tmp, *h1, *sg, *xg, *qg, *og, *bcat;
    int* idxg; unsigned char* klo;
    __nv_bfloat16 *whi, *wlo, *ahi, *alo, *xghi, *xglo;
    cudaGetSymbolAddress((void**)&x,    g_x);
    cudaGetSymbolAddress((void**)&qkv,  g_qkv);
    cudaGetSymbolAddress((void**)&attn, g_attn);
    cudaGetSymbolAddress((void**)&tmp,  g_tmp);
    cudaGetSymbolAddress((void**)&h1,   g_h1);
    cudaGetSymbolAddress((void**)&sg,   g_sg);
    cudaGetSymbolAddress((void**)&xg,   g_xg);
    cudaGetSymbolAddress((void**)&qg,   g_qg);
    cudaGetSymbolAddress((void**)&og,   g_og);
    cudaGetSymbolAddress((void**)&bcat, g_bcat);
    cudaGetSymbolAddress((void**)&idxg, g_idxg);
    cudaGetSymbolAddress((void**)&klo,  g_klo);
    cudaGetSymbolAddress((void**)&whi,  g_whi);
    cudaGetSymbolAddress((void**)&wlo,  g_wlo);
    cudaGetSymbolAddress((void**)&ahi,  g_ahi);
    cudaGetSymbolAddress((void**)&alo,  g_alo);
    cudaGetSymbolAddress((void**)&xghi, g_xghi);
    cudaGetSymbolAddress((void**)&xglo, g_xglo);

    const int SMEM_BAND = (4096 + 4096 + 256*65) * 4;   // 99328 bytes
    cudaFuncSetAttribute(band_fused_k, cudaFuncAttributeMaxDynamicSharedMemorySize, SMEM_BAND);

    prep_k<<<BB, 256>>>(input_ids, attn_mask, idxg, klo);
    embed_ln_k<<<BS, 256>>>(input_ids, emb_tok, emb_pos, ln_e_s, ln_e_b, x);

    // ---- weight conversion + bias concat (both layers) ----
    dim3 wb(32, 8);
    for (int l = 0; l < LL; l++) {
        size_t base = (size_t)l * LWOFF;
        wsplit_t_k<<<dim3(DD/32, DD/32), wb>>>(Wq  + (size_t)l*DD*DD, whi+base+OFF_Q,  wlo+base+OFF_Q,  DD, DD);
        wsplit_t_k<<<dim3(DD/32, DD/32), wb>>>(Wk  + (size_t)l*DD*DD, whi+base+OFF_K,  wlo+base+OFF_K,  DD, DD);
        wsplit_t_k<<<dim3(DD/32, DD/32), wb>>>(Wv  + (size_t)l*DD*DD, whi+base+OFF_V,  wlo+base+OFF_V,  DD, DD);
        wsplit_t_k<<<dim3(DD/32, DD/32), wb>>>(Wkg + (size_t)l*DD*DD, whi+base+OFF_KG, wlo+base+OFF_KG, DD, DD);
        wsplit_t_k<<<dim3(DD/32, DD/32), wb>>>(Wvg + (size_t)l*DD*DD, whi+base+OFF_VG, wlo+base+OFF_VG, DD, DD);
        wsplit_t_k<<<dim3(DD/32, DD/32), wb>>>(Wqg + (size_t)l*DD*DD, whi+base+OFF_QG, wlo+base+OFF_QG, DD, DD);
        wsplit_t_k<<<dim3(DD/32, DD/32), wb>>>(Wo  + (size_t)l*DD*DD, whi+base+OFF_O,  wlo+base+OFF_O,  DD, DD);
        wsplit_t_k<<<dim3(FFN/32, DD/32), wb>>>(Wf1 + (size_t)l*DD*FFN, whi+base+OFF_F1, wlo+base+OFF_F1, DD, FFN);
        wsplit_t_k<<<dim3(DD/32, FFN/32), wb>>>(Wf2 + (size_t)l*FFN*DD, whi+base+OFF_F2, wlo+base+OFF_F2, FFN, DD);
        bcat_k<<<(QS+255)/256, 256>>>(bq + l*DD, bk + l*DD, bv + l*DD, bkg + l*DD, bvg + l*DD,
                                      bcat + l*QS);
    }

    dim3 gTqkv(QS/128, BS/128);    // 30 x 64
    dim3 gT(DD/128, BS/128);       // 6 x 64
    dim3 gT1(FFN/128, BS/128);     // 24 x 64
    dim3 gTqg(DD/128, 1);          // 6 x 1
    dim3 gBand(NB, BB*HH);
    dim3 gGlob(GG, BB*HH);
    const int nXD4 = BS*DD/4, nXG4 = BB*GG*DD/4, nH14 = BS*FFN/4;

    for (int l = 0; l < LL; l++) {
        size_t base = (size_t)l * LWOFF;
        const float* bqg_l = bqg + l*DD;
        const float* bo_l  = bo  + l*DD;
        const float* bf1_l = bf1 + l*FFN; const float* bf2_l = bf2 + l*DD;

        asplit_k<<<(nXD4+255)/256, 256>>>((const float4*)x, (__nv_bfloat162*)ahi, (__nv_bfloat162*)alo, nXD4);
        tgemm_k<0><<<gTqkv, 256>>>(ahi, alo, whi+base+OFF_Q, wlo+base+OFF_Q, bcat + l*QS, qkv, BS, QS, DD);

        gather_k<<<BB*GG, 256>>>(x, idxg, xg);
        asplit_k<<<(nXG4+255)/256, 256>>>((const float4*)xg, (__nv_bfloat162*)xghi, (__nv_bfloat162*)xglo, nXG4);
        tgemm_k<0><<<gTqg, 256>>>(xghi, xglo, whi+base+OFF_QG, wlo+base+OFF_QG, bqg_l, qg, BB*GG, DD, DD);

        band_fused_k<<<gBand, 256, SMEM_BAND>>>(qkv, idxg, klo, attn);

        glob_scores_k<<<gGlob, 256>>>(qg, qkv, attn_mask, sg);
        softmax_k<<<BB*HH*GG, 256>>>(sg, SS);
        glob_out_k<<<gGlob, 256>>>(sg, qkv, og);
        scatter_k<<<BB*GG, 256>>>(og, idxg, attn);

        asplit_k<<<(nXD4+255)/256, 256>>>((const float4*)attn, (__nv_bfloat162*)ahi, (__nv_bfloat162*)alo, nXD4);
        tgemm_k<0><<<gT, 256>>>(ahi, alo, whi+base+OFF_O, wlo+base+OFF_O, bo_l, tmp, BS, DD, DD);
        add_ln_k<<<BS, 256>>>(x, tmp, ln1_s + l*DD, ln1_b + l*DD);

        asplit_k<<<(nXD4+255)/256, 256>>>((const float4*)x, (__nv_bfloat162*)ahi, (__nv_bfloat162*)alo, nXD4);
        tgemm_k<1><<<gT1, 256>>>(ahi, alo, whi+base+OFF_F1, wlo+base+OFF_F1, bf1_l, h1, BS, FFN, DD);
        asplit_k<<<(nH14+255)/256, 256>>>((const float4*)h1, (__nv_bfloat162*)ahi, (__nv_bfloat162*)alo, nH14);
        tgemm_k<0><<<gT, 256>>>(ahi, alo, whi+base+OFF_F2, wlo+base+OFF_F2, bf2_l, tmp, BS, DD, FFN);
        add_ln_k<<<BS, 256>>>(x, tmp, ln2_s + l*DD, ln2_b + l*DD);
    }

    int nrows = out_size / 7;
    classify_k<<<nrows, 256>>>(x, Wc, bc, lo_p, ro_p, out, nrows);
}

// round 5
// speedup vs baseline: 1.7717x; 1.0410x over previous
#include <cuda_runtime.h>
#include <cuda_bf16.h>
#include <cstdint>
#include <math.h>

#define BB 2
#define SS 4096
#define DD 768
#define HH 12
#define LL 2
#define DHH 64
#define WW 256
#define GG 64
#define FFN 3072
#define NB 16
#define SEPID 2
#define NEGV -1000000000.0f
#define BS (BB*SS)
#define QS (5*DD)          // merged qkv row stride (3840)

// weight arena offsets (bf16, transposed [N][K]); Q,K,V,KG,VG contiguous
#define WSZ_DD (DD*DD)
#define OFF_Q  0
#define OFF_K  (1*WSZ_DD)
#define OFF_V  (2*WSZ_DD)
#define OFF_KG (3*WSZ_DD)
#define OFF_VG (4*WSZ_DD)
#define OFF_QG (5*WSZ_DD)
#define OFF_O  (6*WSZ_DD)
#define OFF_F1 (7*WSZ_DD)
#define OFF_F2 (7*WSZ_DD + DD*FFN)
#define LWOFF  (7*WSZ_DD + 2*DD*FFN)

// ---------------- scratch ----------------
__device__ float g_x[BS*DD];
__device__ float g_qkv[(size_t)BS*QS];
__device__ float g_attn[BS*DD];
__device__ float g_tmp[BS*DD];
__device__ float g_xg[BB*GG*DD];
__device__ float g_qg[BB*GG*DD];
__device__ float g_og[BB*GG*DD];
__device__ float g_bcat[2*QS];
__device__ int   g_idxg[BB*GG];
__device__ unsigned char g_klo[BS];

__device__ __align__(16) __nv_bfloat16 g_whi[2*LWOFF];
__device__ __align__(16) __nv_bfloat16 g_wlo[2*LWOFF];
__device__ __align__(16) __nv_bfloat16 g_ahi[BS*FFN];     // h1 split (F1 out / F2 in)
__device__ __align__(16) __nv_bfloat16 g_alo[BS*FFN];
__device__ __align__(16) __nv_bfloat16 g_xhi[BS*DD];      // x / attn split
__device__ __align__(16) __nv_bfloat16 g_xlo[BS*DD];
__device__ __align__(16) __nv_bfloat16 g_xghi[BB*GG*DD];
__device__ __align__(16) __nv_bfloat16 g_xglo[BB*GG*DD];

// ---------------- helpers ----------------
__device__ __forceinline__ uint32_t smem_u32(const void* p) {
    uint32_t a;
    asm("{ .reg .u64 t; cvta.to.shared.u64 t, %1; cvt.u32.u64 %0, t; }" : "=r"(a) : "l"(p));
    return a;
}

__device__ __forceinline__ void cp16(uint32_t dst, const void* src) {
    asm volatile("cp.async.ca.shared.global [%0], [%1], 16;" :: "r"(dst), "l"(src));
}
#define CP_COMMIT() asm volatile("cp.async.commit_group;" ::: "memory")
#define CP_WAIT2()  asm volatile("cp.async.wait_group 2;" ::: "memory")

__device__ __forceinline__ void ldmat4(uint32_t& r0, uint32_t& r1, uint32_t& r2, uint32_t& r3,
                                       uint32_t addr) {
    asm volatile("ldmatrix.sync.aligned.m8n8.x4.shared.b16 {%0,%1,%2,%3}, [%4];"
        : "=r"(r0), "=r"(r1), "=r"(r2), "=r"(r3) : "r"(addr));
}

__device__ __forceinline__ void mma16816(float* d, const uint32_t* a, const uint32_t* b) {
    asm volatile("mma.sync.aligned.m16n8k16.row.col.f32.bf16.bf16.f32 "
        "{%0,%1,%2,%3}, {%4,%5,%6,%7}, {%8,%9}, {%0,%1,%2,%3};"
        : "+f"(d[0]), "+f"(d[1]), "+f"(d[2]), "+f"(d[3])
        : "r"(a[0]), "r"(a[1]), "r"(a[2]), "r"(a[3]), "r"(b[0]), "r"(b[1]));
}

__device__ __forceinline__ float gelu_f(float v) {
    return 0.5f*v*(1.f + tanhf(0.7978845608028654f*(v + 0.044715f*v*v*v)));
}

// ---------------- block reductions ----------------
__device__ __forceinline__ float blk_sum(float v) {
    __shared__ float sm[33];
    int lane = threadIdx.x & 31, wid = threadIdx.x >> 5;
    #pragma unroll
    for (int o = 16; o; o >>= 1) v += __shfl_xor_sync(0xffffffffu, v, o);
    if (lane == 0) sm[wid] = v;
    __syncthreads();
    if (wid == 0) {
        int nw = (blockDim.x + 31) >> 5;
        float r = (lane < nw) ? sm[lane] : 0.f;
        #pragma unroll
        for (int o = 16; o; o >>= 1) r += __shfl_xor_sync(0xffffffffu, r, o);
        if (lane == 0) sm[32] = r;
    }
    __syncthreads();
    float r = sm[32];
    __syncthreads();
    return r;
}

__device__ __forceinline__ float blk_max(float v) {
    __shared__ float sm[33];
    int lane = threadIdx.x & 31, wid = threadIdx.x >> 5;
    #pragma unroll
    for (int o = 16; o; o >>= 1) v = fmaxf(v, __shfl_xor_sync(0xffffffffu, v, o));
    if (lane == 0) sm[wid] = v;
    __syncthreads();
    if (wid == 0) {
        int nw = (blockDim.x + 31) >> 5;
        float r = (lane < nw) ? sm[lane] : -3.4e38f;
        #pragma unroll
        for (int o = 16; o; o >>= 1) r = fmaxf(r, __shfl_xor_sync(0xffffffffu, r, o));
        if (lane == 0) sm[32] = r;
    }
    __syncthreads();
    float r = sm[32];
    __syncthreads();
    return r;
}

// ---------------- prep ----------------
__global__ void prep_k(const int* __restrict__ ids, const int* __restrict__ am,
                       int* __restrict__ idxg, unsigned char* __restrict__ klo) {
    int b = blockIdx.x;
    for (int s = threadIdx.x; s < SS; s += blockDim.x) {
        bool g = (ids[b*SS+s] == SEPID) || (s == 0);
        klo[b*SS+s] = (am[b*SS+s] != 0 && !g) ? 1 : 0;
    }
    if (threadIdx.x == 0) {
        int cnt = 0;
        for (int s = 0; s < SS && cnt < GG; s++)
            if (ids[b*SS+s] == SEPID || s == 0) idxg[b*GG + cnt++] = s;
        for (; cnt < GG; cnt++) idxg[b*GG + cnt] = 0;
    }
}

// ---------------- embedding + LN (+ bf16 split out) ----------------
__global__ void embed_ln_k(const int* __restrict__ ids, const float* __restrict__ etok,
                           const float* __restrict__ epos, const float* __restrict__ lns,
                           const float* __restrict__ lnb, float* __restrict__ x,
                           __nv_bfloat16* __restrict__ xhi, __nv_bfloat16* __restrict__ xlo) {
    int row = blockIdx.x;
    int spos = row & (SS - 1);
    int id = ids[row];
    const float* te = etok + (size_t)id * DD;
    const float* pe = epos + (size_t)spos * DD;
    float v[3]; float sum = 0.f;
    #pragma unroll
    for (int i = 0; i < 3; i++) {
        int d = threadIdx.x + i*256;
        float val = te[d] + pe[d];
        v[i] = val; sum += val;
    }
    float mean = blk_sum(sum) * (1.0f/DD);
    float sq = 0.f;
    #pragma unroll
    for (int i = 0; i < 3; i++) { float c = v[i] - mean; sq += c*c; }
    float inv = rsqrtf(blk_sum(sq) * (1.0f/DD) + 1e-5f);
    #pragma unroll
    for (int i = 0; i < 3; i++) {
        int d = threadIdx.x + i*256;
        float o = (v[i] - mean)*inv*lns[d] + lnb[d];
        x[(size_t)row*DD + d] = o;
        __nv_bfloat16 h = __float2bfloat16(o);
        xhi[(size_t)row*DD + d] = h;
        xlo[(size_t)row*DD + d] = __float2bfloat16(o - __bfloat162float(h));
    }
}

// ---------------- residual add + LN (+ bf16 split out) ----------------
__global__ void add_ln_k(float* __restrict__ x, const float* __restrict__ t,
                         const float* __restrict__ lns, const float* __restrict__ lnb,
                         __nv_bfloat16* __restrict__ xhi, __nv_bfloat16* __restrict__ xlo) {
    int row = blockIdx.x;
    size_t base = (size_t)row * DD;
    float v[3]; float sum = 0.f;
    #pragma unroll
    for (int i = 0; i < 3; i++) {
        int d = threadIdx.x + i*256;
        float val = x[base+d] + t[base+d];
        v[i] = val; sum += val;
    }
    float mean = blk_sum(sum) * (1.0f/DD);
    float sq = 0.f;
    #pragma unroll
    for (int i = 0; i < 3; i++) { float c = v[i] - mean; sq += c*c; }
    float inv = rsqrtf(blk_sum(sq) * (1.0f/DD) + 1e-5f);
    #pragma unroll
    for (int i = 0; i < 3; i++) {
        int d = threadIdx.x + i*256;
        float o = (v[i] - mean)*inv*lns[d] + lnb[d];
        x[base+d] = o;
        __nv_bfloat16 h = __float2bfloat16(o);
        xhi[base+d] = h;
        xlo[base+d] = __float2bfloat16(o - __bfloat162float(h));
    }
}

// ---------------- conversions ----------------
__global__ void asplit_k(const float4* __restrict__ A, __nv_bfloat162* __restrict__ hi,
                         __nv_bfloat162* __restrict__ lo, int n4) {
    int i = blockIdx.x*256 + threadIdx.x;
    if (i >= n4) return;
    float4 v = A[i];
    __nv_bfloat16 hx = __float2bfloat16(v.x), hy = __float2bfloat16(v.y);
    __nv_bfloat16 hz = __float2bfloat16(v.z), hw = __float2bfloat16(v.w);
    hi[2*i]   = __halves2bfloat162(hx, hy);
    hi[2*i+1] = __halves2bfloat162(hz, hw);
    __nv_bfloat16 lx = __float2bfloat16(v.x - __bfloat162float(hx));
    __nv_bfloat16 ly = __float2bfloat16(v.y - __bfloat162float(hy));
    __nv_bfloat16 lz = __float2bfloat16(v.z - __bfloat162float(hz));
    __nv_bfloat16 lw = __float2bfloat16(v.w - __bfloat162float(hw));
    lo[2*i]   = __halves2bfloat162(lx, ly);
    lo[2*i+1] = __halves2bfloat162(lz, lw);
}

// weight split + transpose: W[K][N] fp32 -> hi/lo [N][K] bf16
__global__ void wsplit_t_k(const float* __restrict__ W, __nv_bfloat16* __restrict__ hi,
                           __nv_bfloat16* __restrict__ lo, int K, int N) {
    __shared__ float t[32][33];
    int n0 = blockIdx.x*32, k0 = blockIdx.y*32;
    int tx = threadIdx.x, ty = threadIdx.y;
    #pragma unroll
    for (int i = 0; i < 4; i++)
        t[ty+8*i][tx] = W[(size_t)(k0+ty+8*i)*N + n0 + tx];
    __syncthreads();
    #pragma unroll
    for (int i = 0; i < 4; i++) {
        float v = t[tx][ty+8*i];
        __nv_bfloat16 h = __float2bfloat16(v);
        size_t o = (size_t)(n0+ty+8*i)*K + k0 + tx;
        hi[o] = h;
        lo[o] = __float2bfloat16(v - __bfloat162float(h));
    }
}

__global__ void bcat_k(const float* __restrict__ b0, const float* __restrict__ b1,
                       const float* __restrict__ b2, const float* __restrict__ b3,
                       const float* __restrict__ b4, float* __restrict__ dst) {
    int i = blockIdx.x*256 + threadIdx.x;
    if (i >= QS) return;
    int seg = i / DD, off = i - seg*DD;
    const float* src = (seg == 0) ? b0 : (seg == 1) ? b1 : (seg == 2) ? b2 : (seg == 3) ? b3 : b4;
    dst[i] = src[off];
}

// ---------------- tensor-core GEMM: cp.async 4-stage, 3-pass hi/lo compensated ---
// GELU=0: C fp32 = A@B^T + bias.  GELU=1: gelu(A@B^T + bias) split to Chi/Clo bf16.
#define SPAD 40
#define STG_BYTES (128*SPAD*2)     // 10240 per matrix per stage
#define SMEM_GEMM (8*STG_BYTES)    // 81920

template<int GELU>
__global__ void __launch_bounds__(256) tgemm_k(
        const __nv_bfloat16* __restrict__ Ahi, const __nv_bfloat16* __restrict__ Alo,
        const __nv_bfloat16* __restrict__ Bhi, const __nv_bfloat16* __restrict__ Blo,
        const float* __restrict__ bias, float* __restrict__ C,
        __nv_bfloat16* __restrict__ Chi, __nv_bfloat16* __restrict__ Clo,
        int M, int N, int K) {
    extern __shared__ char smem[];
    const uint32_t sm0 = smem_u32(smem);
    const int bn = blockIdx.x << 7, bm = blockIdx.y << 7;
    const int tid = threadIdx.x, wid = tid >> 5, lane = tid & 31;
    const int wm = (wid >> 2) << 6;
    const int wn = (wid & 3) << 5;

    float acc[4][4][4];
    #pragma unroll
    for (int i = 0; i < 4; i++)
        #pragma unroll
        for (int j = 0; j < 4; j++)
            #pragma unroll
            for (int r = 0; r < 4; r++) acc[i][j][r] = 0.f;

    const int KC = K >> 5;
    const int total = 3 * KC;
    const __nv_bfloat16* Aps[3] = {Ahi, Alo, Ahi};
    const __nv_bfloat16* Bps[3] = {Bhi, Bhi, Blo};

    // cp.async mapping: 512 x 16B per matrix per chunk, 2 per thread
    const int r0 = tid >> 2, c0 = (tid & 3) << 3;       // rows 0..63
    const int r1 = r0 + 64;                              // rows 64..127
    const uint32_t dA0 = (uint32_t)((r0*SPAD + c0) << 1);
    const uint32_t dA1 = (uint32_t)((r1*SPAD + c0) << 1);

    const int lrow = lane & 15, lcol = (lane >> 4) << 3;
    const uint32_t offA = (uint32_t)(((wm + lrow) * SPAD + lcol) << 1);
    const uint32_t offB = (uint32_t)(((wn + lrow) * SPAD + lcol) << 1) + 4*STG_BYTES;

    // prologue: stage chunks 0..2
    #pragma unroll
    for (int p = 0; p < 3; p++) {
        const int pass = (p < KC) ? 0 : (p < 2*KC ? 1 : 2);
        const int kc = p - pass*KC;
        const __nv_bfloat16* Ap = Aps[pass];
        const __nv_bfloat16* Bp = Bps[pass];
        const int kb = kc << 5;
        const uint32_t sa = sm0 + p*STG_BYTES;
        const uint32_t sb = sm0 + 4*STG_BYTES + p*STG_BYTES;
        cp16(sa + dA0, Ap + (size_t)(bm + r0)*K + kb + c0);
        cp16(sa + dA1, Ap + (size_t)(bm + r1)*K + kb + c0);
        cp16(sb + dA0, Bp + (size_t)(bn + r0)*K + kb + c0);
        cp16(sb + dA1, Bp + (size_t)(bn + r1)*K + kb + c0);
        CP_COMMIT();
    }

    for (int s = 0; s < total; s++) {
        CP_WAIT2();
        __syncthreads();
        const int stg = s & 3;
        const uint32_t abase = sm0 + stg*STG_BYTES + offA;
        const uint32_t bbase = sm0 + stg*STG_BYTES + offB;
        #pragma unroll
        for (int ks = 0; ks < 2; ks++) {
            uint32_t af[4][4], bf[4][2];
            #pragma unroll
            for (int mt = 0; mt < 4; mt++)
                ldmat4(af[mt][0], af[mt][1], af[mt][2], af[mt][3],
                       abase + (uint32_t)(((mt << 4) * SPAD + (ks << 4)) << 1));
            #pragma unroll
            for (int np = 0; np < 2; np++) {
                uint32_t m0, m1, m2, m3;
                ldmat4(m0, m1, m2, m3,
                       bbase + (uint32_t)(((np << 4) * SPAD + (ks << 4)) << 1));
                bf[2*np][0] = m0; bf[2*np+1][0] = m1;
                bf[2*np][1] = m2; bf[2*np+1][1] = m3;
            }
            #pragma unroll
            for (int mt = 0; mt < 4; mt++)
                #pragma unroll
                for (int nt = 0; nt < 4; nt++)
                    mma16816(acc[mt][nt], af[mt], bf[nt]);
        }
        // issue chunk s+3 into stage (s+3)&3 (that buffer was consumed at iter s-1)
        const int p = s + 3;
        if (p < total) {
            const int pass = (p < KC) ? 0 : (p < 2*KC ? 1 : 2);
            const int kc = p - pass*KC;
            const __nv_bfloat16* Ap = Aps[pass];
            const __nv_bfloat16* Bp = Bps[pass];
            const int kb = kc << 5;
            const int st2 = p & 3;
            const uint32_t sa = sm0 + st2*STG_BYTES;
            const uint32_t sb = sm0 + 4*STG_BYTES + st2*STG_BYTES;
            cp16(sa + dA0, Ap + (size_t)(bm + r0)*K + kb + c0);
            cp16(sa + dA1, Ap + (size_t)(bm + r1)*K + kb + c0);
            cp16(sb + dA0, Bp + (size_t)(bn + r0)*K + kb + c0);
            cp16(sb + dA1, Bp + (size_t)(bn + r1)*K + kb + c0);
        }
        CP_COMMIT();
        __syncthreads();
    }

    // epilogue
    const int mrow = lane >> 2, ncol = (lane & 3) << 1;
    #pragma unroll
    for (int mt = 0; mt < 4; mt++) {
        #pragma unroll
        for (int nt = 0; nt < 4; nt++) {
            int r = bm + wm + (mt << 4) + mrow;
            int c = bn + wn + (nt << 3) + ncol;
            float b0 = bias[c], b1 = bias[c+1];
            float v0 = acc[mt][nt][0] + b0, v1 = acc[mt][nt][1] + b1;
            float v2 = acc[mt][nt][2] + b0, v3 = acc[mt][nt][3] + b1;
            if (GELU) {
                v0 = gelu_f(v0); v1 = gelu_f(v1); v2 = gelu_f(v2); v3 = gelu_f(v3);
                __nv_bfloat16 h0 = __float2bfloat16(v0), h1 = __float2bfloat16(v1);
                __nv_bfloat16 h2 = __float2bfloat16(v2), h3 = __float2bfloat16(v3);
                *(__nv_bfloat162*)&Chi[(size_t)r*N + c]     = __halves2bfloat162(h0, h1);
                *(__nv_bfloat162*)&Chi[(size_t)(r+8)*N + c] = __halves2bfloat162(h2, h3);
                *(__nv_bfloat162*)&Clo[(size_t)r*N + c]     = __halves2bfloat162(
                    __float2bfloat16(v0 - __bfloat162float(h0)),
                    __float2bfloat16(v1 - __bfloat162float(h1)));
                *(__nv_bfloat162*)&Clo[(size_t)(r+8)*N + c] = __halves2bfloat162(
                    __float2bfloat16(v2 - __bfloat162float(h2)),
                    __float2bfloat16(v3 - __bfloat162float(h3)));
            } else {
                *(float2*)&C[(size_t)r*N + c]     = make_float2(v0, v1);
                *(float2*)&C[(size_t)(r+8)*N + c] = make_float2(v2, v3);
            }
        }
    }
}

// ---------------- fused band attention (online softmax) ----------------
__global__ void band_fused_k(const float* __restrict__ qkv, const int* __restrict__ idxg,
                             const unsigned char* __restrict__ klo, float* __restrict__ out) {
    extern __shared__ float sm[];
    float* kt  = sm;            // 64 x 64
    float* vt  = sm + 4096;     // 64 x 64
    float* ssc = sm + 8192;     // 256 x 65
    int n = blockIdx.x;
    int b = blockIdx.y / HH, h = blockIdx.y % HH;
    int qr = threadIdx.x;
    int sq = n*WW + qr;
    float qv[64];
    const float4* qp = (const float4*)(qkv + (size_t)(b*SS+sq)*QS + h*DHH);
    #pragma unroll
    for (int d4 = 0; d4 < 16; d4++) {
        float4 t = qp[d4];
        qv[4*d4] = t.x; qv[4*d4+1] = t.y; qv[4*d4+2] = t.z; qv[4*d4+3] = t.w;
    }
    float acc[64];
    #pragma unroll
    for (int d = 0; d < 64; d++) acc[d] = 0.f;
    float mrow = -INFINITY, lrow = 0.f;

    for (int c = 0; c < 13; c++) {
        __syncthreads();
        for (int idx = threadIdx.x; idx < 4096; idx += 256) {
            int kk = idx >> 6, d = idx & 63;
            int j = (c << 6) + kk;
            float kval = 0.f, vval = 0.f;
            if (j < 768) {
                int kp = n*WW + j - WW;
                if (kp >= 0 && kp < SS) {
                    size_t base = (size_t)(b*SS+kp)*QS + h*DHH + d;
                    kval = qkv[base + DD];
                    vval = qkv[base + 2*DD];
                }
            } else {
                int kp = idxg[b*GG + (j - 768)];
                size_t base = (size_t)(b*SS+kp)*QS + h*DHH + d;
                kval = qkv[base + DD];
                vval = qkv[base + 2*DD];
            }
            kt[idx] = kval;
            vt[idx] = vval;
        }
        __syncthreads();
        float cmax = -INFINITY;
        for (int kk = 0; kk < 64; kk++) {
            int j = (c << 6) + kk;
            const float4* kr = (const float4*)(kt + (kk << 6));
            float s = 0.f;
            #pragma unroll
            for (int d4 = 0; d4 < 16; d4++) {
                float4 kv = kr[d4];
                s += qv[4*d4]*kv.x + qv[4*d4+1]*kv.y + qv[4*d4+2]*kv.z + qv[4*d4+3]*kv.w;
            }
            s *= 0.125f;
            if (j < 768) {
                int kp = n*WW + j - WW;
                int rel = j - WW - qr;
                bool ok = (kp >= 0) && (kp < SS) && klo[b*SS+kp] && (rel >= -WW) && (rel <= WW);
                if (!ok) s = NEGV;
            }
            ssc[qr*65 + kk] = s;
            cmax = fmaxf(cmax, s);
        }
        float mnew = fmaxf(mrow, cmax);
        float rescale = expf(mrow - mnew);
        lrow *= rescale;
        #pragma unroll
        for (int d = 0; d < 64; d++) acc[d] *= rescale;
        for (int kk = 0; kk < 64; kk++) {
            float e = expf(ssc[qr*65 + kk] - mnew);
            lrow += e;
            const float4* vr = (const float4*)(vt + (kk << 6));
            #pragma unroll
            for (int d4 = 0; d4 < 16; d4++) {
                float4 vv = vr[d4];
                acc[4*d4]   += e*vv.x; acc[4*d4+1] += e*vv.y;
                acc[4*d4+2] += e*vv.z; acc[4*d4+3] += e*vv.w;
            }
        }
        mrow = mnew;
    }
    float inv = 1.f / lrow;
    float4* op = (float4*)(out + (size_t)(b*SS+sq)*DD + h*DHH);
    #pragma unroll
    for (int d4 = 0; d4 < 16; d4++)
        op[d4] = make_float4(acc[4*d4]*inv, acc[4*d4+1]*inv, acc[4*d4+2]*inv, acc[4*d4+3]*inv);
}

// ---------------- fused global attention ----------------
__global__ void glob_fused_k(const float* __restrict__ qg, const float* __restrict__ qkv,
                             const int* __restrict__ am, float* __restrict__ og) {
    __shared__ float qv[64];
    __shared__ float sc[SS];
    __shared__ float red[4][64];
    int g = blockIdx.x;
    int b = blockIdx.y / HH, h = blockIdx.y % HH;
    int tid = threadIdx.x;
    if (tid < 64)
        qv[tid] = qg[(size_t)(b*GG+g)*DD + h*DHH + tid];
    __syncthreads();
    const float* kga = qkv + 3*DD;
    float m = -3.4e38f;
    for (int s = tid; s < SS; s += 256) {
        const float4* kr = (const float4*)(kga + (size_t)(b*SS+s)*QS + h*DHH);
        float dot = 0.f;
        #pragma unroll
        for (int d4 = 0; d4 < 16; d4++) {
            float4 kv = kr[d4];
            dot += qv[4*d4]*kv.x + qv[4*d4+1]*kv.y + qv[4*d4+2]*kv.z + qv[4*d4+3]*kv.w;
        }
        float val = (am[b*SS+s] != 0) ? dot*0.125f : NEGV;
        sc[s] = val; m = fmaxf(m, val);
    }
    m = blk_max(m);
    float sum = 0.f;
    for (int s = tid; s < SS; s += 256) {
        float e = expf(sc[s] - m); sc[s] = e; sum += e;
    }
    sum = blk_sum(sum);
    float inv = 1.f / sum;
    int grp = tid >> 6, d = tid & 63;
    const float* vga = qkv + 4*DD;
    float acc = 0.f;
    int s0 = grp << 10;
    for (int s = s0; s < s0 + 1024; s += 4) {
        acc += sc[s]   * vga[(size_t)(b*SS+s  )*QS + h*DHH + d];
        acc += sc[s+1] * vga[(size_t)(b*SS+s+1)*QS + h*DHH + d];
        acc += sc[s+2] * vga[(size_t)(b*SS+s+2)*QS + h*DHH + d];
        acc += sc[s+3] * vga[(size_t)(b*SS+s+3)*QS + h*DHH + d];
    }
    red[grp][d] = acc;
    __syncthreads();
    if (grp == 0)
        og[(size_t)(b*GG+g)*DD + h*DHH + d] =
            (red[0][d] + red[1][d] + red[2][d] + red[3][d]) * inv;
}

// ---------------- gather / scatter ----------------
__global__ void gather_k(const float* __restrict__ x, const int* __restrict__ idxg,
                         float* __restrict__ xg) {
    int r = blockIdx.x;
    int b = r / GG;
    int src = idxg[r];
    for (int d = threadIdx.x; d < DD; d += blockDim.x)
        xg[(size_t)r*DD + d] = x[((size_t)(b*SS+src))*DD + d];
}

__global__ void scatter_k(const float* __restrict__ og, const int* __restrict__ idxg,
                          float* __restrict__ out) {
    int r = blockIdx.x;
    int b = r / GG;
    int dst = idxg[r];
    for (int d = threadIdx.x; d < DD; d += blockDim.x)
        out[((size_t)(b*SS+dst))*DD + d] = og[(size_t)r*DD + d];
}

// ---------------- classifier ----------------
__global__ void classify_k(const float* __restrict__ x, const float* __restrict__ Wc,
                           const float* __restrict__ bc, const int* __restrict__ lo_p,
                           const int* __restrict__ ro_p, float* __restrict__ out, int nrows) {
    int r = blockIdx.x;
    int lo = *lo_p, ro = *ro_p;
    int per_b = 63 - lo - ro;
    if (per_b <= 0) per_b = 1;
    int b = r / per_b, t = lo + (r - b*per_b);
    const float* row = x + ((size_t)(b*SS + t))*DD;
    float p[7];
    #pragma unroll
    for (int c = 0; c < 7; c++) p[c] = 0.f;
    for (int d = threadIdx.x; d < DD; d += 256) {
        float xv = row[d];
        #pragma unroll
        for (int c = 0; c < 7; c++) p[c] += xv * Wc[d*7 + c];
    }
    #pragma unroll
    for (int c = 0; c < 7; c++) {
        float tot = blk_sum(p[c]);
        if (threadIdx.x == 0) out[r*7 + c] = tot + bc[c];
    }
}

// ---------------- launch ----------------
extern "C" void kernel_launch(void* const* d_in, const int* in_sizes, int n_in,
                              void* d_out, int out_size) {
    const float* emb_tok = (const float*)d_in[0];
    const float* emb_pos = (const float*)d_in[1];
    const float* ln_e_s  = (const float*)d_in[2];
    const float* ln_e_b  = (const float*)d_in[3];
    const float* Wq  = (const float*)d_in[4];
    const float* bq  = (const float*)d_in[5];
    const float* Wk  = (const float*)d_in[6];
    const float* bk  = (const float*)d_in[7];
    const float* Wv  = (const float*)d_in[8];
    const float* bv  = (const float*)d_in[9];
    const float* Wqg = (const float*)d_in[10];
    const float* bqg = (const float*)d_in[11];
    const float* Wkg = (const float*)d_in[12];
    const float* bkg = (const float*)d_in[13];
    const float* Wvg = (const float*)d_in[14];
    const float* bvg = (const float*)d_in[15];
    const float* Wo  = (const float*)d_in[16];
    const float* bo  = (const float*)d_in[17];
    const float* ln1_s = (const float*)d_in[18];
    const float* ln1_b = (const float*)d_in[19];
    const float* Wf1 = (const float*)d_in[20];
    const float* bf1 = (const float*)d_in[21];
    const float* Wf2 = (const float*)d_in[22];
    const float* bf2 = (const float*)d_in[23];
    const float* ln2_s = (const float*)d_in[24];
    const float* ln2_b = (const float*)d_in[25];
    const float* Wc  = (const float*)d_in[26];
    const float* bc  = (const float*)d_in[27];
    const int* input_ids = (const int*)d_in[28];
    const int* attn_mask = (const int*)d_in[29];
    const int* lo_p = (const int*)d_in[30];
    const int* ro_p = (const int*)d_in[31];
    float* out = (float*)d_out;

    float *x, *qkv, *attn, *tmp, *xg, *qg, *og, *bcat;
    int* idxg; unsigned char* klo;
    __nv_bfloat16 *whi, *wlo, *ahi, *alo, *xhi, *xlo, *xghi, *xglo;
    cudaGetSymbolAddress((void**)&x,    g_x);
    cudaGetSymbolAddress((void**)&qkv,  g_qkv);
    cudaGetSymbolAddress((void**)&attn, g_attn);
    cudaGetSymbolAddress((void**)&tmp,  g_tmp);
    cudaGetSymbolAddress((void**)&xg,   g_xg);
    cudaGetSymbolAddress((void**)&qg,   g_qg);
    cudaGetSymbolAddress((void**)&og,   g_og);
    cudaGetSymbolAddress((void**)&bcat, g_bcat);
    cudaGetSymbolAddress((void**)&idxg, g_idxg);
    cudaGetSymbolAddress((void**)&klo,  g_klo);
    cudaGetSymbolAddress((void**)&whi,  g_whi);
    cudaGetSymbolAddress((void**)&wlo,  g_wlo);
    cudaGetSymbolAddress((void**)&ahi,  g_ahi);
    cudaGetSymbolAddress((void**)&alo,  g_alo);
    cudaGetSymbolAddress((void**)&xhi,  g_xhi);
    cudaGetSymbolAddress((void**)&xlo,  g_xlo);
    cudaGetSymbolAddress((void**)&xghi, g_xghi);
    cudaGetSymbolAddress((void**)&xglo, g_xglo);

    const int SMEM_BAND = (4096 + 4096 + 256*65) * 4;
    cudaFuncSetAttribute(band_fused_k, cudaFuncAttributeMaxDynamicSharedMemorySize, SMEM_BAND);
    cudaFuncSetAttribute(tgemm_k<0>, cudaFuncAttributeMaxDynamicSharedMemorySize, SMEM_GEMM);
    cudaFuncSetAttribute(tgemm_k<1>, cudaFuncAttributeMaxDynamicSharedMemorySize, SMEM_GEMM);

    prep_k<<<BB, 256>>>(input_ids, attn_mask, idxg, klo);
    embed_ln_k<<<BS, 256>>>(input_ids, emb_tok, emb_pos, ln_e_s, ln_e_b, x, xhi, xlo);

    dim3 wb(32, 8);
    for (int l = 0; l < LL; l++) {
        size_t base = (size_t)l * LWOFF;
        wsplit_t_k<<<dim3(DD/32, DD/32), wb>>>(Wq  + (size_t)l*DD*DD, whi+base+OFF_Q,  wlo+base+OFF_Q,  DD, DD);
        wsplit_t_k<<<dim3(DD/32, DD/32), wb>>>(Wk  + (size_t)l*DD*DD, whi+base+OFF_K,  wlo+base+OFF_K,  DD, DD);
        wsplit_t_k<<<dim3(DD/32, DD/32), wb>>>(Wv  + (size_t)l*DD*DD, whi+base+OFF_V,  wlo+base+OFF_V,  DD, DD);
        wsplit_t_k<<<dim3(DD/32, DD/32), wb>>>(Wkg + (size_t)l*DD*DD, whi+base+OFF_KG, wlo+base+OFF_KG, DD, DD);
        wsplit_t_k<<<dim3(DD/32, DD/32), wb>>>(Wvg + (size_t)l*DD*DD, whi+base+OFF_VG, wlo+base+OFF_VG, DD, DD);
        wsplit_t_k<<<dim3(DD/32, DD/32), wb>>>(Wqg + (size_t)l*DD*DD, whi+base+OFF_QG, wlo+base+OFF_QG, DD, DD);
        wsplit_t_k<<<dim3(DD/32, DD/32), wb>>>(Wo  + (size_t)l*DD*DD, whi+base+OFF_O,  wlo+base+OFF_O,  DD, DD);
        wsplit_t_k<<<dim3(FFN/32, DD/32), wb>>>(Wf1 + (size_t)l*DD*FFN, whi+base+OFF_F1, wlo+base+OFF_F1, DD, FFN);
        wsplit_t_k<<<dim3(DD/32, FFN/32), wb>>>(Wf2 + (size_t)l*FFN*DD, whi+base+OFF_F2, wlo+base+OFF_F2, FFN, DD);
        bcat_k<<<(QS+255)/256, 256>>>(bq + l*DD, bk + l*DD, bv + l*DD, bkg + l*DD, bvg + l*DD,
                                      bcat + l*QS);
    }

    dim3 gTqkv(QS/128, BS/128);
    dim3 gT(DD/128, BS/128);
    dim3 gT1(FFN/128, BS/128);
    dim3 gTqg(DD/128, 1);
    dim3 gBand(NB, BB*HH);
    dim3 gGlob(GG, BB*HH);
    const int nXD4 = BS*DD/4, nXG4 = BB*GG*DD/4;

    for (int l = 0; l < LL; l++) {
        size_t base = (size_t)l * LWOFF;
        const float* bqg_l = bqg + l*DD;
        const float* bo_l  = bo  + l*DD;
        const float* bf1_l = bf1 + l*FFN; const float* bf2_l = bf2 + l*DD;

        tgemm_k<0><<<gTqkv, 256, SMEM_GEMM>>>(xhi, xlo, whi+base+OFF_Q, wlo+base+OFF_Q,
                                              bcat + l*QS, qkv, 0, 0, BS, QS, DD);

        gather_k<<<BB*GG, 256>>>(x, idxg, xg);
        asplit_k<<<(nXG4+255)/256, 256>>>((const float4*)xg, (__nv_bfloat162*)xghi, (__nv_bfloat162*)xglo, nXG4);
        tgemm_k<0><<<gTqg, 256, SMEM_GEMM>>>(xghi, xglo, whi+base+OFF_QG, wlo+base+OFF_QG,
                                             bqg_l, qg, 0, 0, BB*GG, DD, DD);

        band_fused_k<<<gBand, 256, SMEM_BAND>>>(qkv, idxg, klo, attn);

        glob_fused_k<<<gGlob, 256>>>(qg, qkv, attn_mask, og);
        scatter_k<<<BB*GG, 256>>>(og, idxg, attn);

        asplit_k<<<(nXD4+255)/256, 256>>>((const float4*)attn, (__nv_bfloat162*)xhi, (__nv_bfloat162*)xlo, nXD4);
        tgemm_k<0><<<gT, 256, SMEM_GEMM>>>(xhi, xlo, whi+base+OFF_O, wlo+base+OFF_O,
                                           bo_l, tmp, 0, 0, BS, DD, DD);
        add_ln_k<<<BS, 256>>>(x, tmp, ln1_s + l*DD, ln1_b + l*DD, xhi, xlo);

        tgemm_k<1><<<gT1, 256, SMEM_GEMM>>>(xhi, xlo, whi+base+OFF_F1, wlo+base+OFF_F1,
                                            bf1_l, 0, ahi, alo, BS, FFN, DD);
        tgemm_k<0><<<gT, 256, SMEM_GEMM>>>(ahi, alo, whi+base+OFF_F2, wlo+base+OFF_F2,
                                           bf2_l, tmp, 0, 0, BS, DD, FFN);
        add_ln_k<<<BS, 256>>>(x, tmp, ln2_s + l*DD, ln2_b + l*DD, xhi, xlo);
    }

    int nrows = out_size / 7;
    classify_k<<<nrows, 256>>>(x, Wc, bc, lo_p, ro_p, out, nrows);
}

// round 6
// speedup vs baseline: 2.2256x; 1.2562x over previous
#include <cuda_runtime.h>
#include <cuda_fp16.h>
#include <cstdint>
#include <math.h>

#define BB 2
#define SS 4096
#define DD 768
#define HH 12
#define LL 2
#define DHH 64
#define WW 256
#define GG 64
#define FFN 3072
#define NB 16
#define SEPID 2
#define NEGV -1000000000.0f
#define BS (BB*SS)
#define QS (5*DD)

// weight arena offsets (fp16, transposed [N][K]); Q,K,V,KG,VG contiguous
#define WSZ_DD (DD*DD)
#define OFF_Q  0
#define OFF_K  (1*WSZ_DD)
#define OFF_V  (2*WSZ_DD)
#define OFF_KG (3*WSZ_DD)
#define OFF_VG (4*WSZ_DD)
#define OFF_QG (5*WSZ_DD)
#define OFF_O  (6*WSZ_DD)
#define OFF_F1 (7*WSZ_DD)
#define OFF_F2 (7*WSZ_DD + DD*FFN)
#define LWOFF  (7*WSZ_DD + 2*DD*FFN)

// ---------------- scratch ----------------
__device__ float g_x[BS*DD];
__device__ float g_qkv[(size_t)BS*QS];
__device__ float g_attn[BS*DD];
__device__ float g_tmp[BS*DD];
__device__ float g_xg[BB*GG*DD];
__device__ float g_qg[BB*GG*DD];
__device__ float g_og[BB*GG*DD];
__device__ float g_bcat[2*QS];
__device__ int   g_idxg[BB*GG];
__device__ unsigned char g_klo[BS];

__device__ __align__(16) __half g_w[2*LWOFF];          // fp16 weights (hi only)
__device__ __align__(16) __half g_ahi[BS*FFN];         // h1 split (F1 out / F2 in)
__device__ __align__(16) __half g_alo[BS*FFN];
__device__ __align__(16) __half g_xhi[BS*DD];          // x / attn split
__device__ __align__(16) __half g_xlo[BS*DD];
__device__ __align__(16) __half g_xghi[BB*GG*DD];
__device__ __align__(16) __half g_xglo[BB*GG*DD];

// ---------------- helpers ----------------
__device__ __forceinline__ uint32_t smem_u32(const void* p) {
    uint32_t a;
    asm("{ .reg .u64 t; cvta.to.shared.u64 t, %1; cvt.u32.u64 %0, t; }" : "=r"(a) : "l"(p));
    return a;
}

__device__ __forceinline__ void cp16(uint32_t dst, const void* src) {
    asm volatile("cp.async.ca.shared.global [%0], [%1], 16;" :: "r"(dst), "l"(src));
}
#define CP_COMMIT() asm volatile("cp.async.commit_group;" ::: "memory")
#define CP_WAIT2()  asm volatile("cp.async.wait_group 2;" ::: "memory")

__device__ __forceinline__ void ldmat4(uint32_t& r0, uint32_t& r1, uint32_t& r2, uint32_t& r3,
                                       uint32_t addr) {
    asm volatile("ldmatrix.sync.aligned.m8n8.x4.shared.b16 {%0,%1,%2,%3}, [%4];"
        : "=r"(r0), "=r"(r1), "=r"(r2), "=r"(r3) : "r"(addr));
}

__device__ __forceinline__ void mma16816(float* d, const uint32_t* a, const uint32_t* b) {
    asm volatile("mma.sync.aligned.m16n8k16.row.col.f32.f16.f16.f32 "
        "{%0,%1,%2,%3}, {%4,%5,%6,%7}, {%8,%9}, {%0,%1,%2,%3};"
        : "+f"(d[0]), "+f"(d[1]), "+f"(d[2]), "+f"(d[3])
        : "r"(a[0]), "r"(a[1]), "r"(a[2]), "r"(a[3]), "r"(b[0]), "r"(b[1]));
}

__device__ __forceinline__ float gelu_f(float v) {
    return 0.5f*v*(1.f + tanhf(0.7978845608028654f*(v + 0.044715f*v*v*v)));
}

// ---------------- block reductions ----------------
__device__ __forceinline__ float blk_sum(float v) {
    __shared__ float sm[33];
    int lane = threadIdx.x & 31, wid = threadIdx.x >> 5;
    #pragma unroll
    for (int o = 16; o; o >>= 1) v += __shfl_xor_sync(0xffffffffu, v, o);
    if (lane == 0) sm[wid] = v;
    __syncthreads();
    if (wid == 0) {
        int nw = (blockDim.x + 31) >> 5;
        float r = (lane < nw) ? sm[lane] : 0.f;
        #pragma unroll
        for (int o = 16; o; o >>= 1) r += __shfl_xor_sync(0xffffffffu, r, o);
        if (lane == 0) sm[32] = r;
    }
    __syncthreads();
    float r = sm[32];
    __syncthreads();
    return r;
}

__device__ __forceinline__ float blk_max(float v) {
    __shared__ float sm[33];
    int lane = threadIdx.x & 31, wid = threadIdx.x >> 5;
    #pragma unroll
    for (int o = 16; o; o >>= 1) v = fmaxf(v, __shfl_xor_sync(0xffffffffu, v, o));
    if (lane == 0) sm[wid] = v;
    __syncthreads();
    if (wid == 0) {
        int nw = (blockDim.x + 31) >> 5;
        float r = (lane < nw) ? sm[lane] : -3.4e38f;
        #pragma unroll
        for (int o = 16; o; o >>= 1) r = fmaxf(r, __shfl_xor_sync(0xffffffffu, r, o));
        if (lane == 0) sm[32] = r;
    }
    __syncthreads();
    float r = sm[32];
    __syncthreads();
    return r;
}

// ---------------- prep ----------------
__global__ void prep_k(const int* __restrict__ ids, const int* __restrict__ am,
                       int* __restrict__ idxg, unsigned char* __restrict__ klo) {
    int b = blockIdx.x;
    for (int s = threadIdx.x; s < SS; s += blockDim.x) {
        bool g = (ids[b*SS+s] == SEPID) || (s == 0);
        klo[b*SS+s] = (am[b*SS+s] != 0 && !g) ? 1 : 0;
    }
    if (threadIdx.x == 0) {
        int cnt = 0;
        for (int s = 0; s < SS && cnt < GG; s++)
            if (ids[b*SS+s] == SEPID || s == 0) idxg[b*GG + cnt++] = s;
        for (; cnt < GG; cnt++) idxg[b*GG + cnt] = 0;
    }
}

// ---------------- embedding + LN (+ fp16 split out) ----------------
__global__ void embed_ln_k(const int* __restrict__ ids, const float* __restrict__ etok,
                           const float* __restrict__ epos, const float* __restrict__ lns,
                           const float* __restrict__ lnb, float* __restrict__ x,
                           __half* __restrict__ xhi, __half* __restrict__ xlo) {
    int row = blockIdx.x;
    int spos = row & (SS - 1);
    int id = ids[row];
    const float* te = etok + (size_t)id * DD;
    const float* pe = epos + (size_t)spos * DD;
    float v[3]; float sum = 0.f;
    #pragma unroll
    for (int i = 0; i < 3; i++) {
        int d = threadIdx.x + i*256;
        float val = te[d] + pe[d];
        v[i] = val; sum += val;
    }
    float mean = blk_sum(sum) * (1.0f/DD);
    float sq = 0.f;
    #pragma unroll
    for (int i = 0; i < 3; i++) { float c = v[i] - mean; sq += c*c; }
    float inv = rsqrtf(blk_sum(sq) * (1.0f/DD) + 1e-5f);
    #pragma unroll
    for (int i = 0; i < 3; i++) {
        int d = threadIdx.x + i*256;
        float o = (v[i] - mean)*inv*lns[d] + lnb[d];
        x[(size_t)row*DD + d] = o;
        __half h = __float2half(o);
        xhi[(size_t)row*DD + d] = h;
        xlo[(size_t)row*DD + d] = __float2half(o - __half2float(h));
    }
}

// ---------------- residual add + LN (+ fp16 split out) ----------------
__global__ void add_ln_k(float* __restrict__ x, const float* __restrict__ t,
                         const float* __restrict__ lns, const float* __restrict__ lnb,
                         __half* __restrict__ xhi, __half* __restrict__ xlo) {
    int row = blockIdx.x;
    size_t base = (size_t)row * DD;
    float v[3]; float sum = 0.f;
    #pragma unroll
    for (int i = 0; i < 3; i++) {
        int d = threadIdx.x + i*256;
        float val = x[base+d] + t[base+d];
        v[i] = val; sum += val;
    }
    float mean = blk_sum(sum) * (1.0f/DD);
    float sq = 0.f;
    #pragma unroll
    for (int i = 0; i < 3; i++) { float c = v[i] - mean; sq += c*c; }
    float inv = rsqrtf(blk_sum(sq) * (1.0f/DD) + 1e-5f);
    #pragma unroll
    for (int i = 0; i < 3; i++) {
        int d = threadIdx.x + i*256;
        float o = (v[i] - mean)*inv*lns[d] + lnb[d];
        x[base+d] = o;
        __half h = __float2half(o);
        xhi[base+d] = h;
        xlo[base+d] = __float2half(o - __half2float(h));
    }
}

// ---------------- conversions ----------------
__global__ void asplit_k(const float4* __restrict__ A, __half2* __restrict__ hi,
                         __half2* __restrict__ lo, int n4) {
    int i = blockIdx.x*256 + threadIdx.x;
    if (i >= n4) return;
    float4 v = A[i];
    __half hx = __float2half(v.x), hy = __float2half(v.y);
    __half hz = __float2half(v.z), hw = __float2half(v.w);
    hi[2*i]   = __halves2half2(hx, hy);
    hi[2*i+1] = __halves2half2(hz, hw);
    lo[2*i]   = __halves2half2(__float2half(v.x - __half2float(hx)),
                               __float2half(v.y - __half2float(hy)));
    lo[2*i+1] = __halves2half2(__float2half(v.z - __half2float(hz)),
                               __float2half(v.w - __half2float(hw)));
}

// weight convert + transpose: W[K][N] fp32 -> fp16 [N][K]
__global__ void wsplit_t_k(const float* __restrict__ W, __half* __restrict__ hi,
                           int K, int N) {
    __shared__ float t[32][33];
    int n0 = blockIdx.x*32, k0 = blockIdx.y*32;
    int tx = threadIdx.x, ty = threadIdx.y;
    #pragma unroll
    for (int i = 0; i < 4; i++)
        t[ty+8*i][tx] = W[(size_t)(k0+ty+8*i)*N + n0 + tx];
    __syncthreads();
    #pragma unroll
    for (int i = 0; i < 4; i++) {
        float v = t[tx][ty+8*i];
        hi[(size_t)(n0+ty+8*i)*K + k0 + tx] = __float2half(v);
    }
}

__global__ void bcat_k(const float* __restrict__ b0, const float* __restrict__ b1,
                       const float* __restrict__ b2, const float* __restrict__ b3,
                       const float* __restrict__ b4, float* __restrict__ dst) {
    int i = blockIdx.x*256 + threadIdx.x;
    if (i >= QS) return;
    int seg = i / DD, off = i - seg*DD;
    const float* src = (seg == 0) ? b0 : (seg == 1) ? b1 : (seg == 2) ? b2 : (seg == 3) ? b3 : b4;
    dst[i] = src[off];
}

// ---------------- tensor-core GEMM: cp.async 4-stage, fp16 2-pass compensated ----
// C = (Ahi + Alo) @ B^T + bias (B fp16, correction on A side only)
#define SPAD 40
#define STG_BYTES (128*SPAD*2)
#define SMEM_GEMM (8*STG_BYTES)

template<int GELU>
__global__ void __launch_bounds__(256) tgemm_k(
        const __half* __restrict__ Ahi, const __half* __restrict__ Alo,
        const __half* __restrict__ B,
        const float* __restrict__ bias, float* __restrict__ C,
        __half* __restrict__ Chi, __half* __restrict__ Clo,
        int M, int N, int K) {
    extern __shared__ char smem[];
    const uint32_t sm0 = smem_u32(smem);
    const int bn = blockIdx.x << 7, bm = blockIdx.y << 7;
    const int tid = threadIdx.x, wid = tid >> 5, lane = tid & 31;
    const int wm = (wid >> 2) << 6;
    const int wn = (wid & 3) << 5;

    float acc[4][4][4];
    #pragma unroll
    for (int i = 0; i < 4; i++)
        #pragma unroll
        for (int j = 0; j < 4; j++)
            #pragma unroll
            for (int r = 0; r < 4; r++) acc[i][j][r] = 0.f;

    const int KC = K >> 5;
    const int total = 2 * KC;
    const __half* Aps[2] = {Ahi, Alo};

    const int r0 = tid >> 2, c0 = (tid & 3) << 3;
    const int r1 = r0 + 64;
    const uint32_t dA0 = (uint32_t)((r0*SPAD + c0) << 1);
    const uint32_t dA1 = (uint32_t)((r1*SPAD + c0) << 1);

    const int lrow = lane & 15, lcol = (lane >> 4) << 3;
    const uint32_t offA = (uint32_t)(((wm + lrow) * SPAD + lcol) << 1);
    const uint32_t offB = (uint32_t)(((wn + lrow) * SPAD + lcol) << 1) + 4*STG_BYTES;

    #pragma unroll
    for (int p = 0; p < 3; p++) {
        const int pass = (p < KC) ? 0 : 1;
        const int kc = p - pass*KC;
        const __half* Ap = Aps[pass];
        const int kb = kc << 5;
        const uint32_t sa = sm0 + p*STG_BYTES;
        const uint32_t sb = sm0 + 4*STG_BYTES + p*STG_BYTES;
        cp16(sa + dA0, Ap + (size_t)(bm + r0)*K + kb + c0);
        cp16(sa + dA1, Ap + (size_t)(bm + r1)*K + kb + c0);
        cp16(sb + dA0, B + (size_t)(bn + r0)*K + kb + c0);
        cp16(sb + dA1, B + (size_t)(bn + r1)*K + kb + c0);
        CP_COMMIT();
    }

    for (int s = 0; s < total; s++) {
        CP_WAIT2();
        __syncthreads();
        const int stg = s & 3;
        const uint32_t abase = sm0 + stg*STG_BYTES + offA;
        const uint32_t bbase = sm0 + stg*STG_BYTES + offB;
        #pragma unroll
        for (int ks = 0; ks < 2; ks++) {
            uint32_t af[4][4], bf[4][2];
            #pragma unroll
            for (int mt = 0; mt < 4; mt++)
                ldmat4(af[mt][0], af[mt][1], af[mt][2], af[mt][3],
                       abase + (uint32_t)(((mt << 4) * SPAD + (ks << 4)) << 1));
            #pragma unroll
            for (int np = 0; np < 2; np++) {
                uint32_t m0, m1, m2, m3;
                ldmat4(m0, m1, m2, m3,
                       bbase + (uint32_t)(((np << 4) * SPAD + (ks << 4)) << 1));
                bf[2*np][0] = m0; bf[2*np+1][0] = m1;
                bf[2*np][1] = m2; bf[2*np+1][1] = m3;
            }
            #pragma unroll
            for (int mt = 0; mt < 4; mt++)
                #pragma unroll
                for (int nt = 0; nt < 4; nt++)
                    mma16816(acc[mt][nt], af[mt], bf[nt]);
        }
        const int p = s + 3;
        if (p < total) {
            const int pass = (p < KC) ? 0 : 1;
            const int kc = p - pass*KC;
            const __half* Ap = Aps[pass];
            const int kb = kc << 5;
            const int st2 = p & 3;
            const uint32_t sa = sm0 + st2*STG_BYTES;
            const uint32_t sb = sm0 + 4*STG_BYTES + st2*STG_BYTES;
            cp16(sa + dA0, Ap + (size_t)(bm + r0)*K + kb + c0);
            cp16(sa + dA1, Ap + (size_t)(bm + r1)*K + kb + c0);
            cp16(sb + dA0, B + (size_t)(bn + r0)*K + kb + c0);
            cp16(sb + dA1, B + (size_t)(bn + r1)*K + kb + c0);
        }
        CP_COMMIT();
        __syncthreads();
    }

    const int mrow = lane >> 2, ncol = (lane & 3) << 1;
    #pragma unroll
    for (int mt = 0; mt < 4; mt++) {
        #pragma unroll
        for (int nt = 0; nt < 4; nt++) {
            int r = bm + wm + (mt << 4) + mrow;
            int c = bn + wn + (nt << 3) + ncol;
            float b0 = bias[c], b1 = bias[c+1];
            float v0 = acc[mt][nt][0] + b0, v1 = acc[mt][nt][1] + b1;
            float v2 = acc[mt][nt][2] + b0, v3 = acc[mt][nt][3] + b1;
            if (GELU) {
                v0 = gelu_f(v0); v1 = gelu_f(v1); v2 = gelu_f(v2); v3 = gelu_f(v3);
                __half h0 = __float2half(v0), h1 = __float2half(v1);
                __half h2 = __float2half(v2), h3 = __float2half(v3);
                *(__half2*)&Chi[(size_t)r*N + c]     = __halves2half2(h0, h1);
                *(__half2*)&Chi[(size_t)(r+8)*N + c] = __halves2half2(h2, h3);
                *(__half2*)&Clo[(size_t)r*N + c]     = __halves2half2(
                    __float2half(v0 - __half2float(h0)), __float2half(v1 - __half2float(h1)));
                *(__half2*)&Clo[(size_t)(r+8)*N + c] = __halves2half2(
                    __float2half(v2 - __half2float(h2)), __float2half(v3 - __half2float(h3)));
            } else {
                *(float2*)&C[(size_t)r*N + c]     = make_float2(v0, v1);
                *(float2*)&C[(size_t)(r+8)*N + c] = make_float2(v2, v3);
            }
        }
    }
}

// ---------------- fused band attention (online softmax) ----------------
__global__ void band_fused_k(const float* __restrict__ qkv, const int* __restrict__ idxg,
                             const unsigned char* __restrict__ klo, float* __restrict__ out) {
    extern __shared__ float sm[];
    float* kt  = sm;
    float* vt  = sm + 4096;
    float* ssc = sm + 8192;
    int n = blockIdx.x;
    int b = blockIdx.y / HH, h = blockIdx.y % HH;
    int qr = threadIdx.x;
    int sq = n*WW + qr;
    float qv[64];
    const float4* qp = (const float4*)(qkv + (size_t)(b*SS+sq)*QS + h*DHH);
    #pragma unroll
    for (int d4 = 0; d4 < 16; d4++) {
        float4 t = qp[d4];
        qv[4*d4] = t.x; qv[4*d4+1] = t.y; qv[4*d4+2] = t.z; qv[4*d4+3] = t.w;
    }
    float acc[64];
    #pragma unroll
    for (int d = 0; d < 64; d++) acc[d] = 0.f;
    float mrow = -INFINITY, lrow = 0.f;

    for (int c = 0; c < 13; c++) {
        __syncthreads();
        for (int idx = threadIdx.x; idx < 4096; idx += 256) {
            int kk = idx >> 6, d = idx & 63;
            int j = (c << 6) + kk;
            float kval = 0.f, vval = 0.f;
            if (j < 768) {
                int kp = n*WW + j - WW;
                if (kp >= 0 && kp < SS) {
                    size_t base = (size_t)(b*SS+kp)*QS + h*DHH + d;
                    kval = qkv[base + DD];
                    vval = qkv[base + 2*DD];
                }
            } else {
                int kp = idxg[b*GG + (j - 768)];
                size_t base = (size_t)(b*SS+kp)*QS + h*DHH + d;
                kval = qkv[base + DD];
                vval = qkv[base + 2*DD];
            }
            kt[idx] = kval;
            vt[idx] = vval;
        }
        __syncthreads();
        float cmax = -INFINITY;
        for (int kk = 0; kk < 64; kk++) {
            int j = (c << 6) + kk;
            const float4* kr = (const float4*)(kt + (kk << 6));
            float s = 0.f;
            #pragma unroll
            for (int d4 = 0; d4 < 16; d4++) {
                float4 kv = kr[d4];
                s += qv[4*d4]*kv.x + qv[4*d4+1]*kv.y + qv[4*d4+2]*kv.z + qv[4*d4+3]*kv.w;
            }
            s *= 0.125f;
            if (j < 768) {
                int kp = n*WW + j - WW;
                int rel = j - WW - qr;
                bool ok = (kp >= 0) && (kp < SS) && klo[b*SS+kp] && (rel >= -WW) && (rel <= WW);
                if (!ok) s = NEGV;
            }
            ssc[qr*65 + kk] = s;
            cmax = fmaxf(cmax, s);
        }
        float mnew = fmaxf(mrow, cmax);
        float rescale = expf(mrow - mnew);
        lrow *= rescale;
        #pragma unroll
        for (int d = 0; d < 64; d++) acc[d] *= rescale;
        for (int kk = 0; kk < 64; kk++) {
            float e = expf(ssc[qr*65 + kk] - mnew);
            lrow += e;
            const float4* vr = (const float4*)(vt + (kk << 6));
            #pragma unroll
            for (int d4 = 0; d4 < 16; d4++) {
                float4 vv = vr[d4];
                acc[4*d4]   += e*vv.x; acc[4*d4+1] += e*vv.y;
                acc[4*d4+2] += e*vv.z; acc[4*d4+3] += e*vv.w;
            }
        }
        mrow = mnew;
    }
    float inv = 1.f / lrow;
    float4* op = (float4*)(out + (size_t)(b*SS+sq)*DD + h*DHH);
    #pragma unroll
    for (int d4 = 0; d4 < 16; d4++)
        op[d4] = make_float4(acc[4*d4]*inv, acc[4*d4+1]*inv, acc[4*d4+2]*inv, acc[4*d4+3]*inv);
}

// ---------------- fused global attention ----------------
__global__ void glob_fused_k(const float* __restrict__ qg, const float* __restrict__ qkv,
                             const int* __restrict__ am, float* __restrict__ og) {
    __shared__ float qv[64];
    __shared__ float sc[SS];
    __shared__ float red[4][64];
    int g = blockIdx.x;
    int b = blockIdx.y / HH, h = blockIdx.y % HH;
    int tid = threadIdx.x;
    if (tid < 64)
        qv[tid] = qg[(size_t)(b*GG+g)*DD + h*DHH + tid];
    __syncthreads();
    const float* kga = qkv + 3*DD;
    float m = -3.4e38f;
    for (int s = tid; s < SS; s += 256) {
        const float4* kr = (const float4*)(kga + (size_t)(b*SS+s)*QS + h*DHH);
        float dot = 0.f;
        #pragma unroll
        for (int d4 = 0; d4 < 16; d4++) {
            float4 kv = kr[d4];
            dot += qv[4*d4]*kv.x + qv[4*d4+1]*kv.y + qv[4*d4+2]*kv.z + qv[4*d4+3]*kv.w;
        }
        float val = (am[b*SS+s] != 0) ? dot*0.125f : NEGV;
        sc[s] = val; m = fmaxf(m, val);
    }
    m = blk_max(m);
    float sum = 0.f;
    for (int s = tid; s < SS; s += 256) {
        float e = expf(sc[s] - m); sc[s] = e; sum += e;
    }
    sum = blk_sum(sum);
    float inv = 1.f / sum;
    int grp = tid >> 6, d = tid & 63;
    const float* vga = qkv + 4*DD;
    float acc = 0.f;
    int s0 = grp << 10;
    for (int s = s0; s < s0 + 1024; s += 4) {
        acc += sc[s]   * vga[(size_t)(b*SS+s  )*QS + h*DHH + d];
        acc += sc[s+1] * vga[(size_t)(b*SS+s+1)*QS + h*DHH + d];
        acc += sc[s+2] * vga[(size_t)(b*SS+s+2)*QS + h*DHH + d];
        acc += sc[s+3] * vga[(size_t)(b*SS+s+3)*QS + h*DHH + d];
    }
    red[grp][d] = acc;
    __syncthreads();
    if (grp == 0)
        og[(size_t)(b*GG+g)*DD + h*DHH + d] =
            (red[0][d] + red[1][d] + red[2][d] + red[3][d]) * inv;
}

// ---------------- gather / scatter ----------------
__global__ void gather_k(const float* __restrict__ x, const int* __restrict__ idxg,
                         float* __restrict__ xg) {
    int r = blockIdx.x;
    int b = r / GG;
    int src = idxg[r];
    for (int d = threadIdx.x; d < DD; d += blockDim.x)
        xg[(size_t)r*DD + d] = x[((size_t)(b*SS+src))*DD + d];
}

__global__ void scatter_k(const float* __restrict__ og, const int* __restrict__ idxg,
                          float* __restrict__ out) {
    int r = blockIdx.x;
    int b = r / GG;
    int dst = idxg[r];
    for (int d = threadIdx.x; d < DD; d += blockDim.x)
        out[((size_t)(b*SS+dst))*DD + d] = og[(size_t)r*DD + d];
}

// ---------------- classifier ----------------
__global__ void classify_k(const float* __restrict__ x, const float* __restrict__ Wc,
                           const float* __restrict__ bc, const int* __restrict__ lo_p,
                           const int* __restrict__ ro_p, float* __restrict__ out, int nrows) {
    int r = blockIdx.x;
    int lo = *lo_p, ro = *ro_p;
    int per_b = 63 - lo - ro;
    if (per_b <= 0) per_b = 1;
    int b = r / per_b, t = lo + (r - b*per_b);
    const float* row = x + ((size_t)(b*SS + t))*DD;
    float p[7];
    #pragma unroll
    for (int c = 0; c < 7; c++) p[c] = 0.f;
    for (int d = threadIdx.x; d < DD; d += 256) {
        float xv = row[d];
        #pragma unroll
        for (int c = 0; c < 7; c++) p[c] += xv * Wc[d*7 + c];
    }
    #pragma unroll
    for (int c = 0; c < 7; c++) {
        float tot = blk_sum(p[c]);
        if (threadIdx.x == 0) out[r*7 + c] = tot + bc[c];
    }
}

// ---------------- launch ----------------
extern "C" void kernel_launch(void* const* d_in, const int* in_sizes, int n_in,
                              void* d_out, int out_size) {
    const float* emb_tok = (const float*)d_in[0];
    const float* emb_pos = (const float*)d_in[1];
    const float* ln_e_s  = (const float*)d_in[2];
    const float* ln_e_b  = (const float*)d_in[3];
    const float* Wq  = (const float*)d_in[4];
    const float* bq  = (const float*)d_in[5];
    const float* Wk  = (const float*)d_in[6];
    const float* bk  = (const float*)d_in[7];
    const float* Wv  = (const float*)d_in[8];
    const float* bv  = (const float*)d_in[9];
    const float* Wqg = (const float*)d_in[10];
    const float* bqg = (const float*)d_in[11];
    const float* Wkg = (const float*)d_in[12];
    const float* bkg = (const float*)d_in[13];
    const float* Wvg = (const float*)d_in[14];
    const float* bvg = (const float*)d_in[15];
    const float* Wo  = (const float*)d_in[16];
    const float* bo  = (const float*)d_in[17];
    const float* ln1_s = (const float*)d_in[18];
    const float* ln1_b = (const float*)d_in[19];
    const float* Wf1 = (const float*)d_in[20];
    const float* bf1 = (const float*)d_in[21];
    const float* Wf2 = (const float*)d_in[22];
    const float* bf2 = (const float*)d_in[23];
    const float* ln2_s = (const float*)d_in[24];
    const float* ln2_b = (const float*)d_in[25];
    const float* Wc  = (const float*)d_in[26];
    const float* bc  = (const float*)d_in[27];
    const int* input_ids = (const int*)d_in[28];
    const int* attn_mask = (const int*)d_in[29];
    const int* lo_p = (const int*)d_in[30];
    const int* ro_p = (const int*)d_in[31];
    float* out = (float*)d_out;

    float *x, *qkv, *attn, *tmp, *xg, *qg, *og, *bcat;
    int* idxg; unsigned char* klo;
    __half *w, *ahi, *alo, *xhi, *xlo, *xghi, *xglo;
    cudaGetSymbolAddress((void**)&x,    g_x);
    cudaGetSymbolAddress((void**)&qkv,  g_qkv);
    cudaGetSymbolAddress((void**)&attn, g_attn);
    cudaGetSymbolAddress((void**)&tmp,  g_tmp);
    cudaGetSymbolAddress((void**)&xg,   g_xg);
    cudaGetSymbolAddress((void**)&qg,   g_qg);
    cudaGetSymbolAddress((void**)&og,   g_og);
    cudaGetSymbolAddress((void**)&bcat, g_bcat);
    cudaGetSymbolAddress((void**)&idxg, g_idxg);
    cudaGetSymbolAddress((void**)&klo,  g_klo);
    cudaGetSymbolAddress((void**)&w,    g_w);
    cudaGetSymbolAddress((void**)&ahi,  g_ahi);
    cudaGetSymbolAddress((void**)&alo,  g_alo);
    cudaGetSymbolAddress((void**)&xhi,  g_xhi);
    cudaGetSymbolAddress((void**)&xlo,  g_xlo);
    cudaGetSymbolAddress((void**)&xghi, g_xghi);
    cudaGetSymbolAddress((void**)&xglo, g_xglo);

    const int SMEM_BAND = (4096 + 4096 + 256*65) * 4;
    cudaFuncSetAttribute(band_fused_k, cudaFuncAttributeMaxDynamicSharedMemorySize, SMEM_BAND);
    cudaFuncSetAttribute(tgemm_k<0>, cudaFuncAttributeMaxDynamicSharedMemorySize, SMEM_GEMM);
    cudaFuncSetAttribute(tgemm_k<1>, cudaFuncAttributeMaxDynamicSharedMemorySize, SMEM_GEMM);

    prep_k<<<BB, 256>>>(input_ids, attn_mask, idxg, klo);
    embed_ln_k<<<BS, 256>>>(input_ids, emb_tok, emb_pos, ln_e_s, ln_e_b, x, xhi, xlo);

    dim3 wb(32, 8);
    for (int l = 0; l < LL; l++) {
        size_t base = (size_t)l * LWOFF;
        wsplit_t_k<<<dim3(DD/32, DD/32), wb>>>(Wq  + (size_t)l*DD*DD, w+base+OFF_Q,  DD, DD);
        wsplit_t_k<<<dim3(DD/32, DD/32), wb>>>(Wk  + (size_t)l*DD*DD, w+base+OFF_K,  DD, DD);
        wsplit_t_k<<<dim3(DD/32, DD/32), wb>>>(Wv  + (size_t)l*DD*DD, w+base+OFF_V,  DD, DD);
        wsplit_t_k<<<dim3(DD/32, DD/32), wb>>>(Wkg + (size_t)l*DD*DD, w+base+OFF_KG, DD, DD);
        wsplit_t_k<<<dim3(DD/32, DD/32), wb>>>(Wvg + (size_t)l*DD*DD, w+base+OFF_VG, DD, DD);
        wsplit_t_k<<<dim3(DD/32, DD/32), wb>>>(Wqg + (size_t)l*DD*DD, w+base+OFF_QG, DD, DD);
        wsplit_t_k<<<dim3(DD/32, DD/32), wb>>>(Wo  + (size_t)l*DD*DD, w+base+OFF_O,  DD, DD);
        wsplit_t_k<<<dim3(FFN/32, DD/32), wb>>>(Wf1 + (size_t)l*DD*FFN, w+base+OFF_F1, DD, FFN);
        wsplit_t_k<<<dim3(DD/32, FFN/32), wb>>>(Wf2 + (size_t)l*FFN*DD, w+base+OFF_F2, FFN, DD);
        bcat_k<<<(QS+255)/256, 256>>>(bq + l*DD, bk + l*DD, bv + l*DD, bkg + l*DD, bvg + l*DD,
                                      bcat + l*QS);
    }

    dim3 gTqkv(QS/128, BS/128);
    dim3 gT(DD/128, BS/128);
    dim3 gT1(FFN/128, BS/128);
    dim3 gTqg(DD/128, 1);
    dim3 gBand(NB, BB*HH);
    dim3 gGlob(GG, BB*HH);
    const int nXD4 = BS*DD/4, nXG4 = BB*GG*DD/4;

    for (int l = 0; l < LL; l++) {
        size_t base = (size_t)l * LWOFF;
        const float* bqg_l = bqg + l*DD;
        const float* bo_l  = bo  + l*DD;
        const float* bf1_l = bf1 + l*FFN; const float* bf2_l = bf2 + l*DD;

        tgemm_k<0><<<gTqkv, 256, SMEM_GEMM>>>(xhi, xlo, w+base+OFF_Q,
                                              bcat + l*QS, qkv, 0, 0, BS, QS, DD);

        gather_k<<<BB*GG, 256>>>(x, idxg, xg);
        asplit_k<<<(nXG4+255)/256, 256>>>((const float4*)xg, (__half2*)xghi, (__half2*)xglo, nXG4);
        tgemm_k<0><<<gTqg, 256, SMEM_GEMM>>>(xghi, xglo, w+base+OFF_QG,
                                             bqg_l, qg, 0, 0, BB*GG, DD, DD);

        band_fused_k<<<gBand, 256, SMEM_BAND>>>(qkv, idxg, klo, attn);

        glob_fused_k<<<gGlob, 256>>>(qg, qkv, attn_mask, og);
        scatter_k<<<BB*GG, 256>>>(og, idxg, attn);

        asplit_k<<<(nXD4+255)/256, 256>>>((const float4*)attn, (__half2*)xhi, (__half2*)xlo, nXD4);
        tgemm_k<0><<<gT, 256, SMEM_GEMM>>>(xhi, xlo, w+base+OFF_O,
                                           bo_l, tmp, 0, 0, BS, DD, DD);
        add_ln_k<<<BS, 256>>>(x, tmp, ln1_s + l*DD, ln1_b + l*DD, xhi, xlo);

        tgemm_k<1><<<gT1, 256, SMEM_GEMM>>>(xhi, xlo, w+base+OFF_F1,
                                            bf1_l, 0, ahi, alo, BS, FFN, DD);
        tgemm_k<0><<<gT, 256, SMEM_GEMM>>>(ahi, alo, w+base+OFF_F2,
                                           bf2_l, tmp, 0, 0, BS, DD, FFN);
        add_ln_k<<<BS, 256>>>(x, tmp, ln2_s + l*DD, ln2_b + l*DD, xhi, xlo);
    }

    int nrows = out_size / 7;
    classify_k<<<nrows, 256>>>(x, Wc, bc, lo_p, ro_p, out, nrows);
}

// round 7
// speedup vs baseline: 2.4389x; 1.0958x over previous
#include <cuda_runtime.h>
#include <cuda_fp16.h>
#include <cstdint>
#include <math.h>

#define BB 2
#define SS 4096
#define DD 768
#define HH 12
#define LL 2
#define DHH 64
#define WW 256
#define GG 64
#define FFN 3072
#define NB 16
#define SEPID 2
#define NEGV -1000000000.0f
#define BS (BB*SS)
#define QS (5*DD)
#define NSEG 8
#define SEGS (SS/NSEG)      // 512
#define BH (BB*HH)          // 24

// weight arena offsets (fp16, transposed [N][K]); Q,K,V,KG,VG contiguous
#define WSZ_DD (DD*DD)
#define OFF_Q  0
#define OFF_K  (1*WSZ_DD)
#define OFF_V  (2*WSZ_DD)
#define OFF_KG (3*WSZ_DD)
#define OFF_VG (4*WSZ_DD)
#define OFF_QG (5*WSZ_DD)
#define OFF_O  (6*WSZ_DD)
#define OFF_F1 (7*WSZ_DD)
#define OFF_F2 (7*WSZ_DD + DD*FFN)
#define LWOFF  (7*WSZ_DD + 2*DD*FFN)

// ---------------- scratch ----------------
__device__ float g_x[BS*DD];
__device__ float g_qkv[(size_t)BS*QS];
__device__ float g_attn[BS*DD];
__device__ float g_tmp[BS*DD];
__device__ float g_xg[BB*GG*DD];
__device__ float g_qg[BB*GG*DD];
__device__ float g_og[BB*GG*DD];
__device__ float g_bcat[2*QS];
__device__ float g_pacc[NSEG*BH*GG*64];
__device__ float g_pml[NSEG*BH*GG*2];
__device__ int   g_idxg[BB*GG];
__device__ unsigned char g_klo[BS];

__device__ __align__(16) __half g_w[2*LWOFF];
__device__ __align__(16) __half g_ahi[BS*FFN];
__device__ __align__(16) __half g_alo[BS*FFN];
__device__ __align__(16) __half g_xhi[BS*DD];
__device__ __align__(16) __half g_xlo[BS*DD];
__device__ __align__(16) __half g_xghi[BB*GG*DD];
__device__ __align__(16) __half g_xglo[BB*GG*DD];

// ---------------- helpers ----------------
__device__ __forceinline__ uint32_t smem_u32(const void* p) {
    uint32_t a;
    asm("{ .reg .u64 t; cvta.to.shared.u64 t, %1; cvt.u32.u64 %0, t; }" : "=r"(a) : "l"(p));
    return a;
}

__device__ __forceinline__ void cp16(uint32_t dst, const void* src) {
    asm volatile("cp.async.ca.shared.global [%0], [%1], 16;" :: "r"(dst), "l"(src));
}
#define CP_COMMIT() asm volatile("cp.async.commit_group;" ::: "memory")
#define CP_WAIT2()  asm volatile("cp.async.wait_group 2;" ::: "memory")

__device__ __forceinline__ void ldmat4(uint32_t& r0, uint32_t& r1, uint32_t& r2, uint32_t& r3,
                                       uint32_t addr) {
    asm volatile("ldmatrix.sync.aligned.m8n8.x4.shared.b16 {%0,%1,%2,%3}, [%4];"
        : "=r"(r0), "=r"(r1), "=r"(r2), "=r"(r3) : "r"(addr));
}

__device__ __forceinline__ void mma16816(float* d, const uint32_t* a, const uint32_t* b) {
    asm volatile("mma.sync.aligned.m16n8k16.row.col.f32.f16.f16.f32 "
        "{%0,%1,%2,%3}, {%4,%5,%6,%7}, {%8,%9}, {%0,%1,%2,%3};"
        : "+f"(d[0]), "+f"(d[1]), "+f"(d[2]), "+f"(d[3])
        : "r"(a[0]), "r"(a[1]), "r"(a[2]), "r"(a[3]), "r"(b[0]), "r"(b[1]));
}

__device__ __forceinline__ float gelu_f(float v) {
    return 0.5f*v*(1.f + tanhf(0.7978845608028654f*(v + 0.044715f*v*v*v)));
}

// ---------------- block reductions ----------------
__device__ __forceinline__ float blk_sum(float v) {
    __shared__ float sm[33];
    int lane = threadIdx.x & 31, wid = threadIdx.x >> 5;
    #pragma unroll
    for (int o = 16; o; o >>= 1) v += __shfl_xor_sync(0xffffffffu, v, o);
    if (lane == 0) sm[wid] = v;
    __syncthreads();
    if (wid == 0) {
        int nw = (blockDim.x + 31) >> 5;
        float r = (lane < nw) ? sm[lane] : 0.f;
        #pragma unroll
        for (int o = 16; o; o >>= 1) r += __shfl_xor_sync(0xffffffffu, r, o);
        if (lane == 0) sm[32] = r;
    }
    __syncthreads();
    float r = sm[32];
    __syncthreads();
    return r;
}

// ---------------- prep ----------------
__global__ void prep_k(const int* __restrict__ ids, const int* __restrict__ am,
                       int* __restrict__ idxg, unsigned char* __restrict__ klo) {
    int b = blockIdx.x;
    for (int s = threadIdx.x; s < SS; s += blockDim.x) {
        bool g = (ids[b*SS+s] == SEPID) || (s == 0);
        klo[b*SS+s] = (am[b*SS+s] != 0 && !g) ? 1 : 0;
    }
    if (threadIdx.x == 0) {
        int cnt = 0;
        for (int s = 0; s < SS && cnt < GG; s++)
            if (ids[b*SS+s] == SEPID || s == 0) idxg[b*GG + cnt++] = s;
        for (; cnt < GG; cnt++) idxg[b*GG + cnt] = 0;
    }
}

// ---------------- embedding + LN (+ fp16 split out) ----------------
__global__ void embed_ln_k(const int* __restrict__ ids, const float* __restrict__ etok,
                           const float* __restrict__ epos, const float* __restrict__ lns,
                           const float* __restrict__ lnb, float* __restrict__ x,
                           __half* __restrict__ xhi, __half* __restrict__ xlo) {
    int row = blockIdx.x;
    int spos = row & (SS - 1);
    int id = ids[row];
    const float* te = etok + (size_t)id * DD;
    const float* pe = epos + (size_t)spos * DD;
    float v[3]; float sum = 0.f;
    #pragma unroll
    for (int i = 0; i < 3; i++) {
        int d = threadIdx.x + i*256;
        float val = te[d] + pe[d];
        v[i] = val; sum += val;
    }
    float mean = blk_sum(sum) * (1.0f/DD);
    float sq = 0.f;
    #pragma unroll
    for (int i = 0; i < 3; i++) { float c = v[i] - mean; sq += c*c; }
    float inv = rsqrtf(blk_sum(sq) * (1.0f/DD) + 1e-5f);
    #pragma unroll
    for (int i = 0; i < 3; i++) {
        int d = threadIdx.x + i*256;
        float o = (v[i] - mean)*inv*lns[d] + lnb[d];
        x[(size_t)row*DD + d] = o;
        __half h = __float2half(o);
        xhi[(size_t)row*DD + d] = h;
        xlo[(size_t)row*DD + d] = __float2half(o - __half2float(h));
    }
}

// ---------------- residual add + LN (+ fp16 split out) ----------------
__global__ void add_ln_k(float* __restrict__ x, const float* __restrict__ t,
                         const float* __restrict__ lns, const float* __restrict__ lnb,
                         __half* __restrict__ xhi, __half* __restrict__ xlo) {
    int row = blockIdx.x;
    size_t base = (size_t)row * DD;
    float v[3]; float sum = 0.f;
    #pragma unroll
    for (int i = 0; i < 3; i++) {
        int d = threadIdx.x + i*256;
        float val = x[base+d] + t[base+d];
        v[i] = val; sum += val;
    }
    float mean = blk_sum(sum) * (1.0f/DD);
    float sq = 0.f;
    #pragma unroll
    for (int i = 0; i < 3; i++) { float c = v[i] - mean; sq += c*c; }
    float inv = rsqrtf(blk_sum(sq) * (1.0f/DD) + 1e-5f);
    #pragma unroll
    for (int i = 0; i < 3; i++) {
        int d = threadIdx.x + i*256;
        float o = (v[i] - mean)*inv*lns[d] + lnb[d];
        x[base+d] = o;
        __half h = __float2half(o);
        xhi[base+d] = h;
        xlo[base+d] = __float2half(o - __half2float(h));
    }
}

// ---------------- conversions ----------------
__global__ void asplit_k(const float4* __restrict__ A, __half2* __restrict__ hi,
                         __half2* __restrict__ lo, int n4) {
    int i = blockIdx.x*256 + threadIdx.x;
    if (i >= n4) return;
    float4 v = A[i];
    __half hx = __float2half(v.x), hy = __float2half(v.y);
    __half hz = __float2half(v.z), hw = __float2half(v.w);
    hi[2*i]   = __halves2half2(hx, hy);
    hi[2*i+1] = __halves2half2(hz, hw);
    lo[2*i]   = __halves2half2(__float2half(v.x - __half2float(hx)),
                               __float2half(v.y - __half2float(hy)));
    lo[2*i+1] = __halves2half2(__float2half(v.z - __half2float(hz)),
                               __float2half(v.w - __half2float(hw)));
}

__global__ void wsplit_t_k(const float* __restrict__ W, __half* __restrict__ hi,
                           int K, int N) {
    __shared__ float t[32][33];
    int n0 = blockIdx.x*32, k0 = blockIdx.y*32;
    int tx = threadIdx.x, ty = threadIdx.y;
    #pragma unroll
    for (int i = 0; i < 4; i++)
        t[ty+8*i][tx] = W[(size_t)(k0+ty+8*i)*N + n0 + tx];
    __syncthreads();
    #pragma unroll
    for (int i = 0; i < 4; i++) {
        float v = t[tx][ty+8*i];
        hi[(size_t)(n0+ty+8*i)*K + k0 + tx] = __float2half(v);
    }
}

__global__ void bcat_k(const float* __restrict__ b0, const float* __restrict__ b1,
                       const float* __restrict__ b2, const float* __restrict__ b3,
                       const float* __restrict__ b4, float* __restrict__ dst) {
    int i = blockIdx.x*256 + threadIdx.x;
    if (i >= QS) return;
    int seg = i / DD, off = i - seg*DD;
    const float* src = (seg == 0) ? b0 : (seg == 1) ? b1 : (seg == 2) ? b2 : (seg == 3) ? b3 : b4;
    dst[i] = src[off];
}

// ---------------- tensor-core GEMM: cp.async 4-stage, fp16 2-pass compensated ----
#define SPAD 40
#define STG_BYTES (128*SPAD*2)
#define SMEM_GEMM (8*STG_BYTES)

template<int GELU>
__global__ void __launch_bounds__(256) tgemm_k(
        const __half* __restrict__ Ahi, const __half* __restrict__ Alo,
        const __half* __restrict__ B,
        const float* __restrict__ bias, float* __restrict__ C,
        __half* __restrict__ Chi, __half* __restrict__ Clo,
        int M, int N, int K) {
    extern __shared__ char smem[];
    const uint32_t sm0 = smem_u32(smem);
    const int bn = blockIdx.x << 7, bm = blockIdx.y << 7;
    const int tid = threadIdx.x, wid = tid >> 5, lane = tid & 31;
    const int wm = (wid >> 2) << 6;
    const int wn = (wid & 3) << 5;

    float acc[4][4][4];
    #pragma unroll
    for (int i = 0; i < 4; i++)
        #pragma unroll
        for (int j = 0; j < 4; j++)
            #pragma unroll
            for (int r = 0; r < 4; r++) acc[i][j][r] = 0.f;

    const int KC = K >> 5;
    const int total = 2 * KC;
    const __half* Aps[2] = {Ahi, Alo};

    const int r0 = tid >> 2, c0 = (tid & 3) << 3;
    const int r1 = r0 + 64;
    const uint32_t dA0 = (uint32_t)((r0*SPAD + c0) << 1);
    const uint32_t dA1 = (uint32_t)((r1*SPAD + c0) << 1);

    const int lrow = lane & 15, lcol = (lane >> 4) << 3;
    const uint32_t offA = (uint32_t)(((wm + lrow) * SPAD + lcol) << 1);
    const uint32_t offB = (uint32_t)(((wn + lrow) * SPAD + lcol) << 1) + 4*STG_BYTES;

    #pragma unroll
    for (int p = 0; p < 3; p++) {
        const int pass = (p < KC) ? 0 : 1;
        const int kc = p - pass*KC;
        const __half* Ap = Aps[pass];
        const int kb = kc << 5;
        const uint32_t sa = sm0 + p*STG_BYTES;
        const uint32_t sb = sm0 + 4*STG_BYTES + p*STG_BYTES;
        cp16(sa + dA0, Ap + (size_t)(bm + r0)*K + kb + c0);
        cp16(sa + dA1, Ap + (size_t)(bm + r1)*K + kb + c0);
        cp16(sb + dA0, B + (size_t)(bn + r0)*K + kb + c0);
        cp16(sb + dA1, B + (size_t)(bn + r1)*K + kb + c0);
        CP_COMMIT();
    }

    for (int s = 0; s < total; s++) {
        CP_WAIT2();
        __syncthreads();
        // issue chunk s+3 into stage (s+3)&3 == (s-1)&3, whose compute finished
        // before all threads reached the sync above.
        const int p = s + 3;
        if (p < total) {
            const int pass = (p < KC) ? 0 : 1;
            const int kc = p - pass*KC;
            const __half* Ap = Aps[pass];
            const int kb = kc << 5;
            const int st2 = p & 3;
            const uint32_t sa = sm0 + st2*STG_BYTES;
            const uint32_t sb = sm0 + 4*STG_BYTES + st2*STG_BYTES;
            cp16(sa + dA0, Ap + (size_t)(bm + r0)*K + kb + c0);
            cp16(sa + dA1, Ap + (size_t)(bm + r1)*K + kb + c0);
            cp16(sb + dA0, B + (size_t)(bn + r0)*K + kb + c0);
            cp16(sb + dA1, B + (size_t)(bn + r1)*K + kb + c0);
        }
        CP_COMMIT();
        const int stg = s & 3;
        const uint32_t abase = sm0 + stg*STG_BYTES + offA;
        const uint32_t bbase = sm0 + stg*STG_BYTES + offB;
        #pragma unroll
        for (int ks = 0; ks < 2; ks++) {
            uint32_t af[4][4], bf[4][2];
            #pragma unroll
            for (int mt = 0; mt < 4; mt++)
                ldmat4(af[mt][0], af[mt][1], af[mt][2], af[mt][3],
                       abase + (uint32_t)(((mt << 4) * SPAD + (ks << 4)) << 1));
            #pragma unroll
            for (int np = 0; np < 2; np++) {
                uint32_t m0, m1, m2, m3;
                ldmat4(m0, m1, m2, m3,
                       bbase + (uint32_t)(((np << 4) * SPAD + (ks << 4)) << 1));
                bf[2*np][0] = m0; bf[2*np+1][0] = m1;
                bf[2*np][1] = m2; bf[2*np+1][1] = m3;
            }
            #pragma unroll
            for (int mt = 0; mt < 4; mt++)
                #pragma unroll
                for (int nt = 0; nt < 4; nt++)
                    mma16816(acc[mt][nt], af[mt], bf[nt]);
        }
    }

    const int mrow = lane >> 2, ncol = (lane & 3) << 1;
    #pragma unroll
    for (int mt = 0; mt < 4; mt++) {
        #pragma unroll
        for (int nt = 0; nt < 4; nt++) {
            int r = bm + wm + (mt << 4) + mrow;
            int c = bn + wn + (nt << 3) + ncol;
            float b0 = bias[c], b1 = bias[c+1];
            float v0 = acc[mt][nt][0] + b0, v1 = acc[mt][nt][1] + b1;
            float v2 = acc[mt][nt][2] + b0, v3 = acc[mt][nt][3] + b1;
            if (GELU) {
                v0 = gelu_f(v0); v1 = gelu_f(v1); v2 = gelu_f(v2); v3 = gelu_f(v3);
                __half h0 = __float2half(v0), h1 = __float2half(v1);
                __half h2 = __float2half(v2), h3 = __float2half(v3);
                *(__half2*)&Chi[(size_t)r*N + c]     = __halves2half2(h0, h1);
                *(__half2*)&Chi[(size_t)(r+8)*N + c] = __halves2half2(h2, h3);
                *(__half2*)&Clo[(size_t)r*N + c]     = __halves2half2(
                    __float2half(v0 - __half2float(h0)), __float2half(v1 - __half2float(h1)));
                *(__half2*)&Clo[(size_t)(r+8)*N + c] = __halves2half2(
                    __float2half(v2 - __half2float(h2)), __float2half(v3 - __half2float(h3)));
            } else {
                *(float2*)&C[(size_t)r*N + c]     = make_float2(v0, v1);
                *(float2*)&C[(size_t)(r+8)*N + c] = make_float2(v2, v3);
            }
        }
    }
}

// ---------------- fused band attention (online softmax, per-thread chunk skip) --
__global__ void band_fused_k(const float* __restrict__ qkv, const int* __restrict__ idxg,
                             const unsigned char* __restrict__ klo, float* __restrict__ out) {
    extern __shared__ float sm[];
    float* kt  = sm;
    float* vt  = sm + 4096;
    float* ssc = sm + 8192;
    int n = blockIdx.x;
    int b = blockIdx.y / HH, h = blockIdx.y % HH;
    int qr = threadIdx.x;
    int sq = n*WW + qr;
    float qv[64];
    const float4* qp = (const float4*)(qkv + (size_t)(b*SS+sq)*QS + h*DHH);
    #pragma unroll
    for (int d4 = 0; d4 < 16; d4++) {
        float4 t = qp[d4];
        qv[4*d4] = t.x; qv[4*d4+1] = t.y; qv[4*d4+2] = t.z; qv[4*d4+3] = t.w;
    }
    float acc[64];
    #pragma unroll
    for (int d = 0; d < 64; d++) acc[d] = 0.f;
    float mrow = -INFINITY, lrow = 0.f;

    for (int c = 0; c < 13; c++) {
        __syncthreads();
        for (int idx = threadIdx.x; idx < 4096; idx += 256) {
            int kk = idx >> 6, d = idx & 63;
            int j = (c << 6) + kk;
            float kval = 0.f, vval = 0.f;
            if (j < 768) {
                int kp = n*WW + j - WW;
                if (kp >= 0 && kp < SS) {
                    size_t base = (size_t)(b*SS+kp)*QS + h*DHH + d;
                    kval = qkv[base + DD];
                    vval = qkv[base + 2*DD];
                }
            } else {
                int kp = idxg[b*GG + (j - 768)];
                size_t base = (size_t)(b*SS+kp)*QS + h*DHH + d;
                kval = qkv[base + DD];
                vval = qkv[base + 2*DD];
            }
            kt[idx] = kval;
            vt[idx] = vval;
        }
        __syncthreads();
        // chunk fully masked for this thread iff no j in [64c,64c+64) hits [qr, qr+512]
        bool active = (c == 12) || ((64*c + 63 >= qr) && (64*c <= qr + 512));
        if (active) {
            float cmax = -INFINITY;
            for (int kk = 0; kk < 64; kk++) {
                int j = (c << 6) + kk;
                const float4* kr = (const float4*)(kt + (kk << 6));
                float s = 0.f;
                #pragma unroll
                for (int d4 = 0; d4 < 16; d4++) {
                    float4 kv = kr[d4];
                    s += qv[4*d4]*kv.x + qv[4*d4+1]*kv.y + qv[4*d4+2]*kv.z + qv[4*d4+3]*kv.w;
                }
                s *= 0.125f;
                if (j < 768) {
                    int kp = n*WW + j - WW;
                    int rel = j - WW - qr;
                    bool ok = (kp >= 0) && (kp < SS) && klo[b*SS+kp] && (rel >= -WW) && (rel <= WW);
                    if (!ok) s = NEGV;
                }
                ssc[qr*65 + kk] = s;
                cmax = fmaxf(cmax, s);
            }
            float mnew = fmaxf(mrow, cmax);
            float rescale = __expf(mrow - mnew);
            lrow *= rescale;
            #pragma unroll
            for (int d = 0; d < 64; d++) acc[d] *= rescale;
            for (int kk = 0; kk < 64; kk++) {
                float e = __expf(ssc[qr*65 + kk] - mnew);
                lrow += e;
                const float4* vr = (const float4*)(vt + (kk << 6));
                #pragma unroll
                for (int d4 = 0; d4 < 16; d4++) {
                    float4 vv = vr[d4];
                    acc[4*d4]   += e*vv.x; acc[4*d4+1] += e*vv.y;
                    acc[4*d4+2] += e*vv.z; acc[4*d4+3] += e*vv.w;
                }
            }
            mrow = mnew;
        }
    }
    float inv = 1.f / lrow;
    float4* op = (float4*)(out + (size_t)(b*SS+sq)*DD + h*DHH);
    #pragma unroll
    for (int d4 = 0; d4 < 16; d4++)
        op[d4] = make_float4(acc[4*d4]*inv, acc[4*d4+1]*inv, acc[4*d4+2]*inv, acc[4*d4+3]*inv);
}

// ---------------- global attention: segmented partials ----------------
// grid (NSEG, BH), 256 threads. thread = (g = tid>>2, part = tid&3, 16 dims each).
#define KSP 68
#define SMEM_GLOB ((2*128*KSP + 64*132) * 4)

__global__ void __launch_bounds__(256, 1) glob_part_k(
        const float* __restrict__ qg, const float* __restrict__ qkv,
        const int* __restrict__ am, float* __restrict__ pacc, float* __restrict__ pml) {
    extern __shared__ float sm[];
    float* Ks = sm;
    float* Vs = sm + 128*KSP;
    float* ps = sm + 2*128*KSP;   // 64 x 132
    int seg = blockIdx.x;
    int bh = blockIdx.y, b = bh / HH, h = bh % HH;
    int tid = threadIdx.x;
    int g = tid >> 2, part = tid & 3;

    float qv[64];
    const float4* qp = (const float4*)(qg + (size_t)(b*GG+g)*DD + h*DHH);
    #pragma unroll
    for (int d4 = 0; d4 < 16; d4++) {
        float4 t = qp[d4];
        qv[4*d4] = t.x; qv[4*d4+1] = t.y; qv[4*d4+2] = t.z; qv[4*d4+3] = t.w;
    }
    float acc[16];
    #pragma unroll
    for (int i = 0; i < 16; i++) acc[i] = 0.f;
    float mrow = -INFINITY, lrow = 0.f;

    for (int c = 0; c < SEGS/128; c++) {
        int s0 = seg*SEGS + c*128;
        __syncthreads();
        #pragma unroll
        for (int t = 0; t < 8; t++) {
            int idx = tid + (t << 8);
            int row = idx >> 4, c4 = idx & 15;
            const float* src = qkv + (size_t)(b*SS + s0 + row)*QS + h*DHH + (c4 << 2);
            *(float4*)&Ks[row*KSP + (c4 << 2)] = *(const float4*)(src + 3*DD);
            *(float4*)&Vs[row*KSP + (c4 << 2)] = *(const float4*)(src + 4*DD);
        }
        __syncthreads();
        // scores for 32 keys: kk = 4*i + part
        float es[32];
        float cmax = -INFINITY;
        #pragma unroll 4
        for (int i = 0; i < 32; i++) {
            int kk = (i << 2) + part;
            const float4* kr = (const float4*)(Ks + kk*KSP);
            float dot = 0.f;
            #pragma unroll
            for (int d4 = 0; d4 < 16; d4++) {
                float4 kv = kr[d4];
                dot += qv[4*d4]*kv.x + qv[4*d4+1]*kv.y + qv[4*d4+2]*kv.z + qv[4*d4+3]*kv.w;
            }
            float val = (am[b*SS + s0 + kk] != 0) ? dot*0.125f : NEGV;
            es[i] = val; cmax = fmaxf(cmax, val);
        }
        cmax = fmaxf(cmax, __shfl_xor_sync(0xffffffffu, cmax, 1));
        cmax = fmaxf(cmax, __shfl_xor_sync(0xffffffffu, cmax, 2));
        float mnew = fmaxf(mrow, cmax);
        float rs = __expf(mrow - mnew);
        float lsum = 0.f;
        #pragma unroll 4
        for (int i = 0; i < 32; i++) {
            float e = __expf(es[i] - mnew);
            ps[g*132 + (i << 2) + part] = e;
            lsum += e;
        }
        lsum += __shfl_xor_sync(0xffffffffu, lsum, 1);
        lsum += __shfl_xor_sync(0xffffffffu, lsum, 2);
        lrow = lrow*rs + lsum;
        #pragma unroll
        for (int i = 0; i < 16; i++) acc[i] *= rs;
        mrow = mnew;
        __syncthreads();
        // PV: all 128 keys, dims part*16..part*16+15
        for (int kk = 0; kk < 128; kk++) {
            float e = ps[g*132 + kk];
            const float4* vr = (const float4*)(Vs + kk*KSP + (part << 4));
            #pragma unroll
            for (int i4 = 0; i4 < 4; i4++) {
                float4 vv = vr[i4];
                acc[4*i4]   += e*vv.x; acc[4*i4+1] += e*vv.y;
                acc[4*i4+2] += e*vv.z; acc[4*i4+3] += e*vv.w;
            }
        }
    }
    size_t pb = ((size_t)(seg*BH + bh)*GG + g);
    float4* pa = (float4*)(pacc + pb*64 + (part << 4));
    #pragma unroll
    for (int i4 = 0; i4 < 4; i4++)
        pa[i4] = make_float4(acc[4*i4], acc[4*i4+1], acc[4*i4+2], acc[4*i4+3]);
    if (part == 0) { pml[pb*2] = mrow; pml[pb*2+1] = lrow; }
}

// combine: grid (BH), 256 threads
__global__ void glob_comb_k(const float* __restrict__ pacc, const float* __restrict__ pml,
                            float* __restrict__ og) {
    int bh = blockIdx.x, b = bh / HH, h = bh % HH;
    int tid = threadIdx.x;
    int g = tid >> 2, part = tid & 3;
    float ms[NSEG], ls[NSEG];
    float M = -INFINITY;
    #pragma unroll
    for (int s = 0; s < NSEG; s++) {
        size_t pb = ((size_t)(s*BH + bh)*GG + g);
        ms[s] = pml[pb*2]; ls[s] = pml[pb*2+1];
        M = fmaxf(M, ms[s]);
    }
    float L = 0.f;
    float acc[16];
    #pragma unroll
    for (int i = 0; i < 16; i++) acc[i] = 0.f;
    #pragma unroll
    for (int s = 0; s < NSEG; s++) {
        float wgt = __expf(ms[s] - M);
        L += ls[s]*wgt;
        size_t pb = ((size_t)(s*BH + bh)*GG + g);
        const float4* pa = (const float4*)(pacc + pb*64 + (part << 4));
        #pragma unroll
        for (int i4 = 0; i4 < 4; i4++) {
            float4 v = pa[i4];
            acc[4*i4]   += wgt*v.x; acc[4*i4+1] += wgt*v.y;
            acc[4*i4+2] += wgt*v.z; acc[4*i4+3] += wgt*v.w;
        }
    }
    float inv = 1.f / L;
    float4* op = (float4*)(og + (size_t)(b*GG+g)*DD + h*DHH + (part << 4));
    #pragma unroll
    for (int i4 = 0; i4 < 4; i4++)
        op[i4] = make_float4(acc[4*i4]*inv, acc[4*i4+1]*inv, acc[4*i4+2]*inv, acc[4*i4+3]*inv);
}

// ---------------- gather / scatter ----------------
__global__ void gather_k(const float* __restrict__ x, const int* __restrict__ idxg,
                         float* __restrict__ xg) {
    int r = blockIdx.x;
    int b = r / GG;
    int src = idxg[r];
    for (int d = threadIdx.x; d < DD; d += blockDim.x)
        xg[(size_t)r*DD + d] = x[((size_t)(b*SS+src))*DD + d];
}

__global__ void scatter_k(const float* __restrict__ og, const int* __restrict__ idxg,
                          float* __restrict__ out) {
    int r = blockIdx.x;
    int b = r / GG;
    int dst = idxg[r];
    for (int d = threadIdx.x; d < DD; d += blockDim.x)
        out[((size_t)(b*SS+dst))*DD + d] = og[(size_t)r*DD + d];
}

// ---------------- classifier ----------------
__global__ void classify_k(const float* __restrict__ x, const float* __restrict__ Wc,
                           const float* __restrict__ bc, const int* __restrict__ lo_p,
                           const int* __restrict__ ro_p, float* __restrict__ out, int nrows) {
    int r = blockIdx.x;
    int lo = *lo_p, ro = *ro_p;
    int per_b = 63 - lo - ro;
    if (per_b <= 0) per_b = 1;
    int b = r / per_b, t = lo + (r - b*per_b);
    const float* row = x + ((size_t)(b*SS + t))*DD;
    float p[7];
    #pragma unroll
    for (int c = 0; c < 7; c++) p[c] = 0.f;
    for (int d = threadIdx.x; d < DD; d += 256) {
        float xv = row[d];
        #pragma unroll
        for (int c = 0; c < 7; c++) p[c] += xv * Wc[d*7 + c];
    }
    #pragma unroll
    for (int c = 0; c < 7; c++) {
        float tot = blk_sum(p[c]);
        if (threadIdx.x == 0) out[r*7 + c] = tot + bc[c];
    }
}

// ---------------- launch ----------------
extern "C" void kernel_launch(void* const* d_in, const int* in_sizes, int n_in,
                              void* d_out, int out_size) {
    const float* emb_tok = (const float*)d_in[0];
    const float* emb_pos = (const float*)d_in[1];
    const float* ln_e_s  = (const float*)d_in[2];
    const float* ln_e_b  = (const float*)d_in[3];
    const float* Wq  = (const float*)d_in[4];
    const float* bq  = (const float*)d_in[5];
    const float* Wk  = (const float*)d_in[6];
    const float* bk  = (const float*)d_in[7];
    const float* Wv  = (const float*)d_in[8];
    const float* bv  = (const float*)d_in[9];
    const float* Wqg = (const float*)d_in[10];
    const float* bqg = (const float*)d_in[11];
    const float* Wkg = (const float*)d_in[12];
    const float* bkg = (const float*)d_in[13];
    const float* Wvg = (const float*)d_in[14];
    const float* bvg = (const float*)d_in[15];
    const float* Wo  = (const float*)d_in[16];
    const float* bo  = (const float*)d_in[17];
    const float* ln1_s = (const float*)d_in[18];
    const float* ln1_b = (const float*)d_in[19];
    const float* Wf1 = (const float*)d_in[20];
    const float* bf1 = (const float*)d_in[21];
    const float* Wf2 = (const float*)d_in[22];
    const float* bf2 = (const float*)d_in[23];
    const float* ln2_s = (const float*)d_in[24];
    const float* ln2_b = (const float*)d_in[25];
    const float* Wc  = (const float*)d_in[26];
    const float* bc  = (const float*)d_in[27];
    const int* input_ids = (const int*)d_in[28];
    const int* attn_mask = (const int*)d_in[29];
    const int* lo_p = (const int*)d_in[30];
    const int* ro_p = (const int*)d_in[31];
    float* out = (float*)d_out;

    float *x, *qkv, *attn, *tmp, *xg, *qg, *og, *bcat, *pacc, *pml;
    int* idxg; unsigned char* klo;
    __half *w, *ahi, *alo, *xhi, *xlo, *xghi, *xglo;
    cudaGetSymbolAddress((void**)&x,    g_x);
    cudaGetSymbolAddress((void**)&qkv,  g_qkv);
    cudaGetSymbolAddress((void**)&attn, g_attn);
    cudaGetSymbolAddress((void**)&tmp,  g_tmp);
    cudaGetSymbolAddress((void**)&xg,   g_xg);
    cudaGetSymbolAddress((void**)&qg,   g_qg);
    cudaGetSymbolAddress((void**)&og,   g_og);
    cudaGetSymbolAddress((void**)&bcat, g_bcat);
    cudaGetSymbolAddress((void**)&pacc, g_pacc);
    cudaGetSymbolAddress((void**)&pml,  g_pml);
    cudaGetSymbolAddress((void**)&idxg, g_idxg);
    cudaGetSymbolAddress((void**)&klo,  g_klo);
    cudaGetSymbolAddress((void**)&w,    g_w);
    cudaGetSymbolAddress((void**)&ahi,  g_ahi);
    cudaGetSymbolAddress((void**)&alo,  g_alo);
    cudaGetSymbolAddress((void**)&xhi,  g_xhi);
    cudaGetSymbolAddress((void**)&xlo,  g_xlo);
    cudaGetSymbolAddress((void**)&xghi, g_xghi);
    cudaGetSymbolAddress((void**)&xglo, g_xglo);

    const int SMEM_BAND = (4096 + 4096 + 256*65) * 4;
    cudaFuncSetAttribute(band_fused_k, cudaFuncAttributeMaxDynamicSharedMemorySize, SMEM_BAND);
    cudaFuncSetAttribute(tgemm_k<0>, cudaFuncAttributeMaxDynamicSharedMemorySize, SMEM_GEMM);
    cudaFuncSetAttribute(tgemm_k<1>, cudaFuncAttributeMaxDynamicSharedMemorySize, SMEM_GEMM);
    cudaFuncSetAttribute(glob_part_k, cudaFuncAttributeMaxDynamicSharedMemorySize, SMEM_GLOB);

    prep_k<<<BB, 256>>>(input_ids, attn_mask, idxg, klo);
    embed_ln_k<<<BS, 256>>>(input_ids, emb_tok, emb_pos, ln_e_s, ln_e_b, x, xhi, xlo);

    dim3 wb(32, 8);
    for (int l = 0; l < LL; l++) {
        size_t base = (size_t)l * LWOFF;
        wsplit_t_k<<<dim3(DD/32, DD/32), wb>>>(Wq  + (size_t)l*DD*DD, w+base+OFF_Q,  DD, DD);
        wsplit_t_k<<<dim3(DD/32, DD/32), wb>>>(Wk  + (size_t)l*DD*DD, w+base+OFF_K,  DD, DD);
        wsplit_t_k<<<dim3(DD/32, DD/32), wb>>>(Wv  + (size_t)l*DD*DD, w+base+OFF_V,  DD, DD);
        wsplit_t_k<<<dim3(DD/32, DD/32), wb>>>(Wkg + (size_t)l*DD*DD, w+base+OFF_KG, DD, DD);
        wsplit_t_k<<<dim3(DD/32, DD/32), wb>>>(Wvg + (size_t)l*DD*DD, w+base+OFF_VG, DD, DD);
        wsplit_t_k<<<dim3(DD/32, DD/32), wb>>>(Wqg + (size_t)l*DD*DD, w+base+OFF_QG, DD, DD);
        wsplit_t_k<<<dim3(DD/32, DD/32), wb>>>(Wo  + (size_t)l*DD*DD, w+base+OFF_O,  DD, DD);
        wsplit_t_k<<<dim3(FFN/32, DD/32), wb>>>(Wf1 + (size_t)l*DD*FFN, w+base+OFF_F1, DD, FFN);
        wsplit_t_k<<<dim3(DD/32, FFN/32), wb>>>(Wf2 + (size_t)l*FFN*DD, w+base+OFF_F2, FFN, DD);
        bcat_k<<<(QS+255)/256, 256>>>(bq + l*DD, bk + l*DD, bv + l*DD, bkg + l*DD, bvg + l*DD,
                                      bcat + l*QS);
    }

    dim3 gTqkv(QS/128, BS/128);
    dim3 gT(DD/128, BS/128);
    dim3 gT1(FFN/128, BS/128);
    dim3 gTqg(DD/128, 1);
    dim3 gBand(NB, BB*HH);
    dim3 gGlobP(NSEG, BH);
    const int nXD4 = BS*DD/4, nXG4 = BB*GG*DD/4;

    for (int l = 0; l < LL; l++) {
        size_t base = (size_t)l * LWOFF;
        const float* bqg_l = bqg + l*DD;
        const float* bo_l  = bo  + l*DD;
        const float* bf1_l = bf1 + l*FFN; const float* bf2_l = bf2 + l*DD;

        tgemm_k<0><<<gTqkv, 256, SMEM_GEMM>>>(xhi, xlo, w+base+OFF_Q,
                                              bcat + l*QS, qkv, 0, 0, BS, QS, DD);

        gather_k<<<BB*GG, 256>>>(x, idxg, xg);
        asplit_k<<<(nXG4+255)/256, 256>>>((const float4*)xg, (__half2*)xghi, (__half2*)xglo, nXG4);
        tgemm_k<0><<<gTqg, 256, SMEM_GEMM>>>(xghi, xglo, w+base+OFF_QG,
                                             bqg_l, qg, 0, 0, BB*GG, DD, DD);

        band_fused_k<<<gBand, 256, SMEM_BAND>>>(qkv, idxg, klo, attn);

        glob_part_k<<<gGlobP, 256, SMEM_GLOB>>>(qg, qkv, attn_mask, pacc, pml);
        glob_comb_k<<<BH, 256>>>(pacc, pml, og);
        scatter_k<<<BB*GG, 256>>>(og, idxg, attn);

        asplit_k<<<(nXD4+255)/256, 256>>>((const float4*)attn, (__half2*)xhi, (__half2*)xlo, nXD4);
        tgemm_k<0><<<gT, 256, SMEM_GEMM>>>(xhi, xlo, w+base+OFF_O,
                                           bo_l, tmp, 0, 0, BS, DD, DD);
        add_ln_k<<<BS, 256>>>(x, tmp, ln1_s + l*DD, ln1_b + l*DD, xhi, xlo);

        tgemm_k<1><<<gT1, 256, SMEM_GEMM>>>(xhi, xlo, w+base+OFF_F1,
                                            bf1_l, 0, ahi, alo, BS, FFN, DD);
        tgemm_k<0><<<gT, 256, SMEM_GEMM>>>(ahi, alo, w+base+OFF_F2,
                                           bf2_l, tmp, 0, 0, BS, DD, FFN);
        add_ln_k<<<BS, 256>>>(x, tmp, ln2_s + l*DD, ln2_b + l*DD, xhi, xlo);
    }

    int nrows = out_size / 7;
    classify_k<<<nrows, 256>>>(x, Wc, bc, lo_p, ro_p, out, nrows);
}

// round 8
// speedup vs baseline: 3.8188x; 1.5658x over previous
#include <cuda_runtime.h>
#include <cuda_fp16.h>
#include <cstdint>
#include <math.h>

#define BB 2
#define SS 4096
#define DD 768
#define HH 12
#define LL 2
#define DHH 64
#define WW 256
#define GG 64
#define FFN 3072
#define SEPID 2
#define NEGV -1000000000.0f
#define BS (BB*SS)
#define QS (5*DD)
#define NSEG 8
#define SEGS (SS/NSEG)
#define BH (BB*HH)

#define WSZ_DD (DD*DD)
#define OFF_Q  0
#define OFF_K  (1*WSZ_DD)
#define OFF_V  (2*WSZ_DD)
#define OFF_KG (3*WSZ_DD)
#define OFF_VG (4*WSZ_DD)
#define OFF_QG (5*WSZ_DD)
#define OFF_O  (6*WSZ_DD)
#define OFF_F1 (7*WSZ_DD)
#define OFF_F2 (7*WSZ_DD + DD*FFN)
#define LWOFF  (7*WSZ_DD + 2*DD*FFN)

// ---------------- scratch ----------------
__device__ float g_x[BS*DD];
__device__ float g_qkv[(size_t)BS*QS];
__device__ float g_attn[BS*DD];
__device__ float g_tmp[BS*DD];
__device__ float g_xg[BB*GG*DD];
__device__ float g_qg[BB*GG*DD];
__device__ float g_og[BB*GG*DD];
__device__ float g_bcat[2*QS];
__device__ float g_pacc[NSEG*BH*GG*64];
__device__ float g_pml[NSEG*BH*GG*2];
__device__ int   g_idxg[BB*GG];
__device__ unsigned char g_klo[BS];

__device__ __align__(16) __half g_w[2*LWOFF];
__device__ __align__(16) __half g_ahi[BS*FFN];
__device__ __align__(16) __half g_alo[BS*FFN];
__device__ __align__(16) __half g_xhi[BS*DD];
__device__ __align__(16) __half g_xlo[BS*DD];
__device__ __align__(16) __half g_xghi[BB*GG*DD];
__device__ __align__(16) __half g_xglo[BB*GG*DD];
// band attention fp16 operands
__device__ __align__(16) __half g_bqh[BS*DD];
__device__ __align__(16) __half g_bql[BS*DD];
__device__ __align__(16) __half g_bkh[BS*DD];
__device__ __align__(16) __half g_bvh[BS*DD];
__device__ __align__(16) __half g_bvl[BS*DD];

// ---------------- helpers ----------------
__device__ __forceinline__ uint32_t smem_u32(const void* p) {
    uint32_t a;
    asm("{ .reg .u64 t; cvta.to.shared.u64 t, %1; cvt.u32.u64 %0, t; }" : "=r"(a) : "l"(p));
    return a;
}

__device__ __forceinline__ void cp16(uint32_t dst, const void* src) {
    asm volatile("cp.async.ca.shared.global [%0], [%1], 16;" :: "r"(dst), "l"(src));
}
#define CP_COMMIT() asm volatile("cp.async.commit_group;" ::: "memory")
#define CP_WAIT2()  asm volatile("cp.async.wait_group 2;" ::: "memory")

__device__ __forceinline__ void ldmat4(uint32_t& r0, uint32_t& r1, uint32_t& r2, uint32_t& r3,
                                       uint32_t addr) {
    asm volatile("ldmatrix.sync.aligned.m8n8.x4.shared.b16 {%0,%1,%2,%3}, [%4];"
        : "=r"(r0), "=r"(r1), "=r"(r2), "=r"(r3) : "r"(addr));
}

__device__ __forceinline__ void ldmat4t(uint32_t& r0, uint32_t& r1, uint32_t& r2, uint32_t& r3,
                                        uint32_t addr) {
    asm volatile("ldmatrix.sync.aligned.m8n8.x4.trans.shared.b16 {%0,%1,%2,%3}, [%4];"
        : "=r"(r0), "=r"(r1), "=r"(r2), "=r"(r3) : "r"(addr));
}

__device__ __forceinline__ void mma16816(float* d, const uint32_t* a, const uint32_t* b) {
    asm volatile("mma.sync.aligned.m16n8k16.row.col.f32.f16.f16.f32 "
        "{%0,%1,%2,%3}, {%4,%5,%6,%7}, {%8,%9}, {%0,%1,%2,%3};"
        : "+f"(d[0]), "+f"(d[1]), "+f"(d[2]), "+f"(d[3])
        : "r"(a[0]), "r"(a[1]), "r"(a[2]), "r"(a[3]), "r"(b[0]), "r"(b[1]));
}

__device__ __forceinline__ uint32_t packh2(float a, float b) {
    __half2 h = __floats2half2_rn(a, b);
    return *(uint32_t*)&h;
}

__device__ __forceinline__ float gelu_f(float v) {
    return 0.5f*v*(1.f + tanhf(0.7978845608028654f*(v + 0.044715f*v*v*v)));
}

// ---------------- block reductions ----------------
__device__ __forceinline__ float blk_sum(float v) {
    __shared__ float sm[33];
    int lane = threadIdx.x & 31, wid = threadIdx.x >> 5;
    #pragma unroll
    for (int o = 16; o; o >>= 1) v += __shfl_xor_sync(0xffffffffu, v, o);
    if (lane == 0) sm[wid] = v;
    __syncthreads();
    if (wid == 0) {
        int nw = (blockDim.x + 31) >> 5;
        float r = (lane < nw) ? sm[lane] : 0.f;
        #pragma unroll
        for (int o = 16; o; o >>= 1) r += __shfl_xor_sync(0xffffffffu, r, o);
        if (lane == 0) sm[32] = r;
    }
    __syncthreads();
    float r = sm[32];
    __syncthreads();
    return r;
}

// ---------------- prep ----------------
__global__ void prep_k(const int* __restrict__ ids, const int* __restrict__ am,
                       int* __restrict__ idxg, unsigned char* __restrict__ klo) {
    int b = blockIdx.x;
    for (int s = threadIdx.x; s < SS; s += blockDim.x) {
        bool g = (ids[b*SS+s] == SEPID) || (s == 0);
        klo[b*SS+s] = (am[b*SS+s] != 0 && !g) ? 1 : 0;
    }
    if (threadIdx.x == 0) {
        int cnt = 0;
        for (int s = 0; s < SS && cnt < GG; s++)
            if (ids[b*SS+s] == SEPID || s == 0) idxg[b*GG + cnt++] = s;
        for (; cnt < GG; cnt++) idxg[b*GG + cnt] = 0;
    }
}

// ---------------- embedding + LN ----------------
__global__ void embed_ln_k(const int* __restrict__ ids, const float* __restrict__ etok,
                           const float* __restrict__ epos, const float* __restrict__ lns,
                           const float* __restrict__ lnb, float* __restrict__ x,
                           __half* __restrict__ xhi, __half* __restrict__ xlo) {
    int row = blockIdx.x;
    int spos = row & (SS - 1);
    int id = ids[row];
    const float* te = etok + (size_t)id * DD;
    const float* pe = epos + (size_t)spos * DD;
    float v[3]; float sum = 0.f;
    #pragma unroll
    for (int i = 0; i < 3; i++) {
        int d = threadIdx.x + i*256;
        float val = te[d] + pe[d];
        v[i] = val; sum += val;
    }
    float mean = blk_sum(sum) * (1.0f/DD);
    float sq = 0.f;
    #pragma unroll
    for (int i = 0; i < 3; i++) { float c = v[i] - mean; sq += c*c; }
    float inv = rsqrtf(blk_sum(sq) * (1.0f/DD) + 1e-5f);
    #pragma unroll
    for (int i = 0; i < 3; i++) {
        int d = threadIdx.x + i*256;
        float o = (v[i] - mean)*inv*lns[d] + lnb[d];
        x[(size_t)row*DD + d] = o;
        __half h = __float2half(o);
        xhi[(size_t)row*DD + d] = h;
        xlo[(size_t)row*DD + d] = __float2half(o - __half2float(h));
    }
}

// ---------------- residual add + LN ----------------
__global__ void add_ln_k(float* __restrict__ x, const float* __restrict__ t,
                         const float* __restrict__ lns, const float* __restrict__ lnb,
                         __half* __restrict__ xhi, __half* __restrict__ xlo) {
    int row = blockIdx.x;
    size_t base = (size_t)row * DD;
    float v[3]; float sum = 0.f;
    #pragma unroll
    for (int i = 0; i < 3; i++) {
        int d = threadIdx.x + i*256;
        float val = x[base+d] + t[base+d];
        v[i] = val; sum += val;
    }
    float mean = blk_sum(sum) * (1.0f/DD);
    float sq = 0.f;
    #pragma unroll
    for (int i = 0; i < 3; i++) { float c = v[i] - mean; sq += c*c; }
    float inv = rsqrtf(blk_sum(sq) * (1.0f/DD) + 1e-5f);
    #pragma unroll
    for (int i = 0; i < 3; i++) {
        int d = threadIdx.x + i*256;
        float o = (v[i] - mean)*inv*lns[d] + lnb[d];
        x[base+d] = o;
        __half h = __float2half(o);
        xhi[base+d] = h;
        xlo[base+d] = __float2half(o - __half2float(h));
    }
}

// ---------------- conversions ----------------
__global__ void asplit_k(const float4* __restrict__ A, __half2* __restrict__ hi,
                         __half2* __restrict__ lo, int n4) {
    int i = blockIdx.x*256 + threadIdx.x;
    if (i >= n4) return;
    float4 v = A[i];
    __half hx = __float2half(v.x), hy = __float2half(v.y);
    __half hz = __float2half(v.z), hw = __float2half(v.w);
    hi[2*i]   = __halves2half2(hx, hy);
    hi[2*i+1] = __halves2half2(hz, hw);
    lo[2*i]   = __halves2half2(__float2half(v.x - __half2float(hx)),
                               __float2half(v.y - __half2float(hy)));
    lo[2*i+1] = __halves2half2(__float2half(v.z - __half2float(hz)),
                               __float2half(v.w - __half2float(hw)));
}

// qkv fp32 -> band fp16 operands: q hi/lo, k hi, v hi/lo
__global__ void qkvsplit_k(const float* __restrict__ qkv,
                           __half* __restrict__ qh, __half* __restrict__ ql,
                           __half* __restrict__ kh,
                           __half* __restrict__ vh, __half* __restrict__ vl) {
    const int C4 = 3*DD/4;
    int i = blockIdx.x*256 + threadIdx.x;
    if (i >= BS*C4) return;
    int row = i / C4, c4 = i - row*C4;
    int col = c4 << 2;
    float4 v = *((const float4*)(qkv + (size_t)row*QS) + c4);
    int seg = col / DD;
    size_t off = (size_t)row*DD + (col - seg*DD);
    __half ax = __float2half(v.x), ay = __float2half(v.y);
    __half az = __float2half(v.z), aw = __float2half(v.w);
    __half2 h0 = __halves2half2(ax, ay), h1 = __halves2half2(az, aw);
    __half2 l0 = __halves2half2(__float2half(v.x - __half2float(ax)),
                                __float2half(v.y - __half2float(ay)));
    __half2 l1 = __halves2half2(__float2half(v.z - __half2float(az)),
                                __float2half(v.w - __half2float(aw)));
    if (seg == 0) {
        *(__half2*)&qh[off] = h0; *(__half2*)&qh[off+2] = h1;
        *(__half2*)&ql[off] = l0; *(__half2*)&ql[off+2] = l1;
    } else if (seg == 1) {
        *(__half2*)&kh[off] = h0; *(__half2*)&kh[off+2] = h1;
    } else {
        *(__half2*)&vh[off] = h0; *(__half2*)&vh[off+2] = h1;
        *(__half2*)&vl[off] = l0; *(__half2*)&vl[off+2] = l1;
    }
}

__global__ void wsplit_t_k(const float* __restrict__ W, __half* __restrict__ hi,
                           int K, int N) {
    __shared__ float t[32][33];
    int n0 = blockIdx.x*32, k0 = blockIdx.y*32;
    int tx = threadIdx.x, ty = threadIdx.y;
    #pragma unroll
    for (int i = 0; i < 4; i++)
        t[ty+8*i][tx] = W[(size_t)(k0+ty+8*i)*N + n0 + tx];
    __syncthreads();
    #pragma unroll
    for (int i = 0; i < 4; i++) {
        float v = t[tx][ty+8*i];
        hi[(size_t)(n0+ty+8*i)*K + k0 + tx] = __float2half(v);
    }
}

__global__ void bcat_k(const float* __restrict__ b0, const float* __restrict__ b1,
                       const float* __restrict__ b2, const float* __restrict__ b3,
                       const float* __restrict__ b4, float* __restrict__ dst) {
    int i = blockIdx.x*256 + threadIdx.x;
    if (i >= QS) return;
    int seg = i / DD, off = i - seg*DD;
    const float* src = (seg == 0) ? b0 : (seg == 1) ? b1 : (seg == 2) ? b2 : (seg == 3) ? b3 : b4;
    dst[i] = src[off];
}

// ---------------- tensor-core GEMM: cp.async 4-stage, fp16 2-pass compensated ----
#define SPAD 40
#define STG_BYTES (128*SPAD*2)
#define SMEM_GEMM (8*STG_BYTES)

template<int GELU>
__global__ void __launch_bounds__(256) tgemm_k(
        const __half* __restrict__ Ahi, const __half* __restrict__ Alo,
        const __half* __restrict__ B,
        const float* __restrict__ bias, float* __restrict__ C,
        __half* __restrict__ Chi, __half* __restrict__ Clo,
        int M, int N, int K) {
    extern __shared__ char smem[];
    const uint32_t sm0 = smem_u32(smem);
    const int bn = blockIdx.x << 7, bm = blockIdx.y << 7;
    const int tid = threadIdx.x, wid = tid >> 5, lane = tid & 31;
    const int wm = (wid >> 2) << 6;
    const int wn = (wid & 3) << 5;

    float acc[4][4][4];
    #pragma unroll
    for (int i = 0; i < 4; i++)
        #pragma unroll
        for (int j = 0; j < 4; j++)
            #pragma unroll
            for (int r = 0; r < 4; r++) acc[i][j][r] = 0.f;

    const int KC = K >> 5;
    const int total = 2 * KC;
    const __half* Aps[2] = {Ahi, Alo};

    const int r0 = tid >> 2, c0 = (tid & 3) << 3;
    const int r1 = r0 + 64;
    const uint32_t dA0 = (uint32_t)((r0*SPAD + c0) << 1);
    const uint32_t dA1 = (uint32_t)((r1*SPAD + c0) << 1);

    const int lrow = lane & 15, lcol = (lane >> 4) << 3;
    const uint32_t offA = (uint32_t)(((wm + lrow) * SPAD + lcol) << 1);
    const uint32_t offB = (uint32_t)(((wn + lrow) * SPAD + lcol) << 1) + 4*STG_BYTES;

    #pragma unroll
    for (int p = 0; p < 3; p++) {
        const int pass = (p < KC) ? 0 : 1;
        const int kc = p - pass*KC;
        const __half* Ap = Aps[pass];
        const int kb = kc << 5;
        const uint32_t sa = sm0 + p*STG_BYTES;
        const uint32_t sb = sm0 + 4*STG_BYTES + p*STG_BYTES;
        cp16(sa + dA0, Ap + (size_t)(bm + r0)*K + kb + c0);
        cp16(sa + dA1, Ap + (size_t)(bm + r1)*K + kb + c0);
        cp16(sb + dA0, B + (size_t)(bn + r0)*K + kb + c0);
        cp16(sb + dA1, B + (size_t)(bn + r1)*K + kb + c0);
        CP_COMMIT();
    }

    for (int s = 0; s < total; s++) {
        CP_WAIT2();
        __syncthreads();
        const int p = s + 3;
        if (p < total) {
            const int pass = (p < KC) ? 0 : 1;
            const int kc = p - pass*KC;
            const __half* Ap = Aps[pass];
            const int kb = kc << 5;
            const int st2 = p & 3;
            const uint32_t sa = sm0 + st2*STG_BYTES;
            const uint32_t sb = sm0 + 4*STG_BYTES + st2*STG_BYTES;
            cp16(sa + dA0, Ap + (size_t)(bm + r0)*K + kb + c0);
            cp16(sa + dA1, Ap + (size_t)(bm + r1)*K + kb + c0);
            cp16(sb + dA0, B + (size_t)(bn + r0)*K + kb + c0);
            cp16(sb + dA1, B + (size_t)(bn + r1)*K + kb + c0);
        }
        CP_COMMIT();
        const int stg = s & 3;
        const uint32_t abase = sm0 + stg*STG_BYTES + offA;
        const uint32_t bbase = sm0 + stg*STG_BYTES + offB;
        #pragma unroll
        for (int ks = 0; ks < 2; ks++) {
            uint32_t af[4][4], bf[4][2];
            #pragma unroll
            for (int mt = 0; mt < 4; mt++)
                ldmat4(af[mt][0], af[mt][1], af[mt][2], af[mt][3],
                       abase + (uint32_t)(((mt << 4) * SPAD + (ks << 4)) << 1));
            #pragma unroll
            for (int np = 0; np < 2; np++) {
                uint32_t m0, m1, m2, m3;
                ldmat4(m0, m1, m2, m3,
                       bbase + (uint32_t)(((np << 4) * SPAD + (ks << 4)) << 1));
                bf[2*np][0] = m0; bf[2*np+1][0] = m1;
                bf[2*np][1] = m2; bf[2*np+1][1] = m3;
            }
            #pragma unroll
            for (int mt = 0; mt < 4; mt++)
                #pragma unroll
                for (int nt = 0; nt < 4; nt++)
                    mma16816(acc[mt][nt], af[mt], bf[nt]);
        }
    }

    const int mrow = lane >> 2, ncol = (lane & 3) << 1;
    #pragma unroll
    for (int mt = 0; mt < 4; mt++) {
        #pragma unroll
        for (int nt = 0; nt < 4; nt++) {
            int r = bm + wm + (mt << 4) + mrow;
            int c = bn + wn + (nt << 3) + ncol;
            float b0 = bias[c], b1 = bias[c+1];
            float v0 = acc[mt][nt][0] + b0, v1 = acc[mt][nt][1] + b1;
            float v2 = acc[mt][nt][2] + b0, v3 = acc[mt][nt][3] + b1;
            if (GELU) {
                v0 = gelu_f(v0); v1 = gelu_f(v1); v2 = gelu_f(v2); v3 = gelu_f(v3);
                __half h0 = __float2half(v0), h1 = __float2half(v1);
                __half h2 = __float2half(v2), h3 = __float2half(v3);
                *(__half2*)&Chi[(size_t)r*N + c]     = __halves2half2(h0, h1);
                *(__half2*)&Chi[(size_t)(r+8)*N + c] = __halves2half2(h2, h3);
                *(__half2*)&Clo[(size_t)r*N + c]     = __halves2half2(
                    __float2half(v0 - __half2float(h0)), __float2half(v1 - __half2float(h1)));
                *(__half2*)&Clo[(size_t)(r+8)*N + c] = __halves2half2(
                    __float2half(v2 - __half2float(h2)), __float2half(v3 - __half2float(h3)));
            } else {
                *(float2*)&C[(size_t)r*N + c]     = make_float2(v0, v1);
                *(float2*)&C[(size_t)(r+8)*N + c] = make_float2(v2, v3);
            }
        }
    }
}

// ---------------- band attention via mma (FA2-style, hi/lo compensated) ---------
// grid (SS/128, BH), 256 thr. Block: 128-query tile of window n=(qt>>1), r0=(qt&1)*128.
// Chunks of 64 keys: 10 band chunks (cstart..cstart+9) + global chunk (c==12).
#define QP 72
#define KP 72

__global__ void __launch_bounds__(256) band_mma_k(
        const __half* __restrict__ bqh, const __half* __restrict__ bql,
        const __half* __restrict__ bkh,
        const __half* __restrict__ bvh, const __half* __restrict__ bvl,
        const int* __restrict__ idxg, const unsigned char* __restrict__ klo,
        float* __restrict__ out) {
    __shared__ __half smh[2*128*QP];     // phase1: Qhi|Qlo; phase2: K|Vh|Vl|klo
    unsigned char* klos = (unsigned char*)(smh + 3*64*KP);
    const uint32_t smb = smem_u32(smh);
    const int qt = blockIdx.x, bh = blockIdx.y;
    const int b = bh / HH, h = bh % HH;
    const int n = qt >> 1, r0 = (qt & 1) << 7;
    const int tid = threadIdx.x, w = tid >> 5, lane = tid & 31;
    const int t0 = n*WW + r0;            // first query row (within batch)
    const int lrow = lane & 15, lcol = (lane >> 4) << 3;

    // stage Q hi/lo (128 x 64)
    #pragma unroll
    for (int t = 0; t < 4; t++) {
        int u = tid + (t << 8);
        int row = u >> 3, c8 = (u & 7) << 3;
        size_t src = (size_t)(b*SS + t0 + row)*DD + h*DHH + c8;
        *(uint4*)&smh[row*QP + c8]          = *(const uint4*)&bqh[src];
        *(uint4*)&smh[128*QP + row*QP + c8] = *(const uint4*)&bql[src];
    }
    __syncthreads();
    uint32_t afh[4][4], afl[4][4];
    #pragma unroll
    for (int ks = 0; ks < 4; ks++) {
        uint32_t a0 = smb + (uint32_t)(((w*16 + lrow)*QP + ks*16 + lcol) << 1);
        ldmat4(afh[ks][0], afh[ks][1], afh[ks][2], afh[ks][3], a0);
        ldmat4(afl[ks][0], afl[ks][1], afl[ks][2], afl[ks][3], a0 + (uint32_t)(128*QP*2));
    }

    float acco[8][4];
    #pragma unroll
    for (int nt = 0; nt < 8; nt++)
        #pragma unroll
        for (int r = 0; r < 4; r++) acco[nt][r] = 0.f;
    float m0 = -INFINITY, m1 = -INFINITY, l0 = 0.f, l1 = 0.f;
    const int qw0 = r0 + w*16 + (lane >> 2);    // row-in-window for row r
    const int cstart = (qt & 1) << 1;

    for (int cc = 0; cc <= 10; cc++) {
        const int c = (cc < 10) ? (cstart + cc) : 12;
        const int kpb = n*WW + (c << 6) - WW;
        __syncthreads();
        #pragma unroll
        for (int t = 0; t < 2; t++) {
            int u = tid + (t << 8);
            int row = u >> 3, c8 = (u & 7) << 3;
            int gk; bool valid;
            if (c == 12) { gk = idxg[b*GG + row]; valid = true; }
            else { gk = kpb + row; valid = (gk >= 0) && (gk < SS); }
            uint4 z = make_uint4(0,0,0,0);
            size_t src = (size_t)(b*SS + gk)*DD + h*DHH + c8;
            *(uint4*)&smh[row*KP + c8]          = valid ? *(const uint4*)&bkh[src] : z;
            *(uint4*)&smh[64*KP + row*KP + c8]  = valid ? *(const uint4*)&bvh[src] : z;
            *(uint4*)&smh[128*KP + row*KP + c8] = valid ? *(const uint4*)&bvl[src] : z;
            if (c8 == 0) klos[row] = (c != 12 && valid) ? klo[b*SS + gk] : 0;
        }
        __syncthreads();

        // scores: 2-pass (Qhi,Qlo) x Khi
        float accs[8][4];
        #pragma unroll
        for (int nt = 0; nt < 8; nt++)
            #pragma unroll
            for (int r = 0; r < 4; r++) accs[nt][r] = 0.f;
        #pragma unroll
        for (int ks = 0; ks < 4; ks++) {
            uint32_t bf[8][2];
            #pragma unroll
            for (int np = 0; np < 4; np++) {
                uint32_t q0, q1, q2, q3;
                ldmat4(q0, q1, q2, q3,
                       smb + (uint32_t)(((np*16 + lrow)*KP + ks*16 + lcol) << 1));
                bf[2*np][0] = q0; bf[2*np+1][0] = q1;
                bf[2*np][1] = q2; bf[2*np+1][1] = q3;
            }
            #pragma unroll
            for (int nt = 0; nt < 8; nt++) mma16816(accs[nt], afh[ks], bf[nt]);
            #pragma unroll
            for (int nt = 0; nt < 8; nt++) mma16816(accs[nt], afl[ks], bf[nt]);
        }
        // scale + mask
        float cm0 = -3.4e38f, cm1 = -3.4e38f;
        #pragma unroll
        for (int nt = 0; nt < 8; nt++) {
            int col0 = nt*8 + ((lane & 3) << 1);
            #pragma unroll
            for (int e = 0; e < 2; e++) {
                int col = col0 + e;
                float s0 = accs[nt][e]   * 0.125f;
                float s1 = accs[nt][2+e] * 0.125f;
                if (c != 12) {
                    int gk = kpb + col;
                    bool okc = (gk >= 0) && (gk < SS) && klos[col];
                    int j = (c << 6) + col;
                    if (!(okc && j >= qw0     && j <= qw0 + 512))     s0 = NEGV;
                    if (!(okc && j >= qw0 + 8 && j <= qw0 + 8 + 512)) s1 = NEGV;
                }
                accs[nt][e] = s0; accs[nt][2+e] = s1;
                cm0 = fmaxf(cm0, s0); cm1 = fmaxf(cm1, s1);
            }
        }
        cm0 = fmaxf(cm0, __shfl_xor_sync(0xffffffffu, cm0, 1));
        cm0 = fmaxf(cm0, __shfl_xor_sync(0xffffffffu, cm0, 2));
        cm1 = fmaxf(cm1, __shfl_xor_sync(0xffffffffu, cm1, 1));
        cm1 = fmaxf(cm1, __shfl_xor_sync(0xffffffffu, cm1, 2));
        float mn0 = fmaxf(m0, cm0), mn1 = fmaxf(m1, cm1);
        float rs0 = __expf(m0 - mn0), rs1 = __expf(m1 - mn1);
        uint32_t pfu[4][4];
        float ls0 = 0.f, ls1 = 0.f;
        #pragma unroll
        for (int t = 0; t < 4; t++) {
            int nA = 2*t, nB = 2*t + 1;
            float e00 = __expf(accs[nA][0] - mn0), e01 = __expf(accs[nA][1] - mn0);
            float e10 = __expf(accs[nA][2] - mn1), e11 = __expf(accs[nA][3] - mn1);
            float f00 = __expf(accs[nB][0] - mn0), f01 = __expf(accs[nB][1] - mn0);
            float f10 = __expf(accs[nB][2] - mn1), f11 = __expf(accs[nB][3] - mn1);
            ls0 += e00 + e01 + f00 + f01;
            ls1 += e10 + e11 + f10 + f11;
            pfu[t][0] = packh2(e00, e01);
            pfu[t][1] = packh2(e10, e11);
            pfu[t][2] = packh2(f00, f01);
            pfu[t][3] = packh2(f10, f11);
        }
        ls0 += __shfl_xor_sync(0xffffffffu, ls0, 1);
        ls0 += __shfl_xor_sync(0xffffffffu, ls0, 2);
        ls1 += __shfl_xor_sync(0xffffffffu, ls1, 1);
        ls1 += __shfl_xor_sync(0xffffffffu, ls1, 2);
        l0 = l0*rs0 + ls0; l1 = l1*rs1 + ls1;
        m0 = mn0; m1 = mn1;
        #pragma unroll
        for (int nt = 0; nt < 8; nt++) {
            acco[nt][0] *= rs0; acco[nt][1] *= rs0;
            acco[nt][2] *= rs1; acco[nt][3] *= rs1;
        }
        // PV: P(fp16) x (Vhi + Vlo) via ldmatrix.trans
        #pragma unroll
        for (int ks = 0; ks < 4; ks++) {
            uint32_t bv[8][2], bw[8][2];
            #pragma unroll
            for (int dt = 0; dt < 4; dt++) {
                uint32_t q0, q1, q2, q3;
                uint32_t ad = smb + (uint32_t)((64*KP + (ks*16 + lrow)*KP + dt*16 + lcol) << 1);
                ldmat4t(q0, q1, q2, q3, ad);
                bv[2*dt][0] = q0; bv[2*dt][1] = q1;
                bv[2*dt+1][0] = q2; bv[2*dt+1][1] = q3;
                ldmat4t(q0, q1, q2, q3, ad + (uint32_t)(64*KP*2));
                bw[2*dt][0] = q0; bw[2*dt][1] = q1;
                bw[2*dt+1][0] = q2; bw[2*dt+1][1] = q3;
            }
            #pragma unroll
            for (int nt = 0; nt < 8; nt++) mma16816(acco[nt], pfu[ks], bv[nt]);
            #pragma unroll
            for (int nt = 0; nt < 8; nt++) mma16816(acco[nt], pfu[ks], bw[nt]);
        }
    }
    float i0 = 1.f / l0, i1 = 1.f / l1;
    int grow = b*SS + t0 + w*16 + (lane >> 2);
    #pragma unroll
    for (int nt = 0; nt < 8; nt++) {
        int col = h*DHH + nt*8 + ((lane & 3) << 1);
        *(float2*)&out[(size_t)grow*DD + col]     = make_float2(acco[nt][0]*i0, acco[nt][1]*i0);
        *(float2*)&out[(size_t)(grow+8)*DD + col] = make_float2(acco[nt][2]*i1, acco[nt][3]*i1);
    }
}

// ---------------- global attention: segmented partials ----------------
#define KSP 68
#define SMEM_GLOB ((2*128*KSP + 64*132) * 4)

__global__ void __launch_bounds__(256, 1) glob_part_k(
        const float* __restrict__ qg, const float* __restrict__ qkv,
        const int* __restrict__ am, float* __restrict__ pacc, float* __restrict__ pml) {
    extern __shared__ float sm[];
    float* Ks = sm;
    float* Vs = sm + 128*KSP;
    float* ps = sm + 2*128*KSP;
    int seg = blockIdx.x;
    int bh = blockIdx.y, b = bh / HH, h = bh % HH;
    int tid = threadIdx.x;
    int g = tid >> 2, part = tid & 3;

    float qv[64];
    const float4* qp = (const float4*)(qg + (size_t)(b*GG+g)*DD + h*DHH);
    #pragma unroll
    for (int d4 = 0; d4 < 16; d4++) {
        float4 t = qp[d4];
        qv[4*d4] = t.x; qv[4*d4+1] = t.y; qv[4*d4+2] = t.z; qv[4*d4+3] = t.w;
    }
    float acc[16];
    #pragma unroll
    for (int i = 0; i < 16; i++) acc[i] = 0.f;
    float mrow = -INFINITY, lrow = 0.f;

    for (int c = 0; c < SEGS/128; c++) {
        int s0 = seg*SEGS + c*128;
        __syncthreads();
        #pragma unroll
        for (int t = 0; t < 8; t++) {
            int idx = tid + (t << 8);
            int row = idx >> 4, c4 = idx & 15;
            const float* src = qkv + (size_t)(b*SS + s0 + row)*QS + h*DHH + (c4 << 2);
            *(float4*)&Ks[row*KSP + (c4 << 2)] = *(const float4*)(src + 3*DD);
            *(float4*)&Vs[row*KSP + (c4 << 2)] = *(const float4*)(src + 4*DD);
        }
        __syncthreads();
        float es[32];
        float cmax = -INFINITY;
        #pragma unroll 4
        for (int i = 0; i < 32; i++) {
            int kk = (i << 2) + part;
            const float4* kr = (const float4*)(Ks + kk*KSP);
            float dot = 0.f;
            #pragma unroll
            for (int d4 = 0; d4 < 16; d4++) {
                float4 kv = kr[d4];
                dot += qv[4*d4]*kv.x + qv[4*d4+1]*kv.y + qv[4*d4+2]*kv.z + qv[4*d4+3]*kv.w;
            }
            float val = (am[b*SS + s0 + kk] != 0) ? dot*0.125f : NEGV;
            es[i] = val; cmax = fmaxf(cmax, val);
        }
        cmax = fmaxf(cmax, __shfl_xor_sync(0xffffffffu, cmax, 1));
        cmax = fmaxf(cmax, __shfl_xor_sync(0xffffffffu, cmax, 2));
        float mnew = fmaxf(mrow, cmax);
        float rs = __expf(mrow - mnew);
        float lsum = 0.f;
        #pragma unroll 4
        for (int i = 0; i < 32; i++) {
            float e = __expf(es[i] - mnew);
            ps[g*132 + (i << 2) + part] = e;
            lsum += e;
        }
        lsum += __shfl_xor_sync(0xffffffffu, lsum, 1);
        lsum += __shfl_xor_sync(0xffffffffu, lsum, 2);
        lrow = lrow*rs + lsum;
        #pragma unroll
        for (int i = 0; i < 16; i++) acc[i] *= rs;
        mrow = mnew;
        __syncthreads();
        for (int kk = 0; kk < 128; kk++) {
            float e = ps[g*132 + kk];
            const float4* vr = (const float4*)(Vs + kk*KSP + (part << 4));
            #pragma unroll
            for (int i4 = 0; i4 < 4; i4++) {
                float4 vv = vr[i4];
                acc[4*i4]   += e*vv.x; acc[4*i4+1] += e*vv.y;
                acc[4*i4+2] += e*vv.z; acc[4*i4+3] += e*vv.w;
            }
        }
    }
    size_t pb = ((size_t)(seg*BH + bh)*GG + g);
    float4* pa = (float4*)(pacc + pb*64 + (part << 4));
    #pragma unroll
    for (int i4 = 0; i4 < 4; i4++)
        pa[i4] = make_float4(acc[4*i4], acc[4*i4+1], acc[4*i4+2], acc[4*i4+3]);
    if (part == 0) { pml[pb*2] = mrow; pml[pb*2+1] = lrow; }
}

__global__ void glob_comb_k(const float* __restrict__ pacc, const float* __restrict__ pml,
                            float* __restrict__ og) {
    int bh = blockIdx.x, b = bh / HH, h = bh % HH;
    int tid = threadIdx.x;
    int g = tid >> 2, part = tid & 3;
    float ms[NSEG], ls[NSEG];
    float M = -INFINITY;
    #pragma unroll
    for (int s = 0; s < NSEG; s++) {
        size_t pb = ((size_t)(s*BH + bh)*GG + g);
        ms[s] = pml[pb*2]; ls[s] = pml[pb*2+1];
        M = fmaxf(M, ms[s]);
    }
    float L = 0.f;
    float acc[16];
    #pragma unroll
    for (int i = 0; i < 16; i++) acc[i] = 0.f;
    #pragma unroll
    for (int s = 0; s < NSEG; s++) {
        float wgt = __expf(ms[s] - M);
        L += ls[s]*wgt;
        size_t pb = ((size_t)(s*BH + bh)*GG + g);
        const float4* pa = (const float4*)(pacc + pb*64 + (part << 4));
        #pragma unroll
        for (int i4 = 0; i4 < 4; i4++) {
            float4 v = pa[i4];
            acc[4*i4]   += wgt*v.x; acc[4*i4+1] += wgt*v.y;
            acc[4*i4+2] += wgt*v.z; acc[4*i4+3] += wgt*v.w;
        }
    }
    float inv = 1.f / L;
    float4* op = (float4*)(og + (size_t)(b*GG+g)*DD + h*DHH + (part << 4));
    #pragma unroll
    for (int i4 = 0; i4 < 4; i4++)
        op[i4] = make_float4(acc[4*i4]*inv, acc[4*i4+1]*inv, acc[4*i4+2]*inv, acc[4*i4+3]*inv);
}

// ---------------- gather / scatter ----------------
__global__ void gather_k(const float* __restrict__ x, const int* __restrict__ idxg,
                         float* __restrict__ xg) {
    int r = blockIdx.x;
    int b = r / GG;
    int src = idxg[r];
    for (int d = threadIdx.x; d < DD; d += blockDim.x)
        xg[(size_t)r*DD + d] = x[((size_t)(b*SS+src))*DD + d];
}

__global__ void scatter_k(const float* __restrict__ og, const int* __restrict__ idxg,
                          float* __restrict__ out) {
    int r = blockIdx.x;
    int b = r / GG;
    int dst = idxg[r];
    for (int d = threadIdx.x; d < DD; d += blockDim.x)
        out[((size_t)(b*SS+dst))*DD + d] = og[(size_t)r*DD + d];
}

// ---------------- classifier ----------------
__global__ void classify_k(const float* __restrict__ x, const float* __restrict__ Wc,
                           const float* __restrict__ bc, const int* __restrict__ lo_p,
                           const int* __restrict__ ro_p, float* __restrict__ out, int nrows) {
    int r = blockIdx.x;
    int lo = *lo_p, ro = *ro_p;
    int per_b = 63 - lo - ro;
    if (per_b <= 0) per_b = 1;
    int b = r / per_b, t = lo + (r - b*per_b);
    const float* row = x + ((size_t)(b*SS + t))*DD;
    float p[7];
    #pragma unroll
    for (int c = 0; c < 7; c++) p[c] = 0.f;
    for (int d = threadIdx.x; d < DD; d += 256) {
        float xv = row[d];
        #pragma unroll
        for (int c = 0; c < 7; c++) p[c] += xv * Wc[d*7 + c];
    }
    #pragma unroll
    for (int c = 0; c < 7; c++) {
        float tot = blk_sum(p[c]);
        if (threadIdx.x == 0) out[r*7 + c] = tot + bc[c];
    }
}

// ---------------- launch ----------------
extern "C" void kernel_launch(void* const* d_in, const int* in_sizes, int n_in,
                              void* d_out, int out_size) {
    const float* emb_tok = (const float*)d_in[0];
    const float* emb_pos = (const float*)d_in[1];
    const float* ln_e_s  = (const float*)d_in[2];
    const float* ln_e_b  = (const float*)d_in[3];
    const float* Wq  = (const float*)d_in[4];
    const float* bq  = (const float*)d_in[5];
    const float* Wk  = (const float*)d_in[6];
    const float* bk  = (const float*)d_in[7];
    const float* Wv  = (const float*)d_in[8];
    const float* bv  = (const float*)d_in[9];
    const float* Wqg = (const float*)d_in[10];
    const float* bqg = (const float*)d_in[11];
    const float* Wkg = (const float*)d_in[12];
    const float* bkg = (const float*)d_in[13];
    const float* Wvg = (const float*)d_in[14];
    const float* bvg = (const float*)d_in[15];
    const float* Wo  = (const float*)d_in[16];
    const float* bo  = (const float*)d_in[17];
    const float* ln1_s = (const float*)d_in[18];
    const float* ln1_b = (const float*)d_in[19];
    const float* Wf1 = (const float*)d_in[20];
    const float* bf1 = (const float*)d_in[21];
    const float* Wf2 = (const float*)d_in[22];
    const float* bf2 = (const float*)d_in[23];
    const float* ln2_s = (const float*)d_in[24];
    const float* ln2_b = (const float*)d_in[25];
    const float* Wc  = (const float*)d_in[26];
    const float* bc  = (const float*)d_in[27];
    const int* input_ids = (const int*)d_in[28];
    const int* attn_mask = (const int*)d_in[29];
    const int* lo_p = (const int*)d_in[30];
    const int* ro_p = (const int*)d_in[31];
    float* out = (float*)d_out;

    float *x, *qkv, *attn, *tmp, *xg, *qg, *og, *bcat, *pacc, *pml;
    int* idxg; unsigned char* klo;
    __half *w, *ahi, *alo, *xhi, *xlo, *xghi, *xglo;
    __half *bqh, *bql, *bkh, *bvh, *bvl;
    cudaGetSymbolAddress((void**)&x,    g_x);
    cudaGetSymbolAddress((void**)&qkv,  g_qkv);
    cudaGetSymbolAddress((void**)&attn, g_attn);
    cudaGetSymbolAddress((void**)&tmp,  g_tmp);
    cudaGetSymbolAddress((void**)&xg,   g_xg);
    cudaGetSymbolAddress((void**)&qg,   g_qg);
    cudaGetSymbolAddress((void**)&og,   g_og);
    cudaGetSymbolAddress((void**)&bcat, g_bcat);
    cudaGetSymbolAddress((void**)&pacc, g_pacc);
    cudaGetSymbolAddress((void**)&pml,  g_pml);
    cudaGetSymbolAddress((void**)&idxg, g_idxg);
    cudaGetSymbolAddress((void**)&klo,  g_klo);
    cudaGetSymbolAddress((void**)&w,    g_w);
    cudaGetSymbolAddress((void**)&ahi,  g_ahi);
    cudaGetSymbolAddress((void**)&alo,  g_alo);
    cudaGetSymbolAddress((void**)&xhi,  g_xhi);
    cudaGetSymbolAddress((void**)&xlo,  g_xlo);
    cudaGetSymbolAddress((void**)&xghi, g_xghi);
    cudaGetSymbolAddress((void**)&xglo, g_xglo);
    cudaGetSymbolAddress((void**)&bqh,  g_bqh);
    cudaGetSymbolAddress((void**)&bql,  g_bql);
    cudaGetSymbolAddress((void**)&bkh,  g_bkh);
    cudaGetSymbolAddress((void**)&bvh,  g_bvh);
    cudaGetSymbolAddress((void**)&bvl,  g_bvl);

    cudaFuncSetAttribute(tgemm_k<0>, cudaFuncAttributeMaxDynamicSharedMemorySize, SMEM_GEMM);
    cudaFuncSetAttribute(tgemm_k<1>, cudaFuncAttributeMaxDynamicSharedMemorySize, SMEM_GEMM);
    cudaFuncSetAttribute(glob_part_k, cudaFuncAttributeMaxDynamicSharedMemorySize, SMEM_GLOB);

    prep_k<<<BB, 256>>>(input_ids, attn_mask, idxg, klo);
    embed_ln_k<<<BS, 256>>>(input_ids, emb_tok, emb_pos, ln_e_s, ln_e_b, x, xhi, xlo);

    dim3 wb(32, 8);
    for (int l = 0; l < LL; l++) {
        size_t base = (size_t)l * LWOFF;
        wsplit_t_k<<<dim3(DD/32, DD/32), wb>>>(Wq  + (size_t)l*DD*DD, w+base+OFF_Q,  DD, DD);
        wsplit_t_k<<<dim3(DD/32, DD/32), wb>>>(Wk  + (size_t)l*DD*DD, w+base+OFF_K,  DD, DD);
        wsplit_t_k<<<dim3(DD/32, DD/32), wb>>>(Wv  + (size_t)l*DD*DD, w+base+OFF_V,  DD, DD);
        wsplit_t_k<<<dim3(DD/32, DD/32), wb>>>(Wkg + (size_t)l*DD*DD, w+base+OFF_KG, DD, DD);
        wsplit_t_k<<<dim3(DD/32, DD/32), wb>>>(Wvg + (size_t)l*DD*DD, w+base+OFF_VG, DD, DD);
        wsplit_t_k<<<dim3(DD/32, DD/32), wb>>>(Wqg + (size_t)l*DD*DD, w+base+OFF_QG, DD, DD);
        wsplit_t_k<<<dim3(DD/32, DD/32), wb>>>(Wo  + (size_t)l*DD*DD, w+base+OFF_O,  DD, DD);
        wsplit_t_k<<<dim3(FFN/32, DD/32), wb>>>(Wf1 + (size_t)l*DD*FFN, w+base+OFF_F1, DD, FFN);
        wsplit_t_k<<<dim3(DD/32, FFN/32), wb>>>(Wf2 + (size_t)l*FFN*DD, w+base+OFF_F2, FFN, DD);
        bcat_k<<<(QS+255)/256, 256>>>(bq + l*DD, bk + l*DD, bv + l*DD, bkg + l*DD, bvg + l*DD,
                                      bcat + l*QS);
    }

    dim3 gTqkv(QS/128, BS/128);
    dim3 gT(DD/128, BS/128);
    dim3 gT1(FFN/128, BS/128);
    dim3 gTqg(DD/128, 1);
    dim3 gBandM(SS/128, BH);
    dim3 gGlobP(NSEG, BH);
    const int nXD4 = BS*DD/4, nXG4 = BB*GG*DD/4;
    const int nQKV4 = BS*3*DD/4;

    for (int l = 0; l < LL; l++) {
        size_t base = (size_t)l * LWOFF;
        const float* bqg_l = bqg + l*DD;
        const float* bo_l  = bo  + l*DD;
        const float* bf1_l = bf1 + l*FFN; const float* bf2_l = bf2 + l*DD;

        tgemm_k<0><<<gTqkv, 256, SMEM_GEMM>>>(xhi, xlo, w+base+OFF_Q,
                                              bcat + l*QS, qkv, 0, 0, BS, QS, DD);
        qkvsplit_k<<<(nQKV4+255)/256, 256>>>(qkv, bqh, bql, bkh, bvh, bvl);

        gather_k<<<BB*GG, 256>>>(x, idxg, xg);
        asplit_k<<<(nXG4+255)/256, 256>>>((const float4*)xg, (__half2*)xghi, (__half2*)xglo, nXG4);
        tgemm_k<0><<<gTqg, 256, SMEM_GEMM>>>(xghi, xglo, w+base+OFF_QG,
                                             bqg_l, qg, 0, 0, BB*GG, DD, DD);

        band_mma_k<<<gBandM, 256>>>(bqh, bql, bkh, bvh, bvl, idxg, klo, attn);

        glob_part_k<<<gGlobP, 256, SMEM_GLOB>>>(qg, qkv, attn_mask, pacc, pml);
        glob_comb_k<<<BH, 256>>>(pacc, pml, og);
        scatter_k<<<BB*GG, 256>>>(og, idxg, attn);

        asplit_k<<<(nXD4+255)/256, 256>>>((const float4*)attn, (__half2*)xhi, (__half2*)xlo, nXD4);
        tgemm_k<0><<<gT, 256, SMEM_GEMM>>>(xhi, xlo, w+base+OFF_O,
                                           bo_l, tmp, 0, 0, BS, DD, DD);
        add_ln_k<<<BS, 256>>>(x, tmp, ln1_s + l*DD, ln1_b + l*DD, xhi, xlo);

        tgemm_k<1><<<gT1, 256, SMEM_GEMM>>>(xhi, xlo, w+base+OFF_F1,
                                            bf1_l, 0, ahi, alo, BS, FFN, DD);
        tgemm_k<0><<<gT, 256, SMEM_GEMM>>>(ahi, alo, w+base+OFF_F2,
                                           bf2_l, tmp, 0, 0, BS, DD, FFN);
        add_ln_k<<<BS, 256>>>(x, tmp, ln2_s + l*DD, ln2_b + l*DD, xhi, xlo);
    }

    int nrows = out_size / 7;
    classify_k<<<nrows, 256>>>(x, Wc, bc, lo_p, ro_p, out, nrows);
}

// round 9
// speedup vs baseline: 4.0818x; 1.0689x over previous
#include <cuda_runtime.h>
#include <cuda_fp16.h>
#include <cstdint>
#include <math.h>

#define BB 2
#define SS 4096
#define DD 768
#define HH 12
#define LL 2
#define DHH 64
#define WW 256
#define GG 64
#define FFN 3072
#define SEPID 2
#define NEGV -1000000000.0f
#define BS (BB*SS)
#define QS (5*DD)
#define NSEG 8
#define SEGS (SS/NSEG)
#define BH (BB*HH)

#define WSZ_DD (DD*DD)
#define OFF_Q  0
#define OFF_K  (1*WSZ_DD)
#define OFF_V  (2*WSZ_DD)
#define OFF_KG (3*WSZ_DD)
#define OFF_VG (4*WSZ_DD)
#define OFF_QG (5*WSZ_DD)
#define OFF_O  (6*WSZ_DD)
#define OFF_F1 (7*WSZ_DD)
#define OFF_F2 (7*WSZ_DD + DD*FFN)
#define LWOFF  (7*WSZ_DD + 2*DD*FFN)

// ---------------- scratch ----------------
__device__ float g_x[BS*DD];
__device__ float g_qkv[(size_t)BS*QS];
__device__ float g_tmp[BS*DD];
__device__ float g_qg[BB*GG*DD];
__device__ float g_og[BB*GG*DD];
__device__ float g_bcat[2*QS];
__device__ float g_pacc[NSEG*BH*GG*64];
__device__ float g_pml[NSEG*BH*GG*2];
__device__ int   g_idxg[BB*GG];
__device__ unsigned char g_klo[BS];

__device__ __align__(16) __half g_w[2*LWOFF];
__device__ __align__(16) __half g_ahi[BS*FFN];
__device__ __align__(16) __half g_alo[BS*FFN];
__device__ __align__(16) __half g_xhi[BS*DD];
__device__ __align__(16) __half g_xlo[BS*DD];
__device__ __align__(16) __half g_xghi[BB*GG*DD];
__device__ __align__(16) __half g_xglo[BB*GG*DD];
// band attention fp16 operands
__device__ __align__(16) __half g_bqh[BS*DD];
__device__ __align__(16) __half g_bql[BS*DD];
__device__ __align__(16) __half g_bkh[BS*DD];
__device__ __align__(16) __half g_bvh[BS*DD];
__device__ __align__(16) __half g_bvl[BS*DD];

// ---------------- helpers ----------------
__device__ __forceinline__ uint32_t smem_u32(const void* p) {
    uint32_t a;
    asm("{ .reg .u64 t; cvta.to.shared.u64 t, %1; cvt.u32.u64 %0, t; }" : "=r"(a) : "l"(p));
    return a;
}

__device__ __forceinline__ void cp16(uint32_t dst, const void* src) {
    asm volatile("cp.async.ca.shared.global [%0], [%1], 16;" :: "r"(dst), "l"(src));
}
#define CP_COMMIT() asm volatile("cp.async.commit_group;" ::: "memory")
#define CP_WAIT2()  asm volatile("cp.async.wait_group 2;" ::: "memory")

__device__ __forceinline__ void ldmat4(uint32_t& r0, uint32_t& r1, uint32_t& r2, uint32_t& r3,
                                       uint32_t addr) {
    asm volatile("ldmatrix.sync.aligned.m8n8.x4.shared.b16 {%0,%1,%2,%3}, [%4];"
        : "=r"(r0), "=r"(r1), "=r"(r2), "=r"(r3) : "r"(addr));
}

__device__ __forceinline__ void ldmat4t(uint32_t& r0, uint32_t& r1, uint32_t& r2, uint32_t& r3,
                                        uint32_t addr) {
    asm volatile("ldmatrix.sync.aligned.m8n8.x4.trans.shared.b16 {%0,%1,%2,%3}, [%4];"
        : "=r"(r0), "=r"(r1), "=r"(r2), "=r"(r3) : "r"(addr));
}

__device__ __forceinline__ void mma16816(float* d, const uint32_t* a, const uint32_t* b) {
    asm volatile("mma.sync.aligned.m16n8k16.row.col.f32.f16.f16.f32 "
        "{%0,%1,%2,%3}, {%4,%5,%6,%7}, {%8,%9}, {%0,%1,%2,%3};"
        : "+f"(d[0]), "+f"(d[1]), "+f"(d[2]), "+f"(d[3])
        : "r"(a[0]), "r"(a[1]), "r"(a[2]), "r"(a[3]), "r"(b[0]), "r"(b[1]));
}

__device__ __forceinline__ uint32_t packh2(float a, float b) {
    __half2 h = __floats2half2_rn(a, b);
    return *(uint32_t*)&h;
}

__device__ __forceinline__ float gelu_f(float v) {
    return 0.5f*v*(1.f + tanhf(0.7978845608028654f*(v + 0.044715f*v*v*v)));
}

// ---------------- block reductions ----------------
__device__ __forceinline__ float blk_sum(float v) {
    __shared__ float sm[33];
    int lane = threadIdx.x & 31, wid = threadIdx.x >> 5;
    #pragma unroll
    for (int o = 16; o; o >>= 1) v += __shfl_xor_sync(0xffffffffu, v, o);
    if (lane == 0) sm[wid] = v;
    __syncthreads();
    if (wid == 0) {
        int nw = (blockDim.x + 31) >> 5;
        float r = (lane < nw) ? sm[lane] : 0.f;
        #pragma unroll
        for (int o = 16; o; o >>= 1) r += __shfl_xor_sync(0xffffffffu, r, o);
        if (lane == 0) sm[32] = r;
    }
    __syncthreads();
    float r = sm[32];
    __syncthreads();
    return r;
}

// ---------------- prep ----------------
__global__ void prep_k(const int* __restrict__ ids, const int* __restrict__ am,
                       int* __restrict__ idxg, unsigned char* __restrict__ klo) {
    int b = blockIdx.x;
    for (int s = threadIdx.x; s < SS; s += blockDim.x) {
        bool g = (ids[b*SS+s] == SEPID) || (s == 0);
        klo[b*SS+s] = (am[b*SS+s] != 0 && !g) ? 1 : 0;
    }
    if (threadIdx.x == 0) {
        int cnt = 0;
        for (int s = 0; s < SS && cnt < GG; s++)
            if (ids[b*SS+s] == SEPID || s == 0) idxg[b*GG + cnt++] = s;
        for (; cnt < GG; cnt++) idxg[b*GG + cnt] = 0;
    }
}

// ---------------- embedding + LN ----------------
__global__ void embed_ln_k(const int* __restrict__ ids, const float* __restrict__ etok,
                           const float* __restrict__ epos, const float* __restrict__ lns,
                           const float* __restrict__ lnb, float* __restrict__ x,
                           __half* __restrict__ xhi, __half* __restrict__ xlo) {
    int row = blockIdx.x;
    int spos = row & (SS - 1);
    int id = ids[row];
    const float* te = etok + (size_t)id * DD;
    const float* pe = epos + (size_t)spos * DD;
    float v[3]; float sum = 0.f;
    #pragma unroll
    for (int i = 0; i < 3; i++) {
        int d = threadIdx.x + i*256;
        float val = te[d] + pe[d];
        v[i] = val; sum += val;
    }
    float mean = blk_sum(sum) * (1.0f/DD);
    float sq = 0.f;
    #pragma unroll
    for (int i = 0; i < 3; i++) { float c = v[i] - mean; sq += c*c; }
    float inv = rsqrtf(blk_sum(sq) * (1.0f/DD) + 1e-5f);
    #pragma unroll
    for (int i = 0; i < 3; i++) {
        int d = threadIdx.x + i*256;
        float o = (v[i] - mean)*inv*lns[d] + lnb[d];
        x[(size_t)row*DD + d] = o;
        __half h = __float2half(o);
        xhi[(size_t)row*DD + d] = h;
        xlo[(size_t)row*DD + d] = __float2half(o - __half2float(h));
    }
}

// ---------------- residual add + LN ----------------
__global__ void add_ln_k(float* __restrict__ x, const float* __restrict__ t,
                         const float* __restrict__ lns, const float* __restrict__ lnb,
                         __half* __restrict__ xhi, __half* __restrict__ xlo) {
    int row = blockIdx.x;
    size_t base = (size_t)row * DD;
    float v[3]; float sum = 0.f;
    #pragma unroll
    for (int i = 0; i < 3; i++) {
        int d = threadIdx.x + i*256;
        float val = x[base+d] + t[base+d];
        v[i] = val; sum += val;
    }
    float mean = blk_sum(sum) * (1.0f/DD);
    float sq = 0.f;
    #pragma unroll
    for (int i = 0; i < 3; i++) { float c = v[i] - mean; sq += c*c; }
    float inv = rsqrtf(blk_sum(sq) * (1.0f/DD) + 1e-5f);
    #pragma unroll
    for (int i = 0; i < 3; i++) {
        int d = threadIdx.x + i*256;
        float o = (v[i] - mean)*inv*lns[d] + lnb[d];
        x[base+d] = o;
        __half h = __float2half(o);
        xhi[base+d] = h;
        xlo[base+d] = __float2half(o - __half2float(h));
    }
}

// ---------------- conversions ----------------
__global__ void wsplit_t_k(const float* __restrict__ W, __half* __restrict__ hi,
                           int K, int N) {
    __shared__ float t[32][33];
    int n0 = blockIdx.x*32, k0 = blockIdx.y*32;
    int tx = threadIdx.x, ty = threadIdx.y;
    #pragma unroll
    for (int i = 0; i < 4; i++)
        t[ty+8*i][tx] = W[(size_t)(k0+ty+8*i)*N + n0 + tx];
    __syncthreads();
    #pragma unroll
    for (int i = 0; i < 4; i++) {
        float v = t[tx][ty+8*i];
        hi[(size_t)(n0+ty+8*i)*K + k0 + tx] = __float2half(v);
    }
}

__global__ void bcat_k(const float* __restrict__ b0, const float* __restrict__ b1,
                       const float* __restrict__ b2, const float* __restrict__ b3,
                       const float* __restrict__ b4, float* __restrict__ dst) {
    int i = blockIdx.x*256 + threadIdx.x;
    if (i >= QS) return;
    int seg = i / DD, off = i - seg*DD;
    const float* src = (seg == 0) ? b0 : (seg == 1) ? b1 : (seg == 2) ? b2 : (seg == 3) ? b3 : b4;
    dst[i] = src[off];
}

// ---------------- tensor-core GEMM: cp.async 4-stage, fp16 2-pass compensated ----
// MODE 0: C fp32.  MODE 1: gelu -> Chi/Clo fp16.  MODE 2: QKV — segs 0..2 split to
// band fp16 buffers (device globals), segs 3..4 fp32 to C (stride N=QS).
#define SPAD 40
#define STG_BYTES (128*SPAD*2)
#define SMEM_GEMM (8*STG_BYTES)

template<int MODE>
__global__ void __launch_bounds__(256, 2) tgemm_k(
        const __half* __restrict__ Ahi, const __half* __restrict__ Alo,
        const __half* __restrict__ B,
        const float* __restrict__ bias, float* __restrict__ C,
        __half* __restrict__ Chi, __half* __restrict__ Clo,
        int M, int N, int K) {
    extern __shared__ char smem[];
    const uint32_t sm0 = smem_u32(smem);
    const int bn = blockIdx.x << 7, bm = blockIdx.y << 7;
    const int tid = threadIdx.x, wid = tid >> 5, lane = tid & 31;
    const int wm = (wid >> 2) << 6;
    const int wn = (wid & 3) << 5;

    float acc[4][4][4];
    #pragma unroll
    for (int i = 0; i < 4; i++)
        #pragma unroll
        for (int j = 0; j < 4; j++)
            #pragma unroll
            for (int r = 0; r < 4; r++) acc[i][j][r] = 0.f;

    const int KC = K >> 5;
    const int total = 2 * KC;
    const __half* Aps[2] = {Ahi, Alo};

    const int r0 = tid >> 2, c0 = (tid & 3) << 3;
    const int r1 = r0 + 64;
    const uint32_t dA0 = (uint32_t)((r0*SPAD + c0) << 1);
    const uint32_t dA1 = (uint32_t)((r1*SPAD + c0) << 1);

    const int lrow = lane & 15, lcol = (lane >> 4) << 3;
    const uint32_t offA = (uint32_t)(((wm + lrow) * SPAD + lcol) << 1);
    const uint32_t offB = (uint32_t)(((wn + lrow) * SPAD + lcol) << 1) + 4*STG_BYTES;

    #pragma unroll
    for (int p = 0; p < 3; p++) {
        const int pass = (p < KC) ? 0 : 1;
        const int kc = p - pass*KC;
        const __half* Ap = Aps[pass];
        const int kb = kc << 5;
        const uint32_t sa = sm0 + p*STG_BYTES;
        const uint32_t sb = sm0 + 4*STG_BYTES + p*STG_BYTES;
        cp16(sa + dA0, Ap + (size_t)(bm + r0)*K + kb + c0);
        cp16(sa + dA1, Ap + (size_t)(bm + r1)*K + kb + c0);
        cp16(sb + dA0, B + (size_t)(bn + r0)*K + kb + c0);
        cp16(sb + dA1, B + (size_t)(bn + r1)*K + kb + c0);
        CP_COMMIT();
    }

    for (int s = 0; s < total; s++) {
        CP_WAIT2();
        __syncthreads();
        const int p = s + 3;
        if (p < total) {
            const int pass = (p < KC) ? 0 : 1;
            const int kc = p - pass*KC;
            const __half* Ap = Aps[pass];
            const int kb = kc << 5;
            const int st2 = p & 3;
            const uint32_t sa = sm0 + st2*STG_BYTES;
            const uint32_t sb = sm0 + 4*STG_BYTES + st2*STG_BYTES;
            cp16(sa + dA0, Ap + (size_t)(bm + r0)*K + kb + c0);
            cp16(sa + dA1, Ap + (size_t)(bm + r1)*K + kb + c0);
            cp16(sb + dA0, B + (size_t)(bn + r0)*K + kb + c0);
            cp16(sb + dA1, B + (size_t)(bn + r1)*K + kb + c0);
        }
        CP_COMMIT();
        const int stg = s & 3;
        const uint32_t abase = sm0 + stg*STG_BYTES + offA;
        const uint32_t bbase = sm0 + stg*STG_BYTES + offB;
        #pragma unroll
        for (int ks = 0; ks < 2; ks++) {
            uint32_t af[4][4], bf[4][2];
            #pragma unroll
            for (int mt = 0; mt < 4; mt++)
                ldmat4(af[mt][0], af[mt][1], af[mt][2], af[mt][3],
                       abase + (uint32_t)(((mt << 4) * SPAD + (ks << 4)) << 1));
            #pragma unroll
            for (int np = 0; np < 2; np++) {
                uint32_t m0, m1, m2, m3;
                ldmat4(m0, m1, m2, m3,
                       bbase + (uint32_t)(((np << 4) * SPAD + (ks << 4)) << 1));
                bf[2*np][0] = m0; bf[2*np+1][0] = m1;
                bf[2*np][1] = m2; bf[2*np+1][1] = m3;
            }
            #pragma unroll
            for (int mt = 0; mt < 4; mt++)
                #pragma unroll
                for (int nt = 0; nt < 4; nt++)
                    mma16816(acc[mt][nt], af[mt], bf[nt]);
        }
    }

    const int mrow = lane >> 2, ncol = (lane & 3) << 1;
    const int seg = bn / DD;            // uniform per CTA (DD % 128 == 0)
    #pragma unroll
    for (int mt = 0; mt < 4; mt++) {
        #pragma unroll
        for (int nt = 0; nt < 4; nt++) {
            int r = bm + wm + (mt << 4) + mrow;
            int c = bn + wn + (nt << 3) + ncol;
            float b0 = bias[c], b1 = bias[c+1];
            float v0 = acc[mt][nt][0] + b0, v1 = acc[mt][nt][1] + b1;
            float v2 = acc[mt][nt][2] + b0, v3 = acc[mt][nt][3] + b1;
            if (MODE == 1) {
                v0 = gelu_f(v0); v1 = gelu_f(v1); v2 = gelu_f(v2); v3 = gelu_f(v3);
                __half h0 = __float2half(v0), h1 = __float2half(v1);
                __half h2 = __float2half(v2), h3 = __float2half(v3);
                *(__half2*)&Chi[(size_t)r*N + c]     = __halves2half2(h0, h1);
                *(__half2*)&Chi[(size_t)(r+8)*N + c] = __halves2half2(h2, h3);
                *(__half2*)&Clo[(size_t)r*N + c]     = __halves2half2(
                    __float2half(v0 - __half2float(h0)), __float2half(v1 - __half2float(h1)));
                *(__half2*)&Clo[(size_t)(r+8)*N + c] = __halves2half2(
                    __float2half(v2 - __half2float(h2)), __float2half(v3 - __half2float(h3)));
            } else if (MODE == 2) {
                if (seg <= 2) {
                    int cc = c - seg*DD;
                    size_t o0 = (size_t)r*DD + cc, o1 = (size_t)(r+8)*DD + cc;
                    __half h0 = __float2half(v0), h1 = __float2half(v1);
                    __half h2 = __float2half(v2), h3 = __float2half(v3);
                    __half2 hi0 = __halves2half2(h0, h1), hi1 = __halves2half2(h2, h3);
                    __half2 lo0 = __halves2half2(__float2half(v0 - __half2float(h0)),
                                                 __float2half(v1 - __half2float(h1)));
                    __half2 lo1 = __halves2half2(__float2half(v2 - __half2float(h2)),
                                                 __float2half(v3 - __half2float(h3)));
                    if (seg == 0) {
                        *(__half2*)&g_bqh[o0] = hi0; *(__half2*)&g_bqh[o1] = hi1;
                        *(__half2*)&g_bql[o0] = lo0; *(__half2*)&g_bql[o1] = lo1;
                    } else if (seg == 1) {
                        *(__half2*)&g_bkh[o0] = hi0; *(__half2*)&g_bkh[o1] = hi1;
                    } else {
                        *(__half2*)&g_bvh[o0] = hi0; *(__half2*)&g_bvh[o1] = hi1;
                        *(__half2*)&g_bvl[o0] = lo0; *(__half2*)&g_bvl[o1] = lo1;
                    }
                } else {
                    *(float2*)&C[(size_t)r*N + c]     = make_float2(v0, v1);
                    *(float2*)&C[(size_t)(r+8)*N + c] = make_float2(v2, v3);
                }
            } else {
                *(float2*)&C[(size_t)r*N + c]     = make_float2(v0, v1);
                *(float2*)&C[(size_t)(r+8)*N + c] = make_float2(v2, v3);
            }
        }
    }
}

// ---------------- band attention via mma (writes xhi/xlo split directly) --------
#define QP 72
#define KP 72

__global__ void __launch_bounds__(256) band_mma_k(
        const __half* __restrict__ bqh, const __half* __restrict__ bql,
        const __half* __restrict__ bkh,
        const __half* __restrict__ bvh, const __half* __restrict__ bvl,
        const int* __restrict__ idxg, const unsigned char* __restrict__ klo,
        __half* __restrict__ ohi, __half* __restrict__ olo) {
    __shared__ __half smh[2*128*QP];
    unsigned char* klos = (unsigned char*)(smh + 3*64*KP);
    const uint32_t smb = smem_u32(smh);
    const int qt = blockIdx.x, bh = blockIdx.y;
    const int b = bh / HH, h = bh % HH;
    const int n = qt >> 1, r0 = (qt & 1) << 7;
    const int tid = threadIdx.x, w = tid >> 5, lane = tid & 31;
    const int t0 = n*WW + r0;
    const int lrow = lane & 15, lcol = (lane >> 4) << 3;

    #pragma unroll
    for (int t = 0; t < 4; t++) {
        int u = tid + (t << 8);
        int row = u >> 3, c8 = (u & 7) << 3;
        size_t src = (size_t)(b*SS + t0 + row)*DD + h*DHH + c8;
        *(uint4*)&smh[row*QP + c8]          = *(const uint4*)&bqh[src];
        *(uint4*)&smh[128*QP + row*QP + c8] = *(const uint4*)&bql[src];
    }
    __syncthreads();
    uint32_t afh[4][4], afl[4][4];
    #pragma unroll
    for (int ks = 0; ks < 4; ks++) {
        uint32_t a0 = smb + (uint32_t)(((w*16 + lrow)*QP + ks*16 + lcol) << 1);
        ldmat4(afh[ks][0], afh[ks][1], afh[ks][2], afh[ks][3], a0);
        ldmat4(afl[ks][0], afl[ks][1], afl[ks][2], afl[ks][3], a0 + (uint32_t)(128*QP*2));
    }

    float acco[8][4];
    #pragma unroll
    for (int nt = 0; nt < 8; nt++)
        #pragma unroll
        for (int r = 0; r < 4; r++) acco[nt][r] = 0.f;
    float m0 = -INFINITY, m1 = -INFINITY, l0 = 0.f, l1 = 0.f;
    const int qw0 = r0 + w*16 + (lane >> 2);
    const int cstart = (qt & 1) << 1;

    for (int cc = 0; cc <= 10; cc++) {
        const int c = (cc < 10) ? (cstart + cc) : 12;
        const int kpb = n*WW + (c << 6) - WW;
        __syncthreads();
        #pragma unroll
        for (int t = 0; t < 2; t++) {
            int u = tid + (t << 8);
            int row = u >> 3, c8 = (u & 7) << 3;
            int gk; bool valid;
            if (c == 12) { gk = idxg[b*GG + row]; valid = true; }
            else { gk = kpb + row; valid = (gk >= 0) && (gk < SS); }
            uint4 z = make_uint4(0,0,0,0);
            size_t src = (size_t)(b*SS + gk)*DD + h*DHH + c8;
            *(uint4*)&smh[row*KP + c8]          = valid ? *(const uint4*)&bkh[src] : z;
            *(uint4*)&smh[64*KP + row*KP + c8]  = valid ? *(const uint4*)&bvh[src] : z;
            *(uint4*)&smh[128*KP + row*KP + c8] = valid ? *(const uint4*)&bvl[src] : z;
            if (c8 == 0) klos[row] = (c != 12 && valid) ? klo[b*SS + gk] : 0;
        }
        __syncthreads();

        float accs[8][4];
        #pragma unroll
        for (int nt = 0; nt < 8; nt++)
            #pragma unroll
            for (int r = 0; r < 4; r++) accs[nt][r] = 0.f;
        #pragma unroll
        for (int ks = 0; ks < 4; ks++) {
            uint32_t bf[8][2];
            #pragma unroll
            for (int np = 0; np < 4; np++) {
                uint32_t q0, q1, q2, q3;
                ldmat4(q0, q1, q2, q3,
                       smb + (uint32_t)(((np*16 + lrow)*KP + ks*16 + lcol) << 1));
                bf[2*np][0] = q0; bf[2*np+1][0] = q1;
                bf[2*np][1] = q2; bf[2*np+1][1] = q3;
            }
            #pragma unroll
            for (int nt = 0; nt < 8; nt++) mma16816(accs[nt], afh[ks], bf[nt]);
            #pragma unroll
            for (int nt = 0; nt < 8; nt++) mma16816(accs[nt], afl[ks], bf[nt]);
        }
        float cm0 = -3.4e38f, cm1 = -3.4e38f;
        #pragma unroll
        for (int nt = 0; nt < 8; nt++) {
            int col0 = nt*8 + ((lane & 3) << 1);
            #pragma unroll
            for (int e = 0; e < 2; e++) {
                int col = col0 + e;
                float s0 = accs[nt][e]   * 0.125f;
                float s1 = accs[nt][2+e] * 0.125f;
                if (c != 12) {
                    int gk = kpb + col;
                    bool okc = (gk >= 0) && (gk < SS) && klos[col];
                    int j = (c << 6) + col;
                    if (!(okc && j >= qw0     && j <= qw0 + 512))     s0 = NEGV;
                    if (!(okc && j >= qw0 + 8 && j <= qw0 + 8 + 512)) s1 = NEGV;
                }
                accs[nt][e] = s0; accs[nt][2+e] = s1;
                cm0 = fmaxf(cm0, s0); cm1 = fmaxf(cm1, s1);
            }
        }
        cm0 = fmaxf(cm0, __shfl_xor_sync(0xffffffffu, cm0, 1));
        cm0 = fmaxf(cm0, __shfl_xor_sync(0xffffffffu, cm0, 2));
        cm1 = fmaxf(cm1, __shfl_xor_sync(0xffffffffu, cm1, 1));
        cm1 = fmaxf(cm1, __shfl_xor_sync(0xffffffffu, cm1, 2));
        float mn0 = fmaxf(m0, cm0), mn1 = fmaxf(m1, cm1);
        float rs0 = __expf(m0 - mn0), rs1 = __expf(m1 - mn1);
        uint32_t pfu[4][4];
        float ls0 = 0.f, ls1 = 0.f;
        #pragma unroll
        for (int t = 0; t < 4; t++) {
            int nA = 2*t, nB = 2*t + 1;
            float e00 = __expf(accs[nA][0] - mn0), e01 = __expf(accs[nA][1] - mn0);
            float e10 = __expf(accs[nA][2] - mn1), e11 = __expf(accs[nA][3] - mn1);
            float f00 = __expf(accs[nB][0] - mn0), f01 = __expf(accs[nB][1] - mn0);
            float f10 = __expf(accs[nB][2] - mn1), f11 = __expf(accs[nB][3] - mn1);
            ls0 += e00 + e01 + f00 + f01;
            ls1 += e10 + e11 + f10 + f11;
            pfu[t][0] = packh2(e00, e01);
            pfu[t][1] = packh2(e10, e11);
            pfu[t][2] = packh2(f00, f01);
            pfu[t][3] = packh2(f10, f11);
        }
        ls0 += __shfl_xor_sync(0xffffffffu, ls0, 1);
        ls0 += __shfl_xor_sync(0xffffffffu, ls0, 2);
        ls1 += __shfl_xor_sync(0xffffffffu, ls1, 1);
        ls1 += __shfl_xor_sync(0xffffffffu, ls1, 2);
        l0 = l0*rs0 + ls0; l1 = l1*rs1 + ls1;
        m0 = mn0; m1 = mn1;
        #pragma unroll
        for (int nt = 0; nt < 8; nt++) {
            acco[nt][0] *= rs0; acco[nt][1] *= rs0;
            acco[nt][2] *= rs1; acco[nt][3] *= rs1;
        }
        #pragma unroll
        for (int ks = 0; ks < 4; ks++) {
            uint32_t bv[8][2], bw[8][2];
            #pragma unroll
            for (int dt = 0; dt < 4; dt++) {
                uint32_t q0, q1, q2, q3;
                uint32_t ad = smb + (uint32_t)((64*KP + (ks*16 + lrow)*KP + dt*16 + lcol) << 1);
                ldmat4t(q0, q1, q2, q3, ad);
                bv[2*dt][0] = q0; bv[2*dt][1] = q1;
                bv[2*dt+1][0] = q2; bv[2*dt+1][1] = q3;
                ldmat4t(q0, q1, q2, q3, ad + (uint32_t)(64*KP*2));
                bw[2*dt][0] = q0; bw[2*dt][1] = q1;
                bw[2*dt+1][0] = q2; bw[2*dt+1][1] = q3;
            }
            #pragma unroll
            for (int nt = 0; nt < 8; nt++) mma16816(acco[nt], pfu[ks], bv[nt]);
            #pragma unroll
            for (int nt = 0; nt < 8; nt++) mma16816(acco[nt], pfu[ks], bw[nt]);
        }
    }
    float i0 = 1.f / l0, i1 = 1.f / l1;
    int grow = b*SS + t0 + w*16 + (lane >> 2);
    #pragma unroll
    for (int nt = 0; nt < 8; nt++) {
        int col = h*DHH + nt*8 + ((lane & 3) << 1);
        float v0 = acco[nt][0]*i0, v1 = acco[nt][1]*i0;
        float v2 = acco[nt][2]*i1, v3 = acco[nt][3]*i1;
        __half h0 = __float2half(v0), h1 = __float2half(v1);
        __half h2 = __float2half(v2), h3 = __float2half(v3);
        *(__half2*)&ohi[(size_t)grow*DD + col]     = __halves2half2(h0, h1);
        *(__half2*)&ohi[(size_t)(grow+8)*DD + col] = __halves2half2(h2, h3);
        *(__half2*)&olo[(size_t)grow*DD + col]     = __halves2half2(
            __float2half(v0 - __half2float(h0)), __float2half(v1 - __half2float(h1)));
        *(__half2*)&olo[(size_t)(grow+8)*DD + col] = __halves2half2(
            __float2half(v2 - __half2float(h2)), __float2half(v3 - __half2float(h3)));
    }
}

// ---------------- global attention: segmented partials ----------------
#define KSP 68
#define SMEM_GLOB ((2*128*KSP + 64*132) * 4)

__global__ void __launch_bounds__(256, 1) glob_part_k(
        const float* __restrict__ qg, const float* __restrict__ qkv,
        const int* __restrict__ am, float* __restrict__ pacc, float* __restrict__ pml) {
    extern __shared__ float sm[];
    float* Ks = sm;
    float* Vs = sm + 128*KSP;
    float* ps = sm + 2*128*KSP;
    int seg = blockIdx.x;
    int bh = blockIdx.y, b = bh / HH, h = bh % HH;
    int tid = threadIdx.x;
    int g = tid >> 2, part = tid & 3;

    float qv[64];
    const float4* qp = (const float4*)(qg + (size_t)(b*GG+g)*DD + h*DHH);
    #pragma unroll
    for (int d4 = 0; d4 < 16; d4++) {
        float4 t = qp[d4];
        qv[4*d4] = t.x; qv[4*d4+1] = t.y; qv[4*d4+2] = t.z; qv[4*d4+3] = t.w;
    }
    float acc[16];
    #pragma unroll
    for (int i = 0; i < 16; i++) acc[i] = 0.f;
    float mrow = -INFINITY, lrow = 0.f;

    for (int c = 0; c < SEGS/128; c++) {
        int s0 = seg*SEGS + c*128;
        __syncthreads();
        #pragma unroll
        for (int t = 0; t < 8; t++) {
            int idx = tid + (t << 8);
            int row = idx >> 4, c4 = idx & 15;
            const float* src = qkv + (size_t)(b*SS + s0 + row)*QS + h*DHH + (c4 << 2);
            *(float4*)&Ks[row*KSP + (c4 << 2)] = *(const float4*)(src + 3*DD);
            *(float4*)&Vs[row*KSP + (c4 << 2)] = *(const float4*)(src + 4*DD);
        }
        __syncthreads();
        float es[32];
        float cmax = -INFINITY;
        #pragma unroll 4
        for (int i = 0; i < 32; i++) {
            int kk = (i << 2) + part;
            const float4* kr = (const float4*)(Ks + kk*KSP);
            float dot = 0.f;
            #pragma unroll
            for (int d4 = 0; d4 < 16; d4++) {
                float4 kv = kr[d4];
                dot += qv[4*d4]*kv.x + qv[4*d4+1]*kv.y + qv[4*d4+2]*kv.z + qv[4*d4+3]*kv.w;
            }
            float val = (am[b*SS + s0 + kk] != 0) ? dot*0.125f : NEGV;
            es[i] = val; cmax = fmaxf(cmax, val);
        }
        cmax = fmaxf(cmax, __shfl_xor_sync(0xffffffffu, cmax, 1));
        cmax = fmaxf(cmax, __shfl_xor_sync(0xffffffffu, cmax, 2));
        float mnew = fmaxf(mrow, cmax);
        float rs = __expf(mrow - mnew);
        float lsum = 0.f;
        #pragma unroll 4
        for (int i = 0; i < 32; i++) {
            float e = __expf(es[i] - mnew);
            ps[g*132 + (i << 2) + part] = e;
            lsum += e;
        }
        lsum += __shfl_xor_sync(0xffffffffu, lsum, 1);
        lsum += __shfl_xor_sync(0xffffffffu, lsum, 2);
        lrow = lrow*rs + lsum;
        #pragma unroll
        for (int i = 0; i < 16; i++) acc[i] *= rs;
        mrow = mnew;
        __syncthreads();
        for (int kk = 0; kk < 128; kk++) {
            float e = ps[g*132 + kk];
            const float4* vr = (const float4*)(Vs + kk*KSP + (part << 4));
            #pragma unroll
            for (int i4 = 0; i4 < 4; i4++) {
                float4 vv = vr[i4];
                acc[4*i4]   += e*vv.x; acc[4*i4+1] += e*vv.y;
                acc[4*i4+2] += e*vv.z; acc[4*i4+3] += e*vv.w;
            }
        }
    }
    size_t pb = ((size_t)(seg*BH + bh)*GG + g);
    float4* pa = (float4*)(pacc + pb*64 + (part << 4));
    #pragma unroll
    for (int i4 = 0; i4 < 4; i4++)
        pa[i4] = make_float4(acc[4*i4], acc[4*i4+1], acc[4*i4+2], acc[4*i4+3]);
    if (part == 0) { pml[pb*2] = mrow; pml[pb*2+1] = lrow; }
}

__global__ void glob_comb_k(const float* __restrict__ pacc, const float* __restrict__ pml,
                            float* __restrict__ og) {
    int bh = blockIdx.x, b = bh / HH, h = bh % HH;
    int tid = threadIdx.x;
    int g = tid >> 2, part = tid & 3;
    float ms[NSEG], ls[NSEG];
    float M = -INFINITY;
    #pragma unroll
    for (int s = 0; s < NSEG; s++) {
        size_t pb = ((size_t)(s*BH + bh)*GG + g);
        ms[s] = pml[pb*2]; ls[s] = pml[pb*2+1];
        M = fmaxf(M, ms[s]);
    }
    float L = 0.f;
    float acc[16];
    #pragma unroll
    for (int i = 0; i < 16; i++) acc[i] = 0.f;
    #pragma unroll
    for (int s = 0; s < NSEG; s++) {
        float wgt = __expf(ms[s] - M);
        L += ls[s]*wgt;
        size_t pb = ((size_t)(s*BH + bh)*GG + g);
        const float4* pa = (const float4*)(pacc + pb*64 + (part << 4));
        #pragma unroll
        for (int i4 = 0; i4 < 4; i4++) {
            float4 v = pa[i4];
            acc[4*i4]   += wgt*v.x; acc[4*i4+1] += wgt*v.y;
            acc[4*i4+2] += wgt*v.z; acc[4*i4+3] += wgt*v.w;
        }
    }
    float inv = 1.f / L;
    float4* op = (float4*)(og + (size_t)(b*GG+g)*DD + h*DHH + (part << 4));
    #pragma unroll
    for (int i4 = 0; i4 < 4; i4++)
        op[i4] = make_float4(acc[4*i4]*inv, acc[4*i4+1]*inv, acc[4*i4+2]*inv, acc[4*i4+3]*inv);
}

// ---------------- gather (split) / scatter (split) ----------------
__global__ void gather_split_k(const float* __restrict__ x, const int* __restrict__ idxg,
                               __half* __restrict__ xghi, __half* __restrict__ xglo) {
    int r = blockIdx.x;
    int b = r / GG;
    int src = idxg[r];
    for (int d = threadIdx.x; d < DD; d += blockDim.x) {
        float v = x[((size_t)(b*SS+src))*DD + d];
        __half h = __float2half(v);
        xghi[(size_t)r*DD + d] = h;
        xglo[(size_t)r*DD + d] = __float2half(v - __half2float(h));
    }
}

__global__ void scatter_split_k(const float* __restrict__ og, const int* __restrict__ idxg,
                                __half* __restrict__ xhi, __half* __restrict__ xlo) {
    int r = blockIdx.x;
    int b = r / GG;
    int dst = idxg[r];
    for (int d = threadIdx.x; d < DD; d += blockDim.x) {
        float v = og[(size_t)r*DD + d];
        __half h = __float2half(v);
        xhi[((size_t)(b*SS+dst))*DD + d] = h;
        xlo[((size_t)(b*SS+dst))*DD + d] = __float2half(v - __half2float(h));
    }
}

// ---------------- classifier ----------------
__global__ void classify_k(const float* __restrict__ x, const float* __restrict__ Wc,
                           const float* __restrict__ bc, const int* __restrict__ lo_p,
                           const int* __restrict__ ro_p, float* __restrict__ out, int nrows) {
    int r = blockIdx.x;
    int lo = *lo_p, ro = *ro_p;
    int per_b = 63 - lo - ro;
    if (per_b <= 0) per_b = 1;
    int b = r / per_b, t = lo + (r - b*per_b);
    const float* row = x + ((size_t)(b*SS + t))*DD;
    float p[7];
    #pragma unroll
    for (int c = 0; c < 7; c++) p[c] = 0.f;
    for (int d = threadIdx.x; d < DD; d += 256) {
        float xv = row[d];
        #pragma unroll
        for (int c = 0; c < 7; c++) p[c] += xv * Wc[d*7 + c];
    }
    #pragma unroll
    for (int c = 0; c < 7; c++) {
        float tot = blk_sum(p[c]);
        if (threadIdx.x == 0) out[r*7 + c] = tot + bc[c];
    }
}

// ---------------- launch ----------------
extern "C" void kernel_launch(void* const* d_in, const int* in_sizes, int n_in,
                              void* d_out, int out_size) {
    const float* emb_tok = (const float*)d_in[0];
    const float* emb_pos = (const float*)d_in[1];
    const float* ln_e_s  = (const float*)d_in[2];
    const float* ln_e_b  = (const float*)d_in[3];
    const float* Wq  = (const float*)d_in[4];
    const float* bq  = (const float*)d_in[5];
    const float* Wk  = (const float*)d_in[6];
    const float* bk  = (const float*)d_in[7];
    const float* Wv  = (const float*)d_in[8];
    const float* bv  = (const float*)d_in[9];
    const float* Wqg = (const float*)d_in[10];
    const float* bqg = (const float*)d_in[11];
    const float* Wkg = (const float*)d_in[12];
    const float* bkg = (const float*)d_in[13];
    const float* Wvg = (const float*)d_in[14];
    const float* bvg = (const float*)d_in[15];
    const float* Wo  = (const float*)d_in[16];
    const float* bo  = (const float*)d_in[17];
    const float* ln1_s = (const float*)d_in[18];
    const float* ln1_b = (const float*)d_in[19];
    const float* Wf1 = (const float*)d_in[20];
    const float* bf1 = (const float*)d_in[21];
    const float* Wf2 = (const float*)d_in[22];
    const float* bf2 = (const float*)d_in[23];
    const float* ln2_s = (const float*)d_in[24];
    const float* ln2_b = (const float*)d_in[25];
    const float* Wc  = (const float*)d_in[26];
    const float* bc  = (const float*)d_in[27];
    const int* input_ids = (const int*)d_in[28];
    const int* attn_mask = (const int*)d_in[29];
    const int* lo_p = (const int*)d_in[30];
    const int* ro_p = (const int*)d_in[31];
    float* out = (float*)d_out;

    float *x, *qkv, *tmp, *qg, *og, *bcat, *pacc, *pml;
    int* idxg; unsigned char* klo;
    __half *w, *ahi, *alo, *xhi, *xlo, *xghi, *xglo;
    __half *bqh, *bql, *bkh, *bvh, *bvl;
    cudaGetSymbolAddress((void**)&x,    g_x);
    cudaGetSymbolAddress((void**)&qkv,  g_qkv);
    cudaGetSymbolAddress((void**)&tmp,  g_tmp);
    cudaGetSymbolAddress((void**)&qg,   g_qg);
    cudaGetSymbolAddress((void**)&og,   g_og);
    cudaGetSymbolAddress((void**)&bcat, g_bcat);
    cudaGetSymbolAddress((void**)&pacc, g_pacc);
    cudaGetSymbolAddress((void**)&pml,  g_pml);
    cudaGetSymbolAddress((void**)&idxg, g_idxg);
    cudaGetSymbolAddress((void**)&klo,  g_klo);
    cudaGetSymbolAddress((void**)&w,    g_w);
    cudaGetSymbolAddress((void**)&ahi,  g_ahi);
    cudaGetSymbolAddress((void**)&alo,  g_alo);
    cudaGetSymbolAddress((void**)&xhi,  g_xhi);
    cudaGetSymbolAddress((void**)&xlo,  g_xlo);
    cudaGetSymbolAddress((void**)&xghi, g_xghi);
    cudaGetSymbolAddress((void**)&xglo, g_xglo);
    cudaGetSymbolAddress((void**)&bqh,  g_bqh);
    cudaGetSymbolAddress((void**)&bql,  g_bql);
    cudaGetSymbolAddress((void**)&bkh,  g_bkh);
    cudaGetSymbolAddress((void**)&bvh,  g_bvh);
    cudaGetSymbolAddress((void**)&bvl,  g_bvl);

    cudaFuncSetAttribute(tgemm_k<0>, cudaFuncAttributeMaxDynamicSharedMemorySize, SMEM_GEMM);
    cudaFuncSetAttribute(tgemm_k<1>, cudaFuncAttributeMaxDynamicSharedMemorySize, SMEM_GEMM);
    cudaFuncSetAttribute(tgemm_k<2>, cudaFuncAttributeMaxDynamicSharedMemorySize, SMEM_GEMM);
    cudaFuncSetAttribute(glob_part_k, cudaFuncAttributeMaxDynamicSharedMemorySize, SMEM_GLOB);

    prep_k<<<BB, 256>>>(input_ids, attn_mask, idxg, klo);
    embed_ln_k<<<BS, 256>>>(input_ids, emb_tok, emb_pos, ln_e_s, ln_e_b, x, xhi, xlo);

    dim3 wb(32, 8);
    for (int l = 0; l < LL; l++) {
        size_t base = (size_t)l * LWOFF;
        wsplit_t_k<<<dim3(DD/32, DD/32), wb>>>(Wq  + (size_t)l*DD*DD, w+base+OFF_Q,  DD, DD);
        wsplit_t_k<<<dim3(DD/32, DD/32), wb>>>(Wk  + (size_t)l*DD*DD, w+base+OFF_K,  DD, DD);
        wsplit_t_k<<<dim3(DD/32, DD/32), wb>>>(Wv  + (size_t)l*DD*DD, w+base+OFF_V,  DD, DD);
        wsplit_t_k<<<dim3(DD/32, DD/32), wb>>>(Wkg + (size_t)l*DD*DD, w+base+OFF_KG, DD, DD);
        wsplit_t_k<<<dim3(DD/32, DD/32), wb>>>(Wvg + (size_t)l*DD*DD, w+base+OFF_VG, DD, DD);
        wsplit_t_k<<<dim3(DD/32, DD/32), wb>>>(Wqg + (size_t)l*DD*DD, w+base+OFF_QG, DD, DD);
        wsplit_t_k<<<dim3(DD/32, DD/32), wb>>>(Wo  + (size_t)l*DD*DD, w+base+OFF_O,  DD, DD);
        wsplit_t_k<<<dim3(FFN/32, DD/32), wb>>>(Wf1 + (size_t)l*DD*FFN, w+base+OFF_F1, DD, FFN);
        wsplit_t_k<<<dim3(DD/32, FFN/32), wb>>>(Wf2 + (size_t)l*FFN*DD, w+base+OFF_F2, FFN, DD);
        bcat_k<<<(QS+255)/256, 256>>>(bq + l*DD, bk + l*DD, bv + l*DD, bkg + l*DD, bvg + l*DD,
                                      bcat + l*QS);
    }

    dim3 gTqkv(QS/128, BS/128);
    dim3 gT(DD/128, BS/128);
    dim3 gT1(FFN/128, BS/128);
    dim3 gTqg(DD/128, 1);
    dim3 gBandM(SS/128, BH);
    dim3 gGlobP(NSEG, BH);

    for (int l = 0; l < LL; l++) {
        size_t base = (size_t)l * LWOFF;
        const float* bqg_l = bqg + l*DD;
        const float* bo_l  = bo  + l*DD;
        const float* bf1_l = bf1 + l*FFN; const float* bf2_l = bf2 + l*DD;

        // QKV GEMM: band operands split in epilogue; kga/vga fp32 in qkv (stride QS)
        tgemm_k<2><<<gTqkv, 256, SMEM_GEMM>>>(xhi, xlo, w+base+OFF_Q,
                                              bcat + l*QS, qkv, 0, 0, BS, QS, DD);

        gather_split_k<<<BB*GG, 256>>>(x, idxg, xghi, xglo);
        tgemm_k<0><<<gTqg, 256, SMEM_GEMM>>>(xghi, xglo, w+base+OFF_QG,
                                             bqg_l, qg, 0, 0, BB*GG, DD, DD);

        band_mma_k<<<gBandM, 256>>>(bqh, bql, bkh, bvh, bvl, idxg, klo, xhi, xlo);

        glob_part_k<<<gGlobP, 256, SMEM_GLOB>>>(qg, qkv, attn_mask, pacc, pml);
        glob_comb_k<<<BH, 256>>>(pacc, pml, og);
        scatter_split_k<<<BB*GG, 256>>>(og, idxg, xhi, xlo);

        tgemm_k<0><<<gT, 256, SMEM_GEMM>>>(xhi, xlo, w+base+OFF_O,
                                           bo_l, tmp, 0, 0, BS, DD, DD);
        add_ln_k<<<BS, 256>>>(x, tmp, ln1_s + l*DD, ln1_b + l*DD, xhi, xlo);

        tgemm_k<1><<<gT1, 256, SMEM_GEMM>>>(xhi, xlo, w+base+OFF_F1,
                                            bf1_l, 0, ahi, alo, BS, FFN, DD);
        tgemm_k<0><<<gT, 256, SMEM_GEMM>>>(ahi, alo, w+base+OFF_F2,
                                           bf2_l, tmp, 0, 0, BS, DD, FFN);
        add_ln_k<<<BS, 256>>>(x, tmp, ln2_s + l*DD, ln2_b + l*DD, xhi, xlo);
    }

    int nrows = out_size / 7;
    classify_k<<<nrows, 256>>>(x, Wc, bc, lo_p, ro_p, out, nrows);
}